// round 13
// baseline (speedup 1.0000x reference)
#include <cuda_runtime.h>
#include <cuda_fp16.h>
#include <math.h>
#include <stdint.h>

// Problem dims
#define B_ 32
#define S_ 2048
#define H_ 512
#define V_ 128
#define P_ 256
#define M_ 128
#define SLOTS_ 64
#define L_ 2
#define IT_ 2816
#define IM_ 768
#define HALT_STEPS_ 4

#define SQRT_H_ 22.62741699796952f
#define INV_SQRT_M_ 0.08838834764831845f

// Output offsets (fp32 elements)
#define HALT_OFF   (HALT_STEPS_*B_*S_*V_)
#define ZL_OFF     (HALT_OFF + HALT_STEPS_*B_)
#define HOUT_OFF   (ZL_OFF + B_*S_*H_)
#define MEM_OFF    (HOUT_OFF + B_*P_)

// ------------------------- static device state -----------------------------
__device__ float g_z[B_*S_*H_];
__device__ float g_t[B_*S_*H_];
__device__ float g_h[B_*P_];
__device__ float g_mem[B_*SLOTS_*M_];
__device__ float g_pp[B_*4*H_];
__device__ float g_ctx[B_*H_];
__device__ float g_film[B_*2*H_];
// per-row sum-of-squares partials (written by residual GEMM epilogues)
__device__ float g_tpart[B_*H_*16];    // token-d: 16 col-tiles per row
__device__ float g_zpart[B_*S_*4];     // channel-d: 4 col-tiles per row

// activations: SINGLE fp16 tiles
__device__ __half g_th[B_*S_*H_];
__device__ __half g_zh[B_*S_*H_];
__device__ __half g_acth[B_*S_*IM_];

// recurrent weights: SINGLE fp16; lm_head keeps hi/lo split
__device__ __half g_wtgu[L_*2*IT_*S_];
__device__ __half g_wtd [L_*S_*IT_];
__device__ __half g_wmgu[L_*2*IM_*H_];
__device__ __half g_wmd [L_*H_*IM_];
__device__ __half g_lmh_h[V_*H_], g_lmh_l[V_*H_];

// split sizes (floats)
#define NS0 (L_*2*IT_*S_)
#define NS1 (L_*S_*IT_)
#define NS2 (L_*2*IM_*H_)
#define NS3 (L_*H_*IM_)
#define NS4 (V_*H_)
#define NSALL (NS0+NS1+NS2+NS3+NS4)

// ------------------------- PTX helpers -------------------------------------
__device__ __forceinline__ uint32_t smem_u32(const void* p){
    uint32_t a;
    asm("{ .reg .u64 t; cvta.to.shared.u64 t, %1; cvt.u32.u64 %0, t; }" : "=r"(a) : "l"(p));
    return a;
}
__device__ __forceinline__ void cp16(uint32_t s, const void* g){
    asm volatile("cp.async.cg.shared.global [%0], [%1], 16;" :: "r"(s), "l"(g));
}
__device__ __forceinline__ void cp_commit(){ asm volatile("cp.async.commit_group;" ::: "memory"); }
template<int N> __device__ __forceinline__ void cp_wait(){
    asm volatile("cp.async.wait_group %0;" :: "n"(N) : "memory");
}
__device__ __forceinline__ void ldsm4(uint32_t* r, uint32_t addr){
    asm volatile("ldmatrix.sync.aligned.m8n8.x4.shared.b16 {%0,%1,%2,%3}, [%4];"
        : "=r"(r[0]), "=r"(r[1]), "=r"(r[2]), "=r"(r[3]) : "r"(addr));
}
__device__ __forceinline__ void mma16816(float* c, const uint32_t* a, uint32_t b0, uint32_t b1){
    asm volatile("mma.sync.aligned.m16n8k16.row.col.f32.f16.f16.f32 "
        "{%0,%1,%2,%3}, {%4,%5,%6,%7}, {%8,%9}, {%0,%1,%2,%3};"
        : "+f"(c[0]), "+f"(c[1]), "+f"(c[2]), "+f"(c[3])
        : "r"(a[0]), "r"(a[1]), "r"(a[2]), "r"(a[3]), "r"(b0), "r"(b1));
}
__device__ __forceinline__ void splitw(float x, __half& hi, __half& lo){
    hi = __float2half(x);
    lo = __float2half(x - __half2float(hi));
}
__device__ __forceinline__ float wred(float v){
    #pragma unroll
    for (int o=16;o;o>>=1) v += __shfl_xor_sync(0xffffffffu, v, o);
    return v;
}

// ------------------------- SwiGLU GEMM (one-sync 3-stage pipe) --------------
// Oh = fp16(silu(A@Bg^T) * (A@Bu^T)); A, Bg, Bu single fp16, fp32 accum.
// CTA tile 128x64, 8 warps, warp tile 64x16, chunk 64, 2 CTAs/SM.
// ONE __syncthreads per chunk: load target (c+2)%3 was last read at c-1,
// and every warp passed this sync only after finishing c-1's mmas.
__global__ void __launch_bounds__(256,2) mma_gemm_glu(
    const __half* __restrict__ A,
    const __half* __restrict__ Bg, const __half* __restrict__ Bu,
    __half* __restrict__ Oh,
    int K, int N)
{
    constexpr int CHUNK = 64;
    constexpr int ROWB  = 128;
    constexpr int TA_B  = 128*ROWB;     // 16KB
    constexpr int TB_B  = 64*ROWB;      // 8KB
    constexpr int STAGE = TA_B + 2*TB_B;// 32KB
    extern __shared__ char dsm[];
    const uint32_t sb = smem_u32(dsm);
    const int tid  = threadIdx.x;
    const int lane = tid & 31, warp = tid >> 5;
    const int wm = warp >> 2, wn = warp & 3;
    const int rowBase = blockIdx.y*128;
    const int colBase = blockIdx.x*64;

    const __half* pA = A  + (size_t)rowBase*K;
    const __half* pG = Bg + (size_t)colBase*K;
    const __half* pU = Bu + (size_t)colBase*K;

    auto load_stage = [&](uint32_t sbase, int k0){
        {
            const __half* src = pA + k0;
            #pragma unroll
            for (int it = 0; it < 4; it++){
                int i = tid + it*256;
                int row = i >> 3, seg = i & 7;
                uint32_t off = (uint32_t)(row*ROWB + ((seg ^ (row & 7))<<4));
                cp16(sbase + off, (const void*)(src + row*K + seg*8));
            }
        }
        {
            const __half* src = pG + k0;
            #pragma unroll
            for (int it = 0; it < 2; it++){
                int i = tid + it*256;
                int row = i >> 3, seg = i & 7;
                uint32_t off = (uint32_t)(row*ROWB + ((seg ^ (row & 7))<<4));
                cp16(sbase + TA_B + off, (const void*)(src + row*K + seg*8));
            }
        }
        {
            const __half* src = pU + k0;
            #pragma unroll
            for (int it = 0; it < 2; it++){
                int i = tid + it*256;
                int row = i >> 3, seg = i & 7;
                uint32_t off = (uint32_t)(row*ROWB + ((seg ^ (row & 7))<<4));
                cp16(sbase + TA_B + TB_B + off, (const void*)(src + row*K + seg*8));
            }
        }
    };

    float G[4][2][4];
    float U[4][2][4];
    #pragma unroll
    for (int a=0;a<4;a++)
        #pragma unroll
        for (int b=0;b<2;b++)
            #pragma unroll
            for (int c=0;c<4;c++){ G[a][b][c]=0.f; U[a][b][c]=0.f; }

    const int nCh = K / CHUNK;   // >= 8 at all call sites
    load_stage(sb + 0*STAGE, 0);     cp_commit();
    load_stage(sb + 1*STAGE, CHUNK); cp_commit();

    const int rA = lane & 15;
    const int segSel = lane >> 4;
    const int xorA = rA & 7;

    int stgIdx = 0;
    for (int c = 0; c < nCh; c++){
        const uint32_t stg = sb + (uint32_t)stgIdx*STAGE;
        cp_wait<1>();            // group c drained (c+1 in flight)
        __syncthreads();         // also proves c-1's reads of (c+2)%3 done
        {
            int nstg = stgIdx + 2; if (nstg >= 3) nstg -= 3;
            if (c + 2 < nCh) load_stage(sb + (uint32_t)nstg*STAGE, (c+2)*CHUNK);
            cp_commit();
        }

        const uint32_t aBase = stg + (uint32_t)((wm*64 + rA)*ROWB);
        const uint32_t bRow  = (uint32_t)((wn*16 + rA)*ROWB);

        #pragma unroll
        for (int ks = 0; ks < 4; ks++){
            const uint32_t segOff = (uint32_t)(((2*ks + segSel) ^ xorA) << 4);
            uint32_t aF[4][4];
            #pragma unroll
            for (int mt = 0; mt < 4; mt++)
                ldsm4(aF[mt], aBase + mt*16*ROWB + segOff);
            uint32_t bg[4], bu[4];
            ldsm4(bg, stg + TA_B        + bRow + segOff);
            ldsm4(bu, stg + TA_B + TB_B + bRow + segOff);
            #pragma unroll
            for (int mt = 0; mt < 4; mt++){
                mma16816(G[mt][0], aF[mt], bg[0], bg[2]);
                mma16816(G[mt][1], aF[mt], bg[1], bg[3]);
                mma16816(U[mt][0], aF[mt], bu[0], bu[2]);
                mma16816(U[mt][1], aF[mt], bu[1], bu[3]);
            }
        }
        stgIdx++; if (stgIdx == 3) stgIdx = 0;
    }

    // epilogue: fused swiglu -> fp16
    const int rEp = rowBase + wm*64 + (lane >> 2);
    const int cEp = colBase + wn*16 + (lane & 3)*2;
    #pragma unroll
    for (int mt = 0; mt < 4; mt++){
        #pragma unroll
        for (int nt = 0; nt < 2; nt++){
            int cc = cEp + nt*8;
            #pragma unroll
            for (int half_ = 0; half_ < 2; half_++){
                int rr = rEp + mt*16 + half_*8;
                float g0 = G[mt][nt][half_*2+0], u0 = U[mt][nt][half_*2+0];
                float g1 = G[mt][nt][half_*2+1], u1 = U[mt][nt][half_*2+1];
                float v0 = g0/(1.0f+__expf(-g0))*u0;
                float v1 = g1/(1.0f+__expf(-g1))*u1;
                __half2 hv;
                hv.x = __float2half(v0);
                hv.y = __float2half(v1);
                *(__half2*)(Oh + (size_t)rr*N + cc) = hv;
            }
        }
    }
}

// ------------------------- residual GEMM (one-sync) + row sumsq -------------
// Cf += A@B^T; writes per-CTA partial sumsq of final rows to
// Spart[row*npartx + blockIdx.x] (deterministic fixed-order reduction).
// CTA tile 128x128, warp tile 64x32, chunk 64, 3 stages, 2 CTAs/SM.
__global__ void __launch_bounds__(256,2) mma_gemm2(
    const __half* __restrict__ A,
    const __half* __restrict__ Bw,
    float* __restrict__ Cf,
    float* __restrict__ Spart, int npartx,
    int K, int N)
{
    constexpr int CHUNK = 64;
    constexpr int ROWB  = 128;
    constexpr int TILE_B = 128*ROWB;     // 16KB
    constexpr int STAGE  = 2*TILE_B;     // 32KB
    extern __shared__ char dsm[];
    const uint32_t sb = smem_u32(dsm);
    const int tid  = threadIdx.x;
    const int lane = tid & 31, warp = tid >> 5;
    const int wm = warp >> 2, wn = warp & 3;
    const int rowBase = blockIdx.y*128;
    const int colBase = blockIdx.x*128;

    const __half* pA = A  + (size_t)rowBase*K;
    const __half* pB = Bw + (size_t)colBase*K;

    auto load_stage = [&](uint32_t sbase, int k0){
        {
            const __half* src = pA + k0;
            #pragma unroll
            for (int it = 0; it < 4; it++){
                int i = tid + it*256;
                int row = i >> 3, seg = i & 7;
                uint32_t off = (uint32_t)(row*ROWB + ((seg ^ (row & 7))<<4));
                cp16(sbase + off, (const void*)(src + row*K + seg*8));
            }
        }
        {
            const __half* src = pB + k0;
            #pragma unroll
            for (int it = 0; it < 4; it++){
                int i = tid + it*256;
                int row = i >> 3, seg = i & 7;
                uint32_t off = (uint32_t)(row*ROWB + ((seg ^ (row & 7))<<4));
                cp16(sbase + TILE_B + off, (const void*)(src + row*K + seg*8));
            }
        }
    };

    float G[4][4][4];
    #pragma unroll
    for (int a=0;a<4;a++)
        #pragma unroll
        for (int b=0;b<4;b++)
            #pragma unroll
            for (int c=0;c<4;c++) G[a][b][c]=0.f;

    const int nCh = K / CHUNK;   // >= 12 at all call sites
    load_stage(sb + 0*STAGE, 0);     cp_commit();
    load_stage(sb + 1*STAGE, CHUNK); cp_commit();

    const int rA = lane & 15;
    const int segSel = lane >> 4;
    const int xorA = rA & 7;

    int stgIdx = 0;
    for (int c = 0; c < nCh; c++){
        const uint32_t stg = sb + (uint32_t)stgIdx*STAGE;
        cp_wait<1>();
        __syncthreads();
        {
            int nstg = stgIdx + 2; if (nstg >= 3) nstg -= 3;
            if (c + 2 < nCh) load_stage(sb + (uint32_t)nstg*STAGE, (c+2)*CHUNK);
            cp_commit();
        }

        const uint32_t aBase = stg + (uint32_t)((wm*64 + rA)*ROWB);
        const uint32_t bBase = stg + TILE_B + (uint32_t)((wn*32 + rA)*ROWB);

        #pragma unroll
        for (int ks = 0; ks < 4; ks++){
            const uint32_t segOff = (uint32_t)(((2*ks + segSel) ^ xorA) << 4);
            uint32_t aF[4][4];
            #pragma unroll
            for (int mt = 0; mt < 4; mt++)
                ldsm4(aF[mt], aBase + mt*16*ROWB + segOff);
            #pragma unroll
            for (int bt = 0; bt < 2; bt++){
                uint32_t bh[4];
                ldsm4(bh, bBase + bt*16*ROWB + segOff);
                #pragma unroll
                for (int mt = 0; mt < 4; mt++){
                    mma16816(G[mt][bt*2+0], aF[mt], bh[0], bh[2]);
                    mma16816(G[mt][bt*2+1], aF[mt], bh[1], bh[3]);
                }
            }
        }
        stgIdx++; if (stgIdx == 3) stgIdx = 0;
    }

    // epilogue: residual add + accumulate per-row sumsq
    const int rEp = rowBase + wm*64 + (lane >> 2);
    const int cEp = colBase + wn*32 + (lane & 3)*2;
    float rsum[4][2];
    #pragma unroll
    for (int a=0;a<4;a++){ rsum[a][0]=0.f; rsum[a][1]=0.f; }
    #pragma unroll
    for (int mt = 0; mt < 4; mt++){
        #pragma unroll
        for (int nt = 0; nt < 4; nt++){
            int cc = cEp + nt*8;
            #pragma unroll
            for (int half_ = 0; half_ < 2; half_++){
                int rr = rEp + mt*16 + half_*8;
                float2 o;
                o.x = G[mt][nt][half_*2+0];
                o.y = G[mt][nt][half_*2+1];
                float2* cp2 = (float2*)(Cf + (size_t)rr*N + cc);
                float2 old = *cp2;
                o.x += old.x; o.y += old.y;
                *cp2 = o;
                rsum[mt][half_] += o.x*o.x + o.y*o.y;
            }
        }
    }
    __syncthreads();
    float* part = (float*)dsm;              // 128 x 16 floats = 8KB
    const int slot = wn*4 + (lane & 3);
    #pragma unroll
    for (int mt = 0; mt < 4; mt++)
        #pragma unroll
        for (int half_ = 0; half_ < 2; half_++){
            int lr = wm*64 + (lane>>2) + mt*16 + half_*8;
            part[lr*16 + slot] = rsum[mt][half_];
        }
    __syncthreads();
    if (tid < 128){
        float s = 0.f;
        #pragma unroll
        for (int q = 0; q < 16; q++) s += part[tid*16 + q];
        Spart[(size_t)(rowBase + tid)*npartx + blockIdx.x] = s;
    }
}

// ------------------------- lm_head GEMM (2-term hi/lo, 2-stage) -------------
__global__ void __launch_bounds__(256,2) mma_gemm0(
    const __half* __restrict__ A,
    const __half* __restrict__ Bh,  const __half* __restrict__ Bl,
    float* __restrict__ Cf,
    int K, int N)
{
    constexpr int CHUNK = 64;
    constexpr int ROWB  = 128;
    constexpr int TILE_B = 128*ROWB;
    constexpr int STAGE  = 3*TILE_B;     // 48KB
    extern __shared__ char dsm[];
    const uint32_t sb = smem_u32(dsm);
    const int tid  = threadIdx.x;
    const int lane = tid & 31, warp = tid >> 5;
    const int wm = warp >> 2, wn = warp & 3;
    const int rowBase = blockIdx.y*128;
    const int colBase = blockIdx.x*128;

    const uint32_t tiles0 = sb;
    const uint32_t tiles1 = sb + STAGE;

    const __half* ps[3];
    ps[0] = A  + (size_t)rowBase*K;
    ps[1] = Bh + (size_t)colBase*K;
    ps[2] = Bl + (size_t)colBase*K;

    auto load_stage = [&](uint32_t sbase, int k0){
        #pragma unroll
        for (int t = 0; t < 3; t++){
            const __half* src = ps[t] + k0;
            const uint32_t tb = sbase + (uint32_t)t*TILE_B;
            #pragma unroll
            for (int it = 0; it < 4; it++){
                int i = tid + it*256;
                int row = i >> 3, seg = i & 7;
                uint32_t off = (uint32_t)(row*ROWB + ((seg ^ (row & 7))<<4));
                cp16(tb + off, (const void*)(src + row*K + seg*8));
            }
        }
    };

    float G[4][4][4];
    #pragma unroll
    for (int a=0;a<4;a++)
        #pragma unroll
        for (int b=0;b<4;b++)
            #pragma unroll
            for (int c=0;c<4;c++) G[a][b][c]=0.f;

    const int nCh = K / CHUNK;
    load_stage(tiles0, 0);      cp_commit();
    load_stage(tiles1, CHUNK);  cp_commit();

    const int rA = lane & 15;
    const int segSel = lane >> 4;
    const int xorA = rA & 7;

    for (int c = 0; c < nCh; c++){
        const uint32_t stg = (c & 1) ? tiles1 : tiles0;
        if (c + 1 < nCh) cp_wait<1>(); else cp_wait<0>();
        __syncthreads();

        const uint32_t aBase = stg + (uint32_t)((wm*64 + rA)*ROWB);
        const uint32_t bBase = stg + TILE_B + (uint32_t)((wn*32 + rA)*ROWB);

        #pragma unroll
        for (int ks = 0; ks < 4; ks++){
            const uint32_t segOff = (uint32_t)(((2*ks + segSel) ^ xorA) << 4);
            uint32_t aF[4][4];
            #pragma unroll
            for (int mt = 0; mt < 4; mt++)
                ldsm4(aF[mt], aBase + mt*16*ROWB + segOff);
            #pragma unroll
            for (int bt = 0; bt < 2; bt++){
                uint32_t bh[4], bl[4];
                ldsm4(bh, bBase + bt*16*ROWB + segOff);
                ldsm4(bl, bBase + TILE_B + bt*16*ROWB + segOff);
                #pragma unroll
                for (int mt = 0; mt < 4; mt++){
                    mma16816(G[mt][bt*2+0], aF[mt], bh[0], bh[2]);
                    mma16816(G[mt][bt*2+1], aF[mt], bh[1], bh[3]);
                    mma16816(G[mt][bt*2+0], aF[mt], bl[0], bl[2]);
                    mma16816(G[mt][bt*2+1], aF[mt], bl[1], bl[3]);
                }
            }
        }
        __syncthreads();
        if (c + 2 < nCh){
            load_stage(stg, (c+2)*CHUNK);
            cp_commit();
        }
    }

    const int rEp = rowBase + wm*64 + (lane >> 2);
    const int cEp = colBase + wn*32 + (lane & 3)*2;
    #pragma unroll
    for (int mt = 0; mt < 4; mt++){
        #pragma unroll
        for (int nt = 0; nt < 4; nt++){
            int cc = cEp + nt*8;
            #pragma unroll
            for (int half_ = 0; half_ < 2; half_++){
                int rr = rEp + mt*16 + half_*8;
                float2 o;
                o.x = G[mt][nt][half_*2+0];
                o.y = G[mt][nt][half_*2+1];
                *(float2*)(Cf + (size_t)rr*N + cc) = o;
            }
        }
    }
}

// ------------------------- aux kernels -------------------------------------
__global__ void copy4_kernel(float4* __restrict__ dst, const float4* __restrict__ src, int n4){
    int i = blockIdx.x*blockDim.x + threadIdx.x;
    if (i < n4) dst[i] = src[i];
}

__global__ void copy_init_kernel(const float4* __restrict__ z_in,
                                 const float4* __restrict__ h_in,
                                 const float4* __restrict__ mem_in){
    int i = blockIdx.x*blockDim.x + threadIdx.x;
    const int NZ = B_*S_*H_/4, NH = B_*P_/4, NM = B_*SLOTS_*M_/4;
    if (i < NZ){ ((float4*)g_z)[i] = z_in[i]; return; }
    i -= NZ;
    if (i < NH){ ((float4*)g_h)[i] = h_in[i]; return; }
    i -= NH;
    if (i < NM){ ((float4*)g_mem)[i] = mem_in[i]; }
}

// convert recurrent weights to single fp16; lm_head to hi/lo split
__global__ void split_all_kernel(const float* __restrict__ wt_gu, const float* __restrict__ wt_d,
                                 const float* __restrict__ wm_gu, const float* __restrict__ wm_d,
                                 const float* __restrict__ lmh){
    long long i = (long long)(blockIdx.x*blockDim.x + threadIdx.x)*4;
    const float* src; __half* hd;
    if (i < NS0)             { src=wt_gu; hd=g_wtgu; }
    else if ((i-=NS0) < NS1) { src=wt_d;  hd=g_wtd;  }
    else if ((i-=NS1) < NS2) { src=wm_gu; hd=g_wmgu; }
    else if ((i-=NS2) < NS3) { src=wm_d;  hd=g_wmd;  }
    else if ((i-=NS3) < NS4) {
        float4 v = *(const float4*)(lmh + i);
        __half h0,l0,h1,l1,h2,l2,h3,l3;
        splitw(v.x,h0,l0); splitw(v.y,h1,l1); splitw(v.z,h2,l2); splitw(v.w,h3,l3);
        __half2 a,b,c,d;
        a.x=h0;a.y=h1; b.x=h2;b.y=h3; c.x=l0;c.y=l1; d.x=l2;d.y=l3;
        ((__half2*)(g_lmh_h+i))[0]=a; ((__half2*)(g_lmh_h+i))[1]=b;
        ((__half2*)(g_lmh_l+i))[0]=c; ((__half2*)(g_lmh_l+i))[1]=d;
        return;
    }
    else return;
    float4 v = *(const float4*)(src + i);
    __half2 a,b;
    a.x=__float2half(v.x); a.y=__float2half(v.y);
    b.x=__float2half(v.z); b.y=__float2half(v.w);
    ((__half2*)(hd+i))[0]=a; ((__half2*)(hd+i))[1]=b;
}

__global__ void pooled1_kernel(){
    int b = blockIdx.x, chunk = blockIdx.y, h = threadIdx.x;
    const float* p = g_z + (size_t)b*S_*H_ + (size_t)chunk*(S_/4)*H_ + h;
    float a0=0.f,a1=0.f,a2=0.f,a3=0.f;
    #pragma unroll 4
    for (int s = 0; s < S_/4; s += 4){
        a0 += p[(s+0)*H_]; a1 += p[(s+1)*H_];
        a2 += p[(s+2)*H_]; a3 += p[(s+3)*H_];
    }
    g_pp[(b*4+chunk)*H_ + h] = a0+a1+a2+a3;
}

// planner: warp-per-output coalesced gemvs; 512 threads, pooled2 folded in
__global__ void planner_kernel(
    const float* __restrict__ w1, const float* __restrict__ b1,
    const float* __restrict__ w2, const float* __restrict__ b2,
    const float* __restrict__ hdw, const float* __restrict__ hdb,
    const float* __restrict__ filmw, const float* __restrict__ filmb,
    const float* __restrict__ haltw, const float* __restrict__ haltb,
    const float* __restrict__ qw, const float* __restrict__ qb,
    const float* __restrict__ kw, const float* __restrict__ kb,
    const float* __restrict__ vw, const float* __restrict__ vb,
    const float* __restrict__ gw, const float* __restrict__ gb,
    const float* __restrict__ ow, const float* __restrict__ ob,
    float* __restrict__ halt_out)
{
    int b = blockIdx.x, tid = threadIdx.x;
    int lane = tid & 31, wp = tid >> 5;
    __shared__ float x[768];
    __shared__ float a1s[256];
    __shared__ float hm[256];
    __shared__ float qv[128], kv2[128], vv[128];
    __shared__ float rq[64], rk[64];
    __shared__ float ctxm[128];
    __shared__ float sgate;

    x[tid] = (g_pp[(b*4+0)*H_+tid] + g_pp[(b*4+1)*H_+tid]
            + g_pp[(b*4+2)*H_+tid] + g_pp[(b*4+3)*H_+tid]) * (1.0f/S_);
    if (tid < 256) x[512+tid] = g_h[b*P_+tid];
    __syncthreads();

    for (int j = wp; j < 256; j += 16){
        const float* w = w1 + j*768;
        float acc = 0.f;
        for (int k = lane; k < 768; k += 32) acc += w[k]*x[k];
        acc = wred(acc);
        if (lane==0){
            float v = acc + b1[j];
            a1s[j] = 0.5f*v*(1.0f + erff(v*0.70710678118654752f));
        }
    }
    __syncthreads();
    for (int j = wp; j < 256; j += 16){
        const float* w = w2 + j*256;
        float acc = 0.f;
        for (int k = lane; k < 256; k += 32) acc += w[k]*a1s[k];
        acc = wred(acc);
        if (lane==0) hm[j] = acc + b2[j];
    }
    __syncthreads();
    for (int j = wp; j < 256; j += 16){
        const float* w = hdw + j*256;
        float acc = 0.f;
        for (int k = lane; k < 256; k += 32) acc += w[k]*hm[k];
        acc = wred(acc);
        if (lane==0) g_h[b*P_+j] = x[512+j] + acc + hdb[j];
    }
    for (int j = wp; j < 2*H_; j += 16){
        const float* w = filmw + j*256;
        float acc = 0.f;
        for (int k = lane; k < 256; k += 32) acc += w[k]*hm[k];
        acc = wred(acc);
        if (lane==0) g_film[b*2*H_+j] = acc + filmb[j];
    }
    if (wp == 0){
        float acc = 0.f;
        for (int k = lane; k < 256; k += 32) acc += haltw[k]*hm[k];
        acc = wred(acc);
        if (lane==0) halt_out[b] = acc + haltb[0];
    }
    if (wp == 1){
        float acc = 0.f;
        for (int k = lane; k < 256; k += 32) acc += gw[k]*hm[k];
        acc = wred(acc);
        if (lane==0) sgate = 1.0f/(1.0f+expf(-(acc + gb[0])));
    }
    for (int j = wp; j < 384; j += 16){
        int which = j >> 7, jj = j & 127;
        const float* w  = (which==0 ? qw : which==1 ? kw : vw) + jj*256;
        float acc = 0.f;
        for (int k = lane; k < 256; k += 32) acc += w[k]*hm[k];
        acc = wred(acc);
        if (lane==0){
            float bb = (which==0 ? qb[jj] : which==1 ? kb[jj] : vb[jj]);
            float v = acc + bb;
            if (which==0) qv[jj]=v; else if (which==1) kv2[jj]=v; else vv[jj]=v;
        }
    }
    __syncthreads();

    const float* memb = g_mem + b*SLOTS_*M_;
    for (int n = wp; n < 64; n += 16){
        const float* m = memb + n*M_;
        float aq=0.f, ak=0.f;
        for (int d = lane; d < 128; d += 32){ float mv=m[d]; aq+=mv*qv[d]; ak+=mv*kv2[d]; }
        aq = wred(aq); ak = wred(ak);
        if (lane==0){ rq[n]=aq*INV_SQRT_M_; rk[n]=ak*INV_SQRT_M_; }
    }
    __syncthreads();
    if (wp < 2){
        float* r = wp ? rk : rq;
        float v0 = r[lane], v1 = r[lane+32];
        float mx = fmaxf(v0,v1);
        #pragma unroll
        for (int o=16;o;o>>=1) mx = fmaxf(mx, __shfl_xor_sync(0xffffffffu, mx, o));
        float e0 = expf(v0-mx), e1 = expf(v1-mx);
        float s = e0+e1;
        #pragma unroll
        for (int o=16;o;o>>=1) s += __shfl_xor_sync(0xffffffffu, s, o);
        float inv = 1.0f/s;
        r[lane] = e0*inv; r[lane+32] = e1*inv;
    }
    __syncthreads();
    if (tid < 128){
        float acc=0.f;
        #pragma unroll 4
        for (int n2=0;n2<64;n2++) acc += rq[n2]*memb[n2*M_+tid];
        ctxm[tid]=acc;
    }
    __syncthreads();
    for (int j = wp; j < H_; j += 16){
        const float* w = ow + j*M_;
        float acc = 0.f;
        for (int d = lane; d < 128; d += 32) acc += w[d]*ctxm[d];
        acc = wred(acc);
        if (lane==0) g_ctx[b*H_+j] = acc + ob[j];
    }
    float gv = sgate;
    for (int idx=tid; idx<SLOTS_*M_; idx+=512){
        int n2 = idx>>7, d2 = idx&127;
        float w = rk[n2]*gv;
        g_mem[b*SLOTS_*M_+idx] = memb[idx]*(1.0f-w) + w*vv[d2];
    }
}

// (B,S,H) -> (B,H,S) with optional fused z-update; writes single-fp16 t
template<bool UPD>
__global__ void transpose_zt_split(const int* __restrict__ inputs,
                                   const float* __restrict__ embed_w){
    __shared__ float tile[32][33];
    int b = blockIdx.z;
    int s0 = blockIdx.x*32, h0 = blockIdx.y*32;
    int h = h0 + threadIdx.x;
    for (int r=threadIdx.y; r<32; r+=8){
        size_t idx = (size_t)b*S_*H_ + (size_t)(s0+r)*H_ + h;
        float v = g_z[idx];
        if (UPD){
            int tok = inputs[b*S_ + s0 + r];
            v += SQRT_H_*embed_w[tok*H_ + h] + g_ctx[b*H_ + h];
            g_z[idx] = v;
        }
        tile[r][threadIdx.x] = v;
    }
    __syncthreads();
    int s = s0 + threadIdx.x;
    for (int r=threadIdx.y; r<32; r+=8){
        float v = tile[threadIdx.x][r];
        size_t idx = (size_t)b*H_*S_ + (size_t)(h0+r)*S_ + s;
        g_t[idx] = v;
        g_th[idx] = __float2half(v);
    }
}

// (B,H,S) -> (B,S,H): rmsnorm scale (from g_tpart) + FiLM; writes z + fp16 z
__global__ void transpose_tz_film_split(){
    __shared__ float tile[32][33];
    __shared__ float scl[32];
    int b = blockIdx.z;
    int s0 = blockIdx.x*32, h0 = blockIdx.y*32;
    if (threadIdx.y == 0){
        const float* pp = g_tpart + (size_t)(b*H_ + h0 + threadIdx.x)*16;
        float s = 0.f;
        #pragma unroll
        for (int q = 0; q < 16; q++) s += pp[q];
        scl[threadIdx.x] = rsqrtf(s/(float)S_ + 1e-5f);
    }
    __syncthreads();
    int s = s0 + threadIdx.x;
    for (int r=threadIdx.y; r<32; r+=8)
        tile[r][threadIdx.x] = g_t[(size_t)b*H_*S_ + (size_t)(h0+r)*S_ + s] * scl[r];
    __syncthreads();
    int h = h0 + threadIdx.x;
    float sc = 1.0f + g_film[b*2*H_ + h];
    float sh = g_film[b*2*H_ + H_ + h];
    for (int r=threadIdx.y; r<32; r+=8){
        float v = tile[threadIdx.x][r]*sc + sh;
        size_t idx = (size_t)b*S_*H_ + (size_t)(s0+r)*H_ + h;
        g_z[idx] = v;
        g_zh[idx] = __float2half(v);
    }
}

// single-pass rmsnorm of z rows using precomputed sumsq partials (g_zpart)
__global__ void rmsnorm_z_split_kernel(){
    int row = blockIdx.x;
    __shared__ float ssum;
    if (threadIdx.x == 0){
        const float* pp = g_zpart + (size_t)row*4;
        ssum = pp[0] + pp[1] + pp[2] + pp[3];
    }
    __syncthreads();
    float scale = rsqrtf(ssum/(float)H_ + 1e-5f);
    float* p = g_z + (size_t)row*H_;
    for (int i=threadIdx.x; i<H_; i+=256){
        float v = p[i]*scale;
        p[i] = v;
        g_zh[(size_t)row*H_ + i] = __float2half(v);
    }
}

// ---------------------------------------------------------------------------
extern "C" void kernel_launch(void* const* d_in, const int* in_sizes, int n_in,
                              void* d_out, int out_size)
{
    const int*   inputs    = (const int*)  d_in[0];
    const float* z_in      = (const float*)d_in[1];
    const float* h_in      = (const float*)d_in[2];
    const float* mem_in    = (const float*)d_in[3];
    const float* embed_w   = (const float*)d_in[4];
    const float* lm_head_w = (const float*)d_in[5];
    const float* w1        = (const float*)d_in[6];
    const float* b1        = (const float*)d_in[7];
    const float* w2        = (const float*)d_in[8];
    const float* b2        = (const float*)d_in[9];
    const float* hdw       = (const float*)d_in[10];
    const float* hdb       = (const float*)d_in[11];
    const float* filmw     = (const float*)d_in[12];
    const float* filmb     = (const float*)d_in[13];
    const float* haltw     = (const float*)d_in[14];
    const float* haltb     = (const float*)d_in[15];
    const float* qw        = (const float*)d_in[16];
    const float* qb        = (const float*)d_in[17];
    const float* kw        = (const float*)d_in[18];
    const float* kb        = (const float*)d_in[19];
    const float* vw        = (const float*)d_in[20];
    const float* vb        = (const float*)d_in[21];
    const float* gw        = (const float*)d_in[22];
    const float* gb        = (const float*)d_in[23];
    const float* ow        = (const float*)d_in[24];
    const float* ob        = (const float*)d_in[25];
    const float* wt_gu     = (const float*)d_in[26];
    const float* wt_d      = (const float*)d_in[27];
    const float* wm_gu     = (const float*)d_in[28];
    const float* wm_d      = (const float*)d_in[29];
    float* out = (float*)d_out;

    float *zp, *tp, *hp, *memp, *tpart, *zpart;
    cudaGetSymbolAddress((void**)&zp,    g_z);
    cudaGetSymbolAddress((void**)&tp,    g_t);
    cudaGetSymbolAddress((void**)&hp,    g_h);
    cudaGetSymbolAddress((void**)&memp,  g_mem);
    cudaGetSymbolAddress((void**)&tpart, g_tpart);
    cudaGetSymbolAddress((void**)&zpart, g_zpart);

    __half *th, *zh, *ah;
    __half *wtgu, *wtd, *wmgu, *wmd, *lmhh, *lmhl;
    cudaGetSymbolAddress((void**)&th, g_th);
    cudaGetSymbolAddress((void**)&zh, g_zh);
    cudaGetSymbolAddress((void**)&ah, g_acth);
    cudaGetSymbolAddress((void**)&wtgu, g_wtgu);
    cudaGetSymbolAddress((void**)&wtd,  g_wtd);
    cudaGetSymbolAddress((void**)&wmgu, g_wmgu);
    cudaGetSymbolAddress((void**)&wmd,  g_wmd);
    cudaGetSymbolAddress((void**)&lmhh, g_lmh_h);
    cudaGetSymbolAddress((void**)&lmhl, g_lmh_l);

    const int SMEM_GLU = 3*32*1024;  // 96KB per CTA, 2 CTAs/SM
    const int SMEM_G2  = 3*32*1024;  // 96KB per CTA, 2 CTAs/SM
    const int SMEM_G0  = 2*48*1024;  // 96KB per CTA, 2 CTAs/SM
    cudaFuncSetAttribute(mma_gemm_glu, cudaFuncAttributeMaxDynamicSharedMemorySize, SMEM_GLU);
    cudaFuncSetAttribute(mma_gemm2,    cudaFuncAttributeMaxDynamicSharedMemorySize, SMEM_G2);
    cudaFuncSetAttribute(mma_gemm0,    cudaFuncAttributeMaxDynamicSharedMemorySize, SMEM_G0);

    dim3 trBlk(32,8);
    dim3 trGrd(S_/32, H_/32, B_);

    // launch 0: state init
    {
        int tot4 = (B_*S_*H_ + B_*P_ + B_*SLOTS_*M_)/4;
        copy_init_kernel<<<(tot4+255)/256, 256>>>((const float4*)z_in, (const float4*)h_in, (const float4*)mem_in);
    }
    // launch 1: weight converts/splits
    split_all_kernel<<<(NSALL/4+255)/256, 256>>>(wt_gu, wt_d, wm_gu, wm_d, lm_head_w);
    // launch 2: pooled partials for step 0
    pooled1_kernel<<<dim3(B_,4), 512>>>();
    // launch 3: PROFILING PROBE — glu GEMM replica on a reduced grid; output
    // region fully overwritten by the real token-gu GEMM before any consumer.
    mma_gemm_glu<<<dim3(IT_/64, 4), 256, SMEM_GLU>>>(
        th, wtgu, wtgu+(size_t)IT_*S_, ah, S_, IT_);

    for (int st=0; st<HALT_STEPS_; st++){
        if (st > 0) pooled1_kernel<<<dim3(B_,4), 512>>>();
        planner_kernel<<<B_, 512>>>(w1,b1,w2,b2,hdw,hdb,filmw,filmb,haltw,haltb,
                                    qw,qb,kw,kb,vw,vb,gw,gb,ow,ob,
                                    out + HALT_OFF + st*B_);

        for (int i=0; i<L_; i++){
            if (i==0) transpose_zt_split<true ><<<trGrd, trBlk>>>(inputs, embed_w);
            else      transpose_zt_split<false><<<trGrd, trBlk>>>(inputs, embed_w);
            {
                size_t go = (size_t)i*2*IT_*S_;
                mma_gemm_glu<<<dim3(IT_/64, (B_*H_)/128), 256, SMEM_GLU>>>(
                    th, wtgu+go, wtgu+go+(size_t)IT_*S_, ah, S_, IT_);
            }
            {
                size_t dof = (size_t)i*S_*IT_;
                mma_gemm2<<<dim3(S_/128, (B_*H_)/128), 256, SMEM_G2>>>(
                    ah, wtd+dof, tp, tpart, 16, IT_, S_);
            }
            transpose_tz_film_split<<<trGrd, trBlk>>>();
            {
                size_t go = (size_t)i*2*IM_*H_;
                mma_gemm_glu<<<dim3(IM_/64, (B_*S_)/128), 256, SMEM_GLU>>>(
                    zh, wmgu+go, wmgu+go+(size_t)IM_*H_, ah, H_, IM_);
            }
            {
                size_t dof = (size_t)i*H_*IM_;
                mma_gemm2<<<dim3(H_/128, (B_*S_)/128), 256, SMEM_G2>>>(
                    ah, wmd+dof, zp, zpart, 4, IM_, H_);
            }
            rmsnorm_z_split_kernel<<<B_*S_, 256>>>();
        }
        mma_gemm0<<<dim3(V_/128, (B_*S_)/128), 256, SMEM_G0>>>(
            zh, lmhh, lmhl, out + (size_t)st*B_*S_*V_, H_, V_);
    }

    // final state outputs
    copy4_kernel<<<(B_*S_*H_/4+255)/256, 256>>>((float4*)(out + ZL_OFF), (const float4*)zp, B_*S_*H_/4);
    copy4_kernel<<<(B_*P_/4+255)/256,    256>>>((float4*)(out + HOUT_OFF),(const float4*)hp, B_*P_/4);
    copy4_kernel<<<(B_*SLOTS_*M_/4+255)/256,256>>>((float4*)(out + MEM_OFF),(const float4*)memp, B_*SLOTS_*M_/4);
}

// round 14
// speedup vs baseline: 1.0362x; 1.0362x over previous
#include <cuda_runtime.h>
#include <cuda_fp16.h>
#include <math.h>
#include <stdint.h>

// Problem dims
#define B_ 32
#define S_ 2048
#define H_ 512
#define V_ 128
#define P_ 256
#define M_ 128
#define SLOTS_ 64
#define L_ 2
#define IT_ 2816
#define IM_ 768
#define HALT_STEPS_ 4

#define SQRT_H_ 22.62741699796952f
#define INV_SQRT_M_ 0.08838834764831845f

// Output offsets (fp32 elements)
#define HALT_OFF   (HALT_STEPS_*B_*S_*V_)
#define ZL_OFF     (HALT_OFF + HALT_STEPS_*B_)
#define HOUT_OFF   (ZL_OFF + B_*S_*H_)
#define MEM_OFF    (HOUT_OFF + B_*P_)

// ------------------------- static device state -----------------------------
__device__ float g_z[B_*S_*H_];
__device__ float g_t[B_*S_*H_];
__device__ float g_h[B_*P_];
__device__ float g_mem[B_*SLOTS_*M_];
__device__ float g_pp[B_*4*H_];
__device__ float g_ctx[B_*H_];
__device__ float g_film[B_*2*H_];
// per-row sum-of-squares partials (written by residual GEMM epilogues)
__device__ float g_tpart[B_*H_*16];    // token-d: 16 col-tiles per row
__device__ float g_zpart[B_*S_*4];     // channel-d: 4 col-tiles per row

// activations: SINGLE fp16 tiles
__device__ __half g_th[B_*S_*H_];
__device__ __half g_zh[B_*S_*H_];
__device__ __half g_acth[B_*S_*IM_];

// recurrent weights: SINGLE fp16; lm_head keeps hi/lo split
__device__ __half g_wtgu[L_*2*IT_*S_];
__device__ __half g_wtd [L_*S_*IT_];
__device__ __half g_wmgu[L_*2*IM_*H_];
__device__ __half g_wmd [L_*H_*IM_];
__device__ __half g_lmh_h[V_*H_], g_lmh_l[V_*H_];

// split sizes (floats)
#define NS0 (L_*2*IT_*S_)
#define NS1 (L_*S_*IT_)
#define NS2 (L_*2*IM_*H_)
#define NS3 (L_*H_*IM_)
#define NS4 (V_*H_)
#define NSALL (NS0+NS1+NS2+NS3+NS4)

// ------------------------- PTX helpers -------------------------------------
__device__ __forceinline__ uint32_t smem_u32(const void* p){
    uint32_t a;
    asm("{ .reg .u64 t; cvta.to.shared.u64 t, %1; cvt.u32.u64 %0, t; }" : "=r"(a) : "l"(p));
    return a;
}
__device__ __forceinline__ void cp16(uint32_t s, const void* g){
    asm volatile("cp.async.cg.shared.global [%0], [%1], 16;" :: "r"(s), "l"(g));
}
__device__ __forceinline__ void cp_commit(){ asm volatile("cp.async.commit_group;" ::: "memory"); }
template<int N> __device__ __forceinline__ void cp_wait(){
    asm volatile("cp.async.wait_group %0;" :: "n"(N) : "memory");
}
__device__ __forceinline__ void ldsm4(uint32_t* r, uint32_t addr){
    asm volatile("ldmatrix.sync.aligned.m8n8.x4.shared.b16 {%0,%1,%2,%3}, [%4];"
        : "=r"(r[0]), "=r"(r[1]), "=r"(r[2]), "=r"(r[3]) : "r"(addr));
}
__device__ __forceinline__ void mma16816(float* c, const uint32_t* a, uint32_t b0, uint32_t b1){
    asm volatile("mma.sync.aligned.m16n8k16.row.col.f32.f16.f16.f32 "
        "{%0,%1,%2,%3}, {%4,%5,%6,%7}, {%8,%9}, {%0,%1,%2,%3};"
        : "+f"(c[0]), "+f"(c[1]), "+f"(c[2]), "+f"(c[3])
        : "r"(a[0]), "r"(a[1]), "r"(a[2]), "r"(a[3]), "r"(b0), "r"(b1));
}
__device__ __forceinline__ void splitw(float x, __half& hi, __half& lo){
    hi = __float2half(x);
    lo = __float2half(x - __half2float(hi));
}
__device__ __forceinline__ float wred(float v){
    #pragma unroll
    for (int o=16;o;o>>=1) v += __shfl_xor_sync(0xffffffffu, v, o);
    return v;
}

// ------------------------- SwiGLU GEMM (3-stage pipe, R12 form) -------------
// Oh = fp16(silu(A@Bg^T) * (A@Bu^T)); A, Bg, Bu single fp16, fp32 accum.
// CTA tile 128x64, 8 warps, warp tile 64x16, chunk 64, 3 stages, 2 CTAs/SM.
__global__ void __launch_bounds__(256,2) mma_gemm_glu(
    const __half* __restrict__ A,
    const __half* __restrict__ Bg, const __half* __restrict__ Bu,
    __half* __restrict__ Oh,
    int K, int N)
{
    constexpr int CHUNK = 64;
    constexpr int ROWB  = 128;
    constexpr int TA_B  = 128*ROWB;     // 16KB
    constexpr int TB_B  = 64*ROWB;      // 8KB
    constexpr int STAGE = TA_B + 2*TB_B;// 32KB
    extern __shared__ char dsm[];
    const uint32_t sb = smem_u32(dsm);
    const int tid  = threadIdx.x;
    const int lane = tid & 31, warp = tid >> 5;
    const int wm = warp >> 2, wn = warp & 3;
    const int rowBase = blockIdx.y*128;
    const int colBase = blockIdx.x*64;

    const __half* pA = A  + (size_t)rowBase*K;
    const __half* pG = Bg + (size_t)colBase*K;
    const __half* pU = Bu + (size_t)colBase*K;

    auto load_stage = [&](uint32_t sbase, int k0){
        {
            const __half* src = pA + k0;
            #pragma unroll
            for (int it = 0; it < 4; it++){
                int i = tid + it*256;
                int row = i >> 3, seg = i & 7;
                uint32_t off = (uint32_t)(row*ROWB + ((seg ^ (row & 7))<<4));
                cp16(sbase + off, (const void*)(src + row*K + seg*8));
            }
        }
        {
            const __half* src = pG + k0;
            #pragma unroll
            for (int it = 0; it < 2; it++){
                int i = tid + it*256;
                int row = i >> 3, seg = i & 7;
                uint32_t off = (uint32_t)(row*ROWB + ((seg ^ (row & 7))<<4));
                cp16(sbase + TA_B + off, (const void*)(src + row*K + seg*8));
            }
        }
        {
            const __half* src = pU + k0;
            #pragma unroll
            for (int it = 0; it < 2; it++){
                int i = tid + it*256;
                int row = i >> 3, seg = i & 7;
                uint32_t off = (uint32_t)(row*ROWB + ((seg ^ (row & 7))<<4));
                cp16(sbase + TA_B + TB_B + off, (const void*)(src + row*K + seg*8));
            }
        }
    };

    float G[4][2][4];
    float U[4][2][4];
    #pragma unroll
    for (int a=0;a<4;a++)
        #pragma unroll
        for (int b=0;b<2;b++)
            #pragma unroll
            for (int c=0;c<4;c++){ G[a][b][c]=0.f; U[a][b][c]=0.f; }

    const int nCh = K / CHUNK;
    load_stage(sb + 0*STAGE, 0);        cp_commit();
    load_stage(sb + 1*STAGE, CHUNK);    cp_commit();
    load_stage(sb + 2*STAGE, 2*CHUNK);  cp_commit();

    const int rA = lane & 15;
    const int segSel = lane >> 4;
    const int xorA = rA & 7;

    int stgIdx = 0;
    for (int c = 0; c < nCh; c++){
        const uint32_t stg = sb + (uint32_t)stgIdx*STAGE;
        cp_wait<2>();
        __syncthreads();

        const uint32_t aBase = stg + (uint32_t)((wm*64 + rA)*ROWB);
        const uint32_t bRow  = (uint32_t)((wn*16 + rA)*ROWB);

        #pragma unroll
        for (int ks = 0; ks < 4; ks++){
            const uint32_t segOff = (uint32_t)(((2*ks + segSel) ^ xorA) << 4);
            uint32_t aF[4][4];
            #pragma unroll
            for (int mt = 0; mt < 4; mt++)
                ldsm4(aF[mt], aBase + mt*16*ROWB + segOff);
            uint32_t bg[4], bu[4];
            ldsm4(bg, stg + TA_B        + bRow + segOff);
            ldsm4(bu, stg + TA_B + TB_B + bRow + segOff);
            #pragma unroll
            for (int mt = 0; mt < 4; mt++){
                mma16816(G[mt][0], aF[mt], bg[0], bg[2]);
                mma16816(G[mt][1], aF[mt], bg[1], bg[3]);
                mma16816(U[mt][0], aF[mt], bu[0], bu[2]);
                mma16816(U[mt][1], aF[mt], bu[1], bu[3]);
            }
        }
        __syncthreads();
        if (c + 3 < nCh) load_stage(stg, (c+3)*CHUNK);
        cp_commit();
        stgIdx = (stgIdx==2) ? 0 : stgIdx+1;
    }

    // epilogue: fused swiglu -> fp16
    const int rEp = rowBase + wm*64 + (lane >> 2);
    const int cEp = colBase + wn*16 + (lane & 3)*2;
    #pragma unroll
    for (int mt = 0; mt < 4; mt++){
        #pragma unroll
        for (int nt = 0; nt < 2; nt++){
            int cc = cEp + nt*8;
            #pragma unroll
            for (int half_ = 0; half_ < 2; half_++){
                int rr = rEp + mt*16 + half_*8;
                float g0 = G[mt][nt][half_*2+0], u0 = U[mt][nt][half_*2+0];
                float g1 = G[mt][nt][half_*2+1], u1 = U[mt][nt][half_*2+1];
                float v0 = g0/(1.0f+__expf(-g0))*u0;
                float v1 = g1/(1.0f+__expf(-g1))*u1;
                __half2 hv;
                hv.x = __float2half(v0);
                hv.y = __float2half(v1);
                *(__half2*)(Oh + (size_t)rr*N + cc) = hv;
            }
        }
    }
}

// ------------------------- residual GEMM + row sumsq (R12 form) -------------
// Cf += A@B^T; writes per-CTA partial sumsq of final rows to
// Spart[row*npartx + blockIdx.x] (deterministic fixed-order reduction).
__global__ void __launch_bounds__(256,2) mma_gemm2(
    const __half* __restrict__ A,
    const __half* __restrict__ Bw,
    float* __restrict__ Cf,
    float* __restrict__ Spart, int npartx,
    int K, int N)
{
    constexpr int CHUNK = 64;
    constexpr int ROWB  = 128;
    constexpr int TILE_B = 128*ROWB;     // 16KB
    constexpr int STAGE  = 2*TILE_B;     // 32KB
    extern __shared__ char dsm[];
    const uint32_t sb = smem_u32(dsm);
    const int tid  = threadIdx.x;
    const int lane = tid & 31, warp = tid >> 5;
    const int wm = warp >> 2, wn = warp & 3;
    const int rowBase = blockIdx.y*128;
    const int colBase = blockIdx.x*128;

    const __half* pA = A  + (size_t)rowBase*K;
    const __half* pB = Bw + (size_t)colBase*K;

    auto load_stage = [&](uint32_t sbase, int k0){
        {
            const __half* src = pA + k0;
            #pragma unroll
            for (int it = 0; it < 4; it++){
                int i = tid + it*256;
                int row = i >> 3, seg = i & 7;
                uint32_t off = (uint32_t)(row*ROWB + ((seg ^ (row & 7))<<4));
                cp16(sbase + off, (const void*)(src + row*K + seg*8));
            }
        }
        {
            const __half* src = pB + k0;
            #pragma unroll
            for (int it = 0; it < 4; it++){
                int i = tid + it*256;
                int row = i >> 3, seg = i & 7;
                uint32_t off = (uint32_t)(row*ROWB + ((seg ^ (row & 7))<<4));
                cp16(sbase + TILE_B + off, (const void*)(src + row*K + seg*8));
            }
        }
    };

    float G[4][4][4];
    #pragma unroll
    for (int a=0;a<4;a++)
        #pragma unroll
        for (int b=0;b<4;b++)
            #pragma unroll
            for (int c=0;c<4;c++) G[a][b][c]=0.f;

    const int nCh = K / CHUNK;
    load_stage(sb + 0*STAGE, 0);        cp_commit();
    load_stage(sb + 1*STAGE, CHUNK);    cp_commit();
    load_stage(sb + 2*STAGE, 2*CHUNK);  cp_commit();

    const int rA = lane & 15;
    const int segSel = lane >> 4;
    const int xorA = rA & 7;

    int stgIdx = 0;
    for (int c = 0; c < nCh; c++){
        const uint32_t stg = sb + (uint32_t)stgIdx*STAGE;
        cp_wait<2>();
        __syncthreads();

        const uint32_t aBase = stg + (uint32_t)((wm*64 + rA)*ROWB);
        const uint32_t bBase = stg + TILE_B + (uint32_t)((wn*32 + rA)*ROWB);

        #pragma unroll
        for (int ks = 0; ks < 4; ks++){
            const uint32_t segOff = (uint32_t)(((2*ks + segSel) ^ xorA) << 4);
            uint32_t aF[4][4];
            #pragma unroll
            for (int mt = 0; mt < 4; mt++)
                ldsm4(aF[mt], aBase + mt*16*ROWB + segOff);
            #pragma unroll
            for (int bt = 0; bt < 2; bt++){
                uint32_t bh[4];
                ldsm4(bh, bBase + bt*16*ROWB + segOff);
                #pragma unroll
                for (int mt = 0; mt < 4; mt++){
                    mma16816(G[mt][bt*2+0], aF[mt], bh[0], bh[2]);
                    mma16816(G[mt][bt*2+1], aF[mt], bh[1], bh[3]);
                }
            }
        }
        __syncthreads();
        if (c + 3 < nCh) load_stage(stg, (c+3)*CHUNK);
        cp_commit();
        stgIdx = (stgIdx==2) ? 0 : stgIdx+1;
    }

    // epilogue: residual add + accumulate per-row sumsq
    const int rEp = rowBase + wm*64 + (lane >> 2);
    const int cEp = colBase + wn*32 + (lane & 3)*2;
    float rsum[4][2];
    #pragma unroll
    for (int a=0;a<4;a++){ rsum[a][0]=0.f; rsum[a][1]=0.f; }
    #pragma unroll
    for (int mt = 0; mt < 4; mt++){
        #pragma unroll
        for (int nt = 0; nt < 4; nt++){
            int cc = cEp + nt*8;
            #pragma unroll
            for (int half_ = 0; half_ < 2; half_++){
                int rr = rEp + mt*16 + half_*8;
                float2 o;
                o.x = G[mt][nt][half_*2+0];
                o.y = G[mt][nt][half_*2+1];
                float2* cp2 = (float2*)(Cf + (size_t)rr*N + cc);
                float2 old = *cp2;
                o.x += old.x; o.y += old.y;
                *cp2 = o;
                rsum[mt][half_] += o.x*o.x + o.y*o.y;
            }
        }
    }
    __syncthreads();
    float* part = (float*)dsm;              // 128 x 16 floats = 8KB
    const int slot = wn*4 + (lane & 3);
    #pragma unroll
    for (int mt = 0; mt < 4; mt++)
        #pragma unroll
        for (int half_ = 0; half_ < 2; half_++){
            int lr = wm*64 + (lane>>2) + mt*16 + half_*8;
            part[lr*16 + slot] = rsum[mt][half_];
        }
    __syncthreads();
    if (tid < 128){
        float s = 0.f;
        #pragma unroll
        for (int q = 0; q < 16; q++) s += part[tid*16 + q];
        Spart[(size_t)(rowBase + tid)*npartx + blockIdx.x] = s;
    }
}

// ------------------------- lm_head GEMM (2-term hi/lo, 2-stage) -------------
__global__ void __launch_bounds__(256,2) mma_gemm0(
    const __half* __restrict__ A,
    const __half* __restrict__ Bh,  const __half* __restrict__ Bl,
    float* __restrict__ Cf,
    int K, int N)
{
    constexpr int CHUNK = 64;
    constexpr int ROWB  = 128;
    constexpr int TILE_B = 128*ROWB;
    constexpr int STAGE  = 3*TILE_B;     // 48KB
    extern __shared__ char dsm[];
    const uint32_t sb = smem_u32(dsm);
    const int tid  = threadIdx.x;
    const int lane = tid & 31, warp = tid >> 5;
    const int wm = warp >> 2, wn = warp & 3;
    const int rowBase = blockIdx.y*128;
    const int colBase = blockIdx.x*128;

    const uint32_t tiles0 = sb;
    const uint32_t tiles1 = sb + STAGE;

    const __half* ps[3];
    ps[0] = A  + (size_t)rowBase*K;
    ps[1] = Bh + (size_t)colBase*K;
    ps[2] = Bl + (size_t)colBase*K;

    auto load_stage = [&](uint32_t sbase, int k0){
        #pragma unroll
        for (int t = 0; t < 3; t++){
            const __half* src = ps[t] + k0;
            const uint32_t tb = sbase + (uint32_t)t*TILE_B;
            #pragma unroll
            for (int it = 0; it < 4; it++){
                int i = tid + it*256;
                int row = i >> 3, seg = i & 7;
                uint32_t off = (uint32_t)(row*ROWB + ((seg ^ (row & 7))<<4));
                cp16(tb + off, (const void*)(src + row*K + seg*8));
            }
        }
    };

    float G[4][4][4];
    #pragma unroll
    for (int a=0;a<4;a++)
        #pragma unroll
        for (int b=0;b<4;b++)
            #pragma unroll
            for (int c=0;c<4;c++) G[a][b][c]=0.f;

    const int nCh = K / CHUNK;
    load_stage(tiles0, 0);      cp_commit();
    load_stage(tiles1, CHUNK);  cp_commit();

    const int rA = lane & 15;
    const int segSel = lane >> 4;
    const int xorA = rA & 7;

    for (int c = 0; c < nCh; c++){
        const uint32_t stg = (c & 1) ? tiles1 : tiles0;
        if (c + 1 < nCh) cp_wait<1>(); else cp_wait<0>();
        __syncthreads();

        const uint32_t aBase = stg + (uint32_t)((wm*64 + rA)*ROWB);
        const uint32_t bBase = stg + TILE_B + (uint32_t)((wn*32 + rA)*ROWB);

        #pragma unroll
        for (int ks = 0; ks < 4; ks++){
            const uint32_t segOff = (uint32_t)(((2*ks + segSel) ^ xorA) << 4);
            uint32_t aF[4][4];
            #pragma unroll
            for (int mt = 0; mt < 4; mt++)
                ldsm4(aF[mt], aBase + mt*16*ROWB + segOff);
            #pragma unroll
            for (int bt = 0; bt < 2; bt++){
                uint32_t bh[4], bl[4];
                ldsm4(bh, bBase + bt*16*ROWB + segOff);
                ldsm4(bl, bBase + TILE_B + bt*16*ROWB + segOff);
                #pragma unroll
                for (int mt = 0; mt < 4; mt++){
                    mma16816(G[mt][bt*2+0], aF[mt], bh[0], bh[2]);
                    mma16816(G[mt][bt*2+1], aF[mt], bh[1], bh[3]);
                    mma16816(G[mt][bt*2+0], aF[mt], bl[0], bl[2]);
                    mma16816(G[mt][bt*2+1], aF[mt], bl[1], bl[3]);
                }
            }
        }
        __syncthreads();
        if (c + 2 < nCh){
            load_stage(stg, (c+2)*CHUNK);
            cp_commit();
        }
    }

    const int rEp = rowBase + wm*64 + (lane >> 2);
    const int cEp = colBase + wn*32 + (lane & 3)*2;
    #pragma unroll
    for (int mt = 0; mt < 4; mt++){
        #pragma unroll
        for (int nt = 0; nt < 4; nt++){
            int cc = cEp + nt*8;
            #pragma unroll
            for (int half_ = 0; half_ < 2; half_++){
                int rr = rEp + mt*16 + half_*8;
                float2 o;
                o.x = G[mt][nt][half_*2+0];
                o.y = G[mt][nt][half_*2+1];
                *(float2*)(Cf + (size_t)rr*N + cc) = o;
            }
        }
    }
}

// ------------------------- aux kernels -------------------------------------
__global__ void copy4_kernel(float4* __restrict__ dst, const float4* __restrict__ src, int n4){
    int i = blockIdx.x*blockDim.x + threadIdx.x;
    if (i < n4) dst[i] = src[i];
}

__global__ void copy_init_kernel(const float4* __restrict__ z_in,
                                 const float4* __restrict__ h_in,
                                 const float4* __restrict__ mem_in){
    int i = blockIdx.x*blockDim.x + threadIdx.x;
    const int NZ = B_*S_*H_/4, NH = B_*P_/4, NM = B_*SLOTS_*M_/4;
    if (i < NZ){ ((float4*)g_z)[i] = z_in[i]; return; }
    i -= NZ;
    if (i < NH){ ((float4*)g_h)[i] = h_in[i]; return; }
    i -= NH;
    if (i < NM){ ((float4*)g_mem)[i] = mem_in[i]; }
}

// convert recurrent weights to single fp16; lm_head to hi/lo split
__global__ void split_all_kernel(const float* __restrict__ wt_gu, const float* __restrict__ wt_d,
                                 const float* __restrict__ wm_gu, const float* __restrict__ wm_d,
                                 const float* __restrict__ lmh){
    long long i = (long long)(blockIdx.x*blockDim.x + threadIdx.x)*4;
    const float* src; __half* hd;
    if (i < NS0)             { src=wt_gu; hd=g_wtgu; }
    else if ((i-=NS0) < NS1) { src=wt_d;  hd=g_wtd;  }
    else if ((i-=NS1) < NS2) { src=wm_gu; hd=g_wmgu; }
    else if ((i-=NS2) < NS3) { src=wm_d;  hd=g_wmd;  }
    else if ((i-=NS3) < NS4) {
        float4 v = *(const float4*)(lmh + i);
        __half h0,l0,h1,l1,h2,l2,h3,l3;
        splitw(v.x,h0,l0); splitw(v.y,h1,l1); splitw(v.z,h2,l2); splitw(v.w,h3,l3);
        __half2 a,b,c,d;
        a.x=h0;a.y=h1; b.x=h2;b.y=h3; c.x=l0;c.y=l1; d.x=l2;d.y=l3;
        ((__half2*)(g_lmh_h+i))[0]=a; ((__half2*)(g_lmh_h+i))[1]=b;
        ((__half2*)(g_lmh_l+i))[0]=c; ((__half2*)(g_lmh_l+i))[1]=d;
        return;
    }
    else return;
    float4 v = *(const float4*)(src + i);
    __half2 a,b;
    a.x=__float2half(v.x); a.y=__float2half(v.y);
    b.x=__float2half(v.z); b.y=__float2half(v.w);
    ((__half2*)(hd+i))[0]=a; ((__half2*)(hd+i))[1]=b;
}

__global__ void pooled1_kernel(){
    int b = blockIdx.x, chunk = blockIdx.y, h = threadIdx.x;
    const float* p = g_z + (size_t)b*S_*H_ + (size_t)chunk*(S_/4)*H_ + h;
    float a0=0.f,a1=0.f,a2=0.f,a3=0.f;
    #pragma unroll 4
    for (int s = 0; s < S_/4; s += 4){
        a0 += p[(s+0)*H_]; a1 += p[(s+1)*H_];
        a2 += p[(s+2)*H_]; a3 += p[(s+3)*H_];
    }
    g_pp[(b*4+chunk)*H_ + h] = a0+a1+a2+a3;
}

// planner: warp-per-output coalesced gemvs; 512 threads, pooled2 folded in
__global__ void planner_kernel(
    const float* __restrict__ w1, const float* __restrict__ b1,
    const float* __restrict__ w2, const float* __restrict__ b2,
    const float* __restrict__ hdw, const float* __restrict__ hdb,
    const float* __restrict__ filmw, const float* __restrict__ filmb,
    const float* __restrict__ haltw, const float* __restrict__ haltb,
    const float* __restrict__ qw, const float* __restrict__ qb,
    const float* __restrict__ kw, const float* __restrict__ kb,
    const float* __restrict__ vw, const float* __restrict__ vb,
    const float* __restrict__ gw, const float* __restrict__ gb,
    const float* __restrict__ ow, const float* __restrict__ ob,
    float* __restrict__ halt_out)
{
    int b = blockIdx.x, tid = threadIdx.x;
    int lane = tid & 31, wp = tid >> 5;
    __shared__ float x[768];
    __shared__ float a1s[256];
    __shared__ float hm[256];
    __shared__ float qv[128], kv2[128], vv[128];
    __shared__ float rq[64], rk[64];
    __shared__ float ctxm[128];
    __shared__ float sgate;

    x[tid] = (g_pp[(b*4+0)*H_+tid] + g_pp[(b*4+1)*H_+tid]
            + g_pp[(b*4+2)*H_+tid] + g_pp[(b*4+3)*H_+tid]) * (1.0f/S_);
    if (tid < 256) x[512+tid] = g_h[b*P_+tid];
    __syncthreads();

    for (int j = wp; j < 256; j += 16){
        const float* w = w1 + j*768;
        float acc = 0.f;
        for (int k = lane; k < 768; k += 32) acc += w[k]*x[k];
        acc = wred(acc);
        if (lane==0){
            float v = acc + b1[j];
            a1s[j] = 0.5f*v*(1.0f + erff(v*0.70710678118654752f));
        }
    }
    __syncthreads();
    for (int j = wp; j < 256; j += 16){
        const float* w = w2 + j*256;
        float acc = 0.f;
        for (int k = lane; k < 256; k += 32) acc += w[k]*a1s[k];
        acc = wred(acc);
        if (lane==0) hm[j] = acc + b2[j];
    }
    __syncthreads();
    for (int j = wp; j < 256; j += 16){
        const float* w = hdw + j*256;
        float acc = 0.f;
        for (int k = lane; k < 256; k += 32) acc += w[k]*hm[k];
        acc = wred(acc);
        if (lane==0) g_h[b*P_+j] = x[512+j] + acc + hdb[j];
    }
    for (int j = wp; j < 2*H_; j += 16){
        const float* w = filmw + j*256;
        float acc = 0.f;
        for (int k = lane; k < 256; k += 32) acc += w[k]*hm[k];
        acc = wred(acc);
        if (lane==0) g_film[b*2*H_+j] = acc + filmb[j];
    }
    if (wp == 0){
        float acc = 0.f;
        for (int k = lane; k < 256; k += 32) acc += haltw[k]*hm[k];
        acc = wred(acc);
        if (lane==0) halt_out[b] = acc + haltb[0];
    }
    if (wp == 1){
        float acc = 0.f;
        for (int k = lane; k < 256; k += 32) acc += gw[k]*hm[k];
        acc = wred(acc);
        if (lane==0) sgate = 1.0f/(1.0f+expf(-(acc + gb[0])));
    }
    for (int j = wp; j < 384; j += 16){
        int which = j >> 7, jj = j & 127;
        const float* w  = (which==0 ? qw : which==1 ? kw : vw) + jj*256;
        float acc = 0.f;
        for (int k = lane; k < 256; k += 32) acc += w[k]*hm[k];
        acc = wred(acc);
        if (lane==0){
            float bb = (which==0 ? qb[jj] : which==1 ? kb[jj] : vb[jj]);
            float v = acc + bb;
            if (which==0) qv[jj]=v; else if (which==1) kv2[jj]=v; else vv[jj]=v;
        }
    }
    __syncthreads();

    const float* memb = g_mem + b*SLOTS_*M_;
    for (int n = wp; n < 64; n += 16){
        const float* m = memb + n*M_;
        float aq=0.f, ak=0.f;
        for (int d = lane; d < 128; d += 32){ float mv=m[d]; aq+=mv*qv[d]; ak+=mv*kv2[d]; }
        aq = wred(aq); ak = wred(ak);
        if (lane==0){ rq[n]=aq*INV_SQRT_M_; rk[n]=ak*INV_SQRT_M_; }
    }
    __syncthreads();
    if (wp < 2){
        float* r = wp ? rk : rq;
        float v0 = r[lane], v1 = r[lane+32];
        float mx = fmaxf(v0,v1);
        #pragma unroll
        for (int o=16;o;o>>=1) mx = fmaxf(mx, __shfl_xor_sync(0xffffffffu, mx, o));
        float e0 = expf(v0-mx), e1 = expf(v1-mx);
        float s = e0+e1;
        #pragma unroll
        for (int o=16;o;o>>=1) s += __shfl_xor_sync(0xffffffffu, s, o);
        float inv = 1.0f/s;
        r[lane] = e0*inv; r[lane+32] = e1*inv;
    }
    __syncthreads();
    if (tid < 128){
        float acc=0.f;
        #pragma unroll 4
        for (int n2=0;n2<64;n2++) acc += rq[n2]*memb[n2*M_+tid];
        ctxm[tid]=acc;
    }
    __syncthreads();
    for (int j = wp; j < H_; j += 16){
        const float* w = ow + j*M_;
        float acc = 0.f;
        for (int d = lane; d < 128; d += 32) acc += w[d]*ctxm[d];
        acc = wred(acc);
        if (lane==0) g_ctx[b*H_+j] = acc + ob[j];
    }
    float gv = sgate;
    for (int idx=tid; idx<SLOTS_*M_; idx+=512){
        int n2 = idx>>7, d2 = idx&127;
        float w = rk[n2]*gv;
        g_mem[b*SLOTS_*M_+idx] = memb[idx]*(1.0f-w) + w*vv[d2];
    }
}

// (B,S,H) -> (B,H,S); UPD: fused z-update (reads g_ctx/emb, keeps g_z fresh);
// NORM: applies per-row rmsnorm scale from g_zpart on read (fuses the i=0
// rmsnorm_z). No g_z store in either variant (g_z is fully overwritten by
// transpose_tz_film before any other reader) EXCEPT UPD, which must persist
// the updated trunk?  -> No: audited, transpose_tz_film overwrites g_z.
template<bool UPD, bool NORM>
__global__ void transpose_zt_split(const int* __restrict__ inputs,
                                   const float* __restrict__ embed_w){
    __shared__ float tile[32][33];
    __shared__ float scl[32];
    int b = blockIdx.z;
    int s0 = blockIdx.x*32, h0 = blockIdx.y*32;
    if (NORM){
        if (threadIdx.y == 0){
            const float* pp = g_zpart + (size_t)(b*S_ + s0 + threadIdx.x)*4;
            float ss = pp[0] + pp[1] + pp[2] + pp[3];
            scl[threadIdx.x] = rsqrtf(ss/(float)H_ + 1e-5f);
        }
        __syncthreads();
    }
    int h = h0 + threadIdx.x;
    for (int r=threadIdx.y; r<32; r+=8){
        size_t idx = (size_t)b*S_*H_ + (size_t)(s0+r)*H_ + h;
        float v = g_z[idx];
        if (NORM) v *= scl[r];
        if (UPD){
            int tok = inputs[b*S_ + s0 + r];
            v += SQRT_H_*embed_w[tok*H_ + h] + g_ctx[b*H_ + h];
        }
        tile[r][threadIdx.x] = v;
    }
    __syncthreads();
    int s = s0 + threadIdx.x;
    for (int r=threadIdx.y; r<32; r+=8){
        float v = tile[threadIdx.x][r];
        size_t idx = (size_t)b*H_*S_ + (size_t)(h0+r)*S_ + s;
        g_t[idx] = v;
        g_th[idx] = __float2half(v);
    }
}

// (B,H,S) -> (B,S,H): rmsnorm scale (from g_tpart) + FiLM; writes z + fp16 z
__global__ void transpose_tz_film_split(){
    __shared__ float tile[32][33];
    __shared__ float scl[32];
    int b = blockIdx.z;
    int s0 = blockIdx.x*32, h0 = blockIdx.y*32;
    if (threadIdx.y == 0){
        const float* pp = g_tpart + (size_t)(b*H_ + h0 + threadIdx.x)*16;
        float s = 0.f;
        #pragma unroll
        for (int q = 0; q < 16; q++) s += pp[q];
        scl[threadIdx.x] = rsqrtf(s/(float)S_ + 1e-5f);
    }
    __syncthreads();
    int s = s0 + threadIdx.x;
    for (int r=threadIdx.y; r<32; r+=8)
        tile[r][threadIdx.x] = g_t[(size_t)b*H_*S_ + (size_t)(h0+r)*S_ + s] * scl[r];
    __syncthreads();
    int h = h0 + threadIdx.x;
    float sc = 1.0f + g_film[b*2*H_ + h];
    float sh = g_film[b*2*H_ + H_ + h];
    for (int r=threadIdx.y; r<32; r+=8){
        float v = tile[threadIdx.x][r]*sc + sh;
        size_t idx = (size_t)b*S_*H_ + (size_t)(s0+r)*H_ + h;
        g_z[idx] = v;
        g_zh[idx] = __float2half(v);
    }
}

// single-pass rmsnorm of z rows using precomputed sumsq partials (g_zpart).
// Only launched for the LAST layer of each step (i=0's norm is fused into
// the next transpose_zt).
__global__ void rmsnorm_z_split_kernel(){
    int row = blockIdx.x;
    __shared__ float ssum;
    if (threadIdx.x == 0){
        const float* pp = g_zpart + (size_t)row*4;
        ssum = pp[0] + pp[1] + pp[2] + pp[3];
    }
    __syncthreads();
    float scale = rsqrtf(ssum/(float)H_ + 1e-5f);
    float* p = g_z + (size_t)row*H_;
    for (int i=threadIdx.x; i<H_; i+=256){
        float v = p[i]*scale;
        p[i] = v;
        g_zh[(size_t)row*H_ + i] = __float2half(v);
    }
}

// ---------------------------------------------------------------------------
extern "C" void kernel_launch(void* const* d_in, const int* in_sizes, int n_in,
                              void* d_out, int out_size)
{
    const int*   inputs    = (const int*)  d_in[0];
    const float* z_in      = (const float*)d_in[1];
    const float* h_in      = (const float*)d_in[2];
    const float* mem_in    = (const float*)d_in[3];
    const float* embed_w   = (const float*)d_in[4];
    const float* lm_head_w = (const float*)d_in[5];
    const float* w1        = (const float*)d_in[6];
    const float* b1        = (const float*)d_in[7];
    const float* w2        = (const float*)d_in[8];
    const float* b2        = (const float*)d_in[9];
    const float* hdw       = (const float*)d_in[10];
    const float* hdb       = (const float*)d_in[11];
    const float* filmw     = (const float*)d_in[12];
    const float* filmb     = (const float*)d_in[13];
    const float* haltw     = (const float*)d_in[14];
    const float* haltb     = (const float*)d_in[15];
    const float* qw        = (const float*)d_in[16];
    const float* qb        = (const float*)d_in[17];
    const float* kw        = (const float*)d_in[18];
    const float* kb        = (const float*)d_in[19];
    const float* vw        = (const float*)d_in[20];
    const float* vb        = (const float*)d_in[21];
    const float* gw        = (const float*)d_in[22];
    const float* gb        = (const float*)d_in[23];
    const float* ow        = (const float*)d_in[24];
    const float* ob        = (const float*)d_in[25];
    const float* wt_gu     = (const float*)d_in[26];
    const float* wt_d      = (const float*)d_in[27];
    const float* wm_gu     = (const float*)d_in[28];
    const float* wm_d      = (const float*)d_in[29];
    float* out = (float*)d_out;

    float *zp, *tp, *hp, *memp, *tpart, *zpart;
    cudaGetSymbolAddress((void**)&zp,    g_z);
    cudaGetSymbolAddress((void**)&tp,    g_t);
    cudaGetSymbolAddress((void**)&hp,    g_h);
    cudaGetSymbolAddress((void**)&memp,  g_mem);
    cudaGetSymbolAddress((void**)&tpart, g_tpart);
    cudaGetSymbolAddress((void**)&zpart, g_zpart);

    __half *th, *zh, *ah;
    __half *wtgu, *wtd, *wmgu, *wmd, *lmhh, *lmhl;
    cudaGetSymbolAddress((void**)&th, g_th);
    cudaGetSymbolAddress((void**)&zh, g_zh);
    cudaGetSymbolAddress((void**)&ah, g_acth);
    cudaGetSymbolAddress((void**)&wtgu, g_wtgu);
    cudaGetSymbolAddress((void**)&wtd,  g_wtd);
    cudaGetSymbolAddress((void**)&wmgu, g_wmgu);
    cudaGetSymbolAddress((void**)&wmd,  g_wmd);
    cudaGetSymbolAddress((void**)&lmhh, g_lmh_h);
    cudaGetSymbolAddress((void**)&lmhl, g_lmh_l);

    const int SMEM_GLU = 3*32*1024;  // 96KB per CTA, 2 CTAs/SM
    const int SMEM_G2  = 3*32*1024;  // 96KB per CTA, 2 CTAs/SM
    const int SMEM_G0  = 2*48*1024;  // 96KB per CTA, 2 CTAs/SM
    cudaFuncSetAttribute(mma_gemm_glu, cudaFuncAttributeMaxDynamicSharedMemorySize, SMEM_GLU);
    cudaFuncSetAttribute(mma_gemm2,    cudaFuncAttributeMaxDynamicSharedMemorySize, SMEM_G2);
    cudaFuncSetAttribute(mma_gemm0,    cudaFuncAttributeMaxDynamicSharedMemorySize, SMEM_G0);

    dim3 trBlk(32,8);
    dim3 trGrd(S_/32, H_/32, B_);

    // state init
    {
        int tot4 = (B_*S_*H_ + B_*P_ + B_*SLOTS_*M_)/4;
        copy_init_kernel<<<(tot4+255)/256, 256>>>((const float4*)z_in, (const float4*)h_in, (const float4*)mem_in);
    }
    // weight converts/splits
    split_all_kernel<<<(NSALL/4+255)/256, 256>>>(wt_gu, wt_d, wm_gu, wm_d, lm_head_w);

    for (int st=0; st<HALT_STEPS_; st++){
        pooled1_kernel<<<dim3(B_,4), 512>>>();
        planner_kernel<<<B_, 512>>>(w1,b1,w2,b2,hdw,hdb,filmw,filmb,haltw,haltb,
                                    qw,qb,kw,kb,vw,vb,gw,gb,ow,ob,
                                    out + HALT_OFF + st*B_);

        for (int i=0; i<L_; i++){
            // i=0: fused z-update; i=1: fused rmsnorm of layer-0's z
            if (i==0) transpose_zt_split<true,false><<<trGrd, trBlk>>>(inputs, embed_w);
            else      transpose_zt_split<false,true><<<trGrd, trBlk>>>(inputs, embed_w);
            {
                size_t go = (size_t)i*2*IT_*S_;
                mma_gemm_glu<<<dim3(IT_/64, (B_*H_)/128), 256, SMEM_GLU>>>(
                    th, wtgu+go, wtgu+go+(size_t)IT_*S_, ah, S_, IT_);
            }
            {
                size_t dof = (size_t)i*S_*IT_;
                mma_gemm2<<<dim3(S_/128, (B_*H_)/128), 256, SMEM_G2>>>(
                    ah, wtd+dof, tp, tpart, 16, IT_, S_);
            }
            transpose_tz_film_split<<<trGrd, trBlk>>>();
            {
                size_t go = (size_t)i*2*IM_*H_;
                mma_gemm_glu<<<dim3(IM_/64, (B_*S_)/128), 256, SMEM_GLU>>>(
                    zh, wmgu+go, wmgu+go+(size_t)IM_*H_, ah, H_, IM_);
            }
            {
                size_t dof = (size_t)i*H_*IM_;
                mma_gemm2<<<dim3(H_/128, (B_*S_)/128), 256, SMEM_G2>>>(
                    ah, wmd+dof, zp, zpart, 4, IM_, H_);
            }
            // only the step's final layer needs materialized normalized z
            if (i == L_-1)
                rmsnorm_z_split_kernel<<<B_*S_, 256>>>();
        }
        mma_gemm0<<<dim3(V_/128, (B_*S_)/128), 256, SMEM_G0>>>(
            zh, lmhh, lmhl, out + (size_t)st*B_*S_*V_, H_, V_);
    }

    // final state outputs
    copy4_kernel<<<(B_*S_*H_/4+255)/256, 256>>>((float4*)(out + ZL_OFF), (const float4*)zp, B_*S_*H_/4);
    copy4_kernel<<<(B_*P_/4+255)/256,    256>>>((float4*)(out + HOUT_OFF),(const float4*)hp, B_*P_/4);
    copy4_kernel<<<(B_*SLOTS_*M_/4+255)/256,256>>>((float4*)(out + MEM_OFF),(const float4*)memp, B_*SLOTS_*M_/4);
}

// round 15
// speedup vs baseline: 1.0524x; 1.0156x over previous
#include <cuda_runtime.h>
#include <cuda_fp16.h>
#include <math.h>
#include <stdint.h>

// Problem dims
#define B_ 32
#define S_ 2048
#define H_ 512
#define V_ 128
#define P_ 256
#define M_ 128
#define SLOTS_ 64
#define L_ 2
#define IT_ 2816
#define IM_ 768
#define HALT_STEPS_ 4

#define SQRT_H_ 22.62741699796952f
#define INV_SQRT_M_ 0.08838834764831845f

// Output offsets (fp32 elements)
#define HALT_OFF   (HALT_STEPS_*B_*S_*V_)
#define ZL_OFF     (HALT_OFF + HALT_STEPS_*B_)
#define HOUT_OFF   (ZL_OFF + B_*S_*H_)
#define MEM_OFF    (HOUT_OFF + B_*P_)

// ------------------------- static device state -----------------------------
__device__ float g_z[B_*S_*H_];
__device__ float g_t[B_*S_*H_];
__device__ float g_h[B_*P_];
__device__ float g_mem[B_*SLOTS_*M_];
__device__ float g_ctx[B_*H_];
__device__ float g_film[B_*2*H_];
// per-row sum-of-squares partials (written by residual GEMM epilogues)
__device__ float g_tpart[B_*H_*16];    // token-d: 16 col-tiles per row
__device__ float g_zpart[B_*S_*4];     // channel-d: 4 col-tiles per row

// activations: SINGLE fp16 tiles
__device__ __half g_th[B_*S_*H_];
__device__ __half g_zh[B_*S_*H_];
__device__ __half g_acth[B_*S_*IM_];

// recurrent weights: SINGLE fp16; lm_head keeps hi/lo split
__device__ __half g_wtgu[L_*2*IT_*S_];
__device__ __half g_wtd [L_*S_*IT_];
__device__ __half g_wmgu[L_*2*IM_*H_];
__device__ __half g_wmd [L_*H_*IM_];
__device__ __half g_lmh_h[V_*H_], g_lmh_l[V_*H_];

// split sizes (floats)
#define NS0 (L_*2*IT_*S_)
#define NS1 (L_*S_*IT_)
#define NS2 (L_*2*IM_*H_)
#define NS3 (L_*H_*IM_)
#define NS4 (V_*H_)
#define NSALL (NS0+NS1+NS2+NS3+NS4)

// ------------------------- PTX helpers -------------------------------------
__device__ __forceinline__ uint32_t smem_u32(const void* p){
    uint32_t a;
    asm("{ .reg .u64 t; cvta.to.shared.u64 t, %1; cvt.u32.u64 %0, t; }" : "=r"(a) : "l"(p));
    return a;
}
__device__ __forceinline__ void cp16(uint32_t s, const void* g){
    asm volatile("cp.async.cg.shared.global [%0], [%1], 16;" :: "r"(s), "l"(g));
}
__device__ __forceinline__ void cp_commit(){ asm volatile("cp.async.commit_group;" ::: "memory"); }
template<int N> __device__ __forceinline__ void cp_wait(){
    asm volatile("cp.async.wait_group %0;" :: "n"(N) : "memory");
}
__device__ __forceinline__ void ldsm4(uint32_t* r, uint32_t addr){
    asm volatile("ldmatrix.sync.aligned.m8n8.x4.shared.b16 {%0,%1,%2,%3}, [%4];"
        : "=r"(r[0]), "=r"(r[1]), "=r"(r[2]), "=r"(r[3]) : "r"(addr));
}
__device__ __forceinline__ void mma16816(float* c, const uint32_t* a, uint32_t b0, uint32_t b1){
    asm volatile("mma.sync.aligned.m16n8k16.row.col.f32.f16.f16.f32 "
        "{%0,%1,%2,%3}, {%4,%5,%6,%7}, {%8,%9}, {%0,%1,%2,%3};"
        : "+f"(c[0]), "+f"(c[1]), "+f"(c[2]), "+f"(c[3])
        : "r"(a[0]), "r"(a[1]), "r"(a[2]), "r"(a[3]), "r"(b0), "r"(b1));
}
__device__ __forceinline__ void splitw(float x, __half& hi, __half& lo){
    hi = __float2half(x);
    lo = __float2half(x - __half2float(hi));
}
__device__ __forceinline__ float wred(float v){
    #pragma unroll
    for (int o=16;o;o>>=1) v += __shfl_xor_sync(0xffffffffu, v, o);
    return v;
}

// ------------------------- SwiGLU GEMM (3-stage pipe) -----------------------
// Oh = fp16(silu(A@Bg^T) * (A@Bu^T)); A, Bg, Bu single fp16, fp32 accum.
// CTA tile 128x64, 8 warps, warp tile 64x16, chunk 64, 3 stages, 2 CTAs/SM.
__global__ void __launch_bounds__(256,2) mma_gemm_glu(
    const __half* __restrict__ A,
    const __half* __restrict__ Bg, const __half* __restrict__ Bu,
    __half* __restrict__ Oh,
    int K, int N)
{
    constexpr int CHUNK = 64;
    constexpr int ROWB  = 128;
    constexpr int TA_B  = 128*ROWB;     // 16KB
    constexpr int TB_B  = 64*ROWB;      // 8KB
    constexpr int STAGE = TA_B + 2*TB_B;// 32KB
    extern __shared__ char dsm[];
    const uint32_t sb = smem_u32(dsm);
    const int tid  = threadIdx.x;
    const int lane = tid & 31, warp = tid >> 5;
    const int wm = warp >> 2, wn = warp & 3;
    const int rowBase = blockIdx.y*128;
    const int colBase = blockIdx.x*64;

    const __half* pA = A  + (size_t)rowBase*K;
    const __half* pG = Bg + (size_t)colBase*K;
    const __half* pU = Bu + (size_t)colBase*K;

    auto load_stage = [&](uint32_t sbase, int k0){
        {
            const __half* src = pA + k0;
            #pragma unroll
            for (int it = 0; it < 4; it++){
                int i = tid + it*256;
                int row = i >> 3, seg = i & 7;
                uint32_t off = (uint32_t)(row*ROWB + ((seg ^ (row & 7))<<4));
                cp16(sbase + off, (const void*)(src + row*K + seg*8));
            }
        }
        {
            const __half* src = pG + k0;
            #pragma unroll
            for (int it = 0; it < 2; it++){
                int i = tid + it*256;
                int row = i >> 3, seg = i & 7;
                uint32_t off = (uint32_t)(row*ROWB + ((seg ^ (row & 7))<<4));
                cp16(sbase + TA_B + off, (const void*)(src + row*K + seg*8));
            }
        }
        {
            const __half* src = pU + k0;
            #pragma unroll
            for (int it = 0; it < 2; it++){
                int i = tid + it*256;
                int row = i >> 3, seg = i & 7;
                uint32_t off = (uint32_t)(row*ROWB + ((seg ^ (row & 7))<<4));
                cp16(sbase + TA_B + TB_B + off, (const void*)(src + row*K + seg*8));
            }
        }
    };

    float G[4][2][4];
    float U[4][2][4];
    #pragma unroll
    for (int a=0;a<4;a++)
        #pragma unroll
        for (int b=0;b<2;b++)
            #pragma unroll
            for (int c=0;c<4;c++){ G[a][b][c]=0.f; U[a][b][c]=0.f; }

    const int nCh = K / CHUNK;
    load_stage(sb + 0*STAGE, 0);        cp_commit();
    load_stage(sb + 1*STAGE, CHUNK);    cp_commit();
    load_stage(sb + 2*STAGE, 2*CHUNK);  cp_commit();

    const int rA = lane & 15;
    const int segSel = lane >> 4;
    const int xorA = rA & 7;

    int stgIdx = 0;
    for (int c = 0; c < nCh; c++){
        const uint32_t stg = sb + (uint32_t)stgIdx*STAGE;
        cp_wait<2>();
        __syncthreads();

        const uint32_t aBase = stg + (uint32_t)((wm*64 + rA)*ROWB);
        const uint32_t bRow  = (uint32_t)((wn*16 + rA)*ROWB);

        #pragma unroll
        for (int ks = 0; ks < 4; ks++){
            const uint32_t segOff = (uint32_t)(((2*ks + segSel) ^ xorA) << 4);
            uint32_t aF[4][4];
            #pragma unroll
            for (int mt = 0; mt < 4; mt++)
                ldsm4(aF[mt], aBase + mt*16*ROWB + segOff);
            uint32_t bg[4], bu[4];
            ldsm4(bg, stg + TA_B        + bRow + segOff);
            ldsm4(bu, stg + TA_B + TB_B + bRow + segOff);
            #pragma unroll
            for (int mt = 0; mt < 4; mt++){
                mma16816(G[mt][0], aF[mt], bg[0], bg[2]);
                mma16816(G[mt][1], aF[mt], bg[1], bg[3]);
                mma16816(U[mt][0], aF[mt], bu[0], bu[2]);
                mma16816(U[mt][1], aF[mt], bu[1], bu[3]);
            }
        }
        __syncthreads();
        if (c + 3 < nCh) load_stage(stg, (c+3)*CHUNK);
        cp_commit();
        stgIdx = (stgIdx==2) ? 0 : stgIdx+1;
    }

    // epilogue: fused swiglu -> fp16
    const int rEp = rowBase + wm*64 + (lane >> 2);
    const int cEp = colBase + wn*16 + (lane & 3)*2;
    #pragma unroll
    for (int mt = 0; mt < 4; mt++){
        #pragma unroll
        for (int nt = 0; nt < 2; nt++){
            int cc = cEp + nt*8;
            #pragma unroll
            for (int half_ = 0; half_ < 2; half_++){
                int rr = rEp + mt*16 + half_*8;
                float g0 = G[mt][nt][half_*2+0], u0 = U[mt][nt][half_*2+0];
                float g1 = G[mt][nt][half_*2+1], u1 = U[mt][nt][half_*2+1];
                float v0 = g0/(1.0f+__expf(-g0))*u0;
                float v1 = g1/(1.0f+__expf(-g1))*u1;
                __half2 hv;
                hv.x = __float2half(v0);
                hv.y = __float2half(v1);
                *(__half2*)(Oh + (size_t)rr*N + cc) = hv;
            }
        }
    }
}

// ------------------------- residual GEMM + row sumsq ------------------------
// Cf += A@B^T; writes per-CTA partial sumsq of final rows to
// Spart[row*npartx + blockIdx.x] (deterministic fixed-order reduction).
__global__ void __launch_bounds__(256,2) mma_gemm2(
    const __half* __restrict__ A,
    const __half* __restrict__ Bw,
    float* __restrict__ Cf,
    float* __restrict__ Spart, int npartx,
    int K, int N)
{
    constexpr int CHUNK = 64;
    constexpr int ROWB  = 128;
    constexpr int TILE_B = 128*ROWB;     // 16KB
    constexpr int STAGE  = 2*TILE_B;     // 32KB
    extern __shared__ char dsm[];
    const uint32_t sb = smem_u32(dsm);
    const int tid  = threadIdx.x;
    const int lane = tid & 31, warp = tid >> 5;
    const int wm = warp >> 2, wn = warp & 3;
    const int rowBase = blockIdx.y*128;
    const int colBase = blockIdx.x*128;

    const __half* pA = A  + (size_t)rowBase*K;
    const __half* pB = Bw + (size_t)colBase*K;

    auto load_stage = [&](uint32_t sbase, int k0){
        {
            const __half* src = pA + k0;
            #pragma unroll
            for (int it = 0; it < 4; it++){
                int i = tid + it*256;
                int row = i >> 3, seg = i & 7;
                uint32_t off = (uint32_t)(row*ROWB + ((seg ^ (row & 7))<<4));
                cp16(sbase + off, (const void*)(src + row*K + seg*8));
            }
        }
        {
            const __half* src = pB + k0;
            #pragma unroll
            for (int it = 0; it < 4; it++){
                int i = tid + it*256;
                int row = i >> 3, seg = i & 7;
                uint32_t off = (uint32_t)(row*ROWB + ((seg ^ (row & 7))<<4));
                cp16(sbase + TILE_B + off, (const void*)(src + row*K + seg*8));
            }
        }
    };

    float G[4][4][4];
    #pragma unroll
    for (int a=0;a<4;a++)
        #pragma unroll
        for (int b=0;b<4;b++)
            #pragma unroll
            for (int c=0;c<4;c++) G[a][b][c]=0.f;

    const int nCh = K / CHUNK;
    load_stage(sb + 0*STAGE, 0);        cp_commit();
    load_stage(sb + 1*STAGE, CHUNK);    cp_commit();
    load_stage(sb + 2*STAGE, 2*CHUNK);  cp_commit();

    const int rA = lane & 15;
    const int segSel = lane >> 4;
    const int xorA = rA & 7;

    int stgIdx = 0;
    for (int c = 0; c < nCh; c++){
        const uint32_t stg = sb + (uint32_t)stgIdx*STAGE;
        cp_wait<2>();
        __syncthreads();

        const uint32_t aBase = stg + (uint32_t)((wm*64 + rA)*ROWB);
        const uint32_t bBase = stg + TILE_B + (uint32_t)((wn*32 + rA)*ROWB);

        #pragma unroll
        for (int ks = 0; ks < 4; ks++){
            const uint32_t segOff = (uint32_t)(((2*ks + segSel) ^ xorA) << 4);
            uint32_t aF[4][4];
            #pragma unroll
            for (int mt = 0; mt < 4; mt++)
                ldsm4(aF[mt], aBase + mt*16*ROWB + segOff);
            #pragma unroll
            for (int bt = 0; bt < 2; bt++){
                uint32_t bh[4];
                ldsm4(bh, bBase + bt*16*ROWB + segOff);
                #pragma unroll
                for (int mt = 0; mt < 4; mt++){
                    mma16816(G[mt][bt*2+0], aF[mt], bh[0], bh[2]);
                    mma16816(G[mt][bt*2+1], aF[mt], bh[1], bh[3]);
                }
            }
        }
        __syncthreads();
        if (c + 3 < nCh) load_stage(stg, (c+3)*CHUNK);
        cp_commit();
        stgIdx = (stgIdx==2) ? 0 : stgIdx+1;
    }

    // epilogue: residual add + accumulate per-row sumsq
    const int rEp = rowBase + wm*64 + (lane >> 2);
    const int cEp = colBase + wn*32 + (lane & 3)*2;
    float rsum[4][2];
    #pragma unroll
    for (int a=0;a<4;a++){ rsum[a][0]=0.f; rsum[a][1]=0.f; }
    #pragma unroll
    for (int mt = 0; mt < 4; mt++){
        #pragma unroll
        for (int nt = 0; nt < 4; nt++){
            int cc = cEp + nt*8;
            #pragma unroll
            for (int half_ = 0; half_ < 2; half_++){
                int rr = rEp + mt*16 + half_*8;
                float2 o;
                o.x = G[mt][nt][half_*2+0];
                o.y = G[mt][nt][half_*2+1];
                float2* cp2 = (float2*)(Cf + (size_t)rr*N + cc);
                float2 old = *cp2;
                o.x += old.x; o.y += old.y;
                *cp2 = o;
                rsum[mt][half_] += o.x*o.x + o.y*o.y;
            }
        }
    }
    __syncthreads();
    float* part = (float*)dsm;              // 128 x 16 floats = 8KB
    const int slot = wn*4 + (lane & 3);
    #pragma unroll
    for (int mt = 0; mt < 4; mt++)
        #pragma unroll
        for (int half_ = 0; half_ < 2; half_++){
            int lr = wm*64 + (lane>>2) + mt*16 + half_*8;
            part[lr*16 + slot] = rsum[mt][half_];
        }
    __syncthreads();
    if (tid < 128){
        float s = 0.f;
        #pragma unroll
        for (int q = 0; q < 16; q++) s += part[tid*16 + q];
        Spart[(size_t)(rowBase + tid)*npartx + blockIdx.x] = s;
    }
}

// ------------------------- lm_head GEMM (2-term hi/lo, 2-stage) -------------
__global__ void __launch_bounds__(256,2) mma_gemm0(
    const __half* __restrict__ A,
    const __half* __restrict__ Bh,  const __half* __restrict__ Bl,
    float* __restrict__ Cf,
    int K, int N)
{
    constexpr int CHUNK = 64;
    constexpr int ROWB  = 128;
    constexpr int TILE_B = 128*ROWB;
    constexpr int STAGE  = 3*TILE_B;     // 48KB
    extern __shared__ char dsm[];
    const uint32_t sb = smem_u32(dsm);
    const int tid  = threadIdx.x;
    const int lane = tid & 31, warp = tid >> 5;
    const int wm = warp >> 2, wn = warp & 3;
    const int rowBase = blockIdx.y*128;
    const int colBase = blockIdx.x*128;

    const uint32_t tiles0 = sb;
    const uint32_t tiles1 = sb + STAGE;

    const __half* ps[3];
    ps[0] = A  + (size_t)rowBase*K;
    ps[1] = Bh + (size_t)colBase*K;
    ps[2] = Bl + (size_t)colBase*K;

    auto load_stage = [&](uint32_t sbase, int k0){
        #pragma unroll
        for (int t = 0; t < 3; t++){
            const __half* src = ps[t] + k0;
            const uint32_t tb = sbase + (uint32_t)t*TILE_B;
            #pragma unroll
            for (int it = 0; it < 4; it++){
                int i = tid + it*256;
                int row = i >> 3, seg = i & 7;
                uint32_t off = (uint32_t)(row*ROWB + ((seg ^ (row & 7))<<4));
                cp16(tb + off, (const void*)(src + row*K + seg*8));
            }
        }
    };

    float G[4][4][4];
    #pragma unroll
    for (int a=0;a<4;a++)
        #pragma unroll
        for (int b=0;b<4;b++)
            #pragma unroll
            for (int c=0;c<4;c++) G[a][b][c]=0.f;

    const int nCh = K / CHUNK;
    load_stage(tiles0, 0);      cp_commit();
    load_stage(tiles1, CHUNK);  cp_commit();

    const int rA = lane & 15;
    const int segSel = lane >> 4;
    const int xorA = rA & 7;

    for (int c = 0; c < nCh; c++){
        const uint32_t stg = (c & 1) ? tiles1 : tiles0;
        if (c + 1 < nCh) cp_wait<1>(); else cp_wait<0>();
        __syncthreads();

        const uint32_t aBase = stg + (uint32_t)((wm*64 + rA)*ROWB);
        const uint32_t bBase = stg + TILE_B + (uint32_t)((wn*32 + rA)*ROWB);

        #pragma unroll
        for (int ks = 0; ks < 4; ks++){
            const uint32_t segOff = (uint32_t)(((2*ks + segSel) ^ xorA) << 4);
            uint32_t aF[4][4];
            #pragma unroll
            for (int mt = 0; mt < 4; mt++)
                ldsm4(aF[mt], aBase + mt*16*ROWB + segOff);
            #pragma unroll
            for (int bt = 0; bt < 2; bt++){
                uint32_t bh[4], bl[4];
                ldsm4(bh, bBase + bt*16*ROWB + segOff);
                ldsm4(bl, bBase + TILE_B + bt*16*ROWB + segOff);
                #pragma unroll
                for (int mt = 0; mt < 4; mt++){
                    mma16816(G[mt][bt*2+0], aF[mt], bh[0], bh[2]);
                    mma16816(G[mt][bt*2+1], aF[mt], bh[1], bh[3]);
                    mma16816(G[mt][bt*2+0], aF[mt], bl[0], bl[2]);
                    mma16816(G[mt][bt*2+1], aF[mt], bl[1], bl[3]);
                }
            }
        }
        __syncthreads();
        if (c + 2 < nCh){
            load_stage(stg, (c+2)*CHUNK);
            cp_commit();
        }
    }

    const int rEp = rowBase + wm*64 + (lane >> 2);
    const int cEp = colBase + wn*32 + (lane & 3)*2;
    #pragma unroll
    for (int mt = 0; mt < 4; mt++){
        #pragma unroll
        for (int nt = 0; nt < 4; nt++){
            int cc = cEp + nt*8;
            #pragma unroll
            for (int half_ = 0; half_ < 2; half_++){
                int rr = rEp + mt*16 + half_*8;
                float2 o;
                o.x = G[mt][nt][half_*2+0];
                o.y = G[mt][nt][half_*2+1];
                *(float2*)(Cf + (size_t)rr*N + cc) = o;
            }
        }
    }
}

// ------------------------- aux kernels -------------------------------------
__global__ void copy4_kernel(float4* __restrict__ dst, const float4* __restrict__ src, int n4){
    int i = blockIdx.x*blockDim.x + threadIdx.x;
    if (i < n4) dst[i] = src[i];
}

__global__ void copy_init_kernel(const float4* __restrict__ z_in,
                                 const float4* __restrict__ h_in,
                                 const float4* __restrict__ mem_in){
    int i = blockIdx.x*blockDim.x + threadIdx.x;
    const int NZ = B_*S_*H_/4, NH = B_*P_/4, NM = B_*SLOTS_*M_/4;
    if (i < NZ){ ((float4*)g_z)[i] = z_in[i]; return; }
    i -= NZ;
    if (i < NH){ ((float4*)g_h)[i] = h_in[i]; return; }
    i -= NH;
    if (i < NM){ ((float4*)g_mem)[i] = mem_in[i]; }
}

// convert recurrent weights to single fp16; lm_head to hi/lo split
__global__ void split_all_kernel(const float* __restrict__ wt_gu, const float* __restrict__ wt_d,
                                 const float* __restrict__ wm_gu, const float* __restrict__ wm_d,
                                 const float* __restrict__ lmh){
    long long i = (long long)(blockIdx.x*blockDim.x + threadIdx.x)*4;
    const float* src; __half* hd;
    if (i < NS0)             { src=wt_gu; hd=g_wtgu; }
    else if ((i-=NS0) < NS1) { src=wt_d;  hd=g_wtd;  }
    else if ((i-=NS1) < NS2) { src=wm_gu; hd=g_wmgu; }
    else if ((i-=NS2) < NS3) { src=wm_d;  hd=g_wmd;  }
    else if ((i-=NS3) < NS4) {
        float4 v = *(const float4*)(lmh + i);
        __half h0,l0,h1,l1,h2,l2,h3,l3;
        splitw(v.x,h0,l0); splitw(v.y,h1,l1); splitw(v.z,h2,l2); splitw(v.w,h3,l3);
        __half2 a,b,c,d;
        a.x=h0;a.y=h1; b.x=h2;b.y=h3; c.x=l0;c.y=l1; d.x=l2;d.y=l3;
        ((__half2*)(g_lmh_h+i))[0]=a; ((__half2*)(g_lmh_h+i))[1]=b;
        ((__half2*)(g_lmh_l+i))[0]=c; ((__half2*)(g_lmh_l+i))[1]=d;
        return;
    }
    else return;
    float4 v = *(const float4*)(src + i);
    __half2 a,b;
    a.x=__float2half(v.x); a.y=__float2half(v.y);
    b.x=__float2half(v.z); b.y=__float2half(v.w);
    ((__half2*)(hd+i))[0]=a; ((__half2*)(hd+i))[1]=b;
}

// planner: 1024 threads (32 warps); pooled mean folded into the prologue.
// All gemvs are warp-per-output coalesced with warp-shuffle reduction.
__global__ void __launch_bounds__(1024) planner_kernel(
    const float* __restrict__ w1, const float* __restrict__ b1,
    const float* __restrict__ w2, const float* __restrict__ b2,
    const float* __restrict__ hdw, const float* __restrict__ hdb,
    const float* __restrict__ filmw, const float* __restrict__ filmb,
    const float* __restrict__ haltw, const float* __restrict__ haltb,
    const float* __restrict__ qw, const float* __restrict__ qb,
    const float* __restrict__ kw, const float* __restrict__ kb,
    const float* __restrict__ vw, const float* __restrict__ vb,
    const float* __restrict__ gw, const float* __restrict__ gb,
    const float* __restrict__ ow, const float* __restrict__ ob,
    float* __restrict__ halt_out)
{
    int b = blockIdx.x, tid = threadIdx.x;   // 1024 threads = 32 warps
    int lane = tid & 31, wp = tid >> 5;
    __shared__ float x[768];
    __shared__ float red2[512];
    __shared__ float a1s[256];
    __shared__ float hm[256];
    __shared__ float qv[128], kv2[128], vv[128];
    __shared__ float rq[64], rk[64];
    __shared__ float ctxm[128];
    __shared__ float sgate;

    // ---- pooled mean over s (2 chunks of 1024 rows) ----
    {
        int h = tid & 511;
        int chunk = tid >> 9;   // 0 or 1
        const float* p = g_z + (size_t)b*S_*H_ + (size_t)chunk*(S_/2)*H_ + h;
        float a0=0.f,a1=0.f,a2=0.f,a3=0.f;
        #pragma unroll 4
        for (int s = 0; s < S_/2; s += 4){
            a0 += p[(s+0)*H_]; a1 += p[(s+1)*H_];
            a2 += p[(s+2)*H_]; a3 += p[(s+3)*H_];
        }
        float v = (a0+a1)+(a2+a3);
        if (chunk) red2[h] = v;
        __syncthreads();
        if (!chunk) x[h] = (v + red2[h]) * (1.0f/S_);
        if (tid >= 512 && tid < 768) x[tid] = g_h[b*P_ + tid - 512];
    }
    __syncthreads();

    // a1 = gelu(W1 [pooled,h] + b1): 256 outputs, K=768
    for (int j = wp; j < 256; j += 32){
        const float* w = w1 + j*768;
        float acc = 0.f;
        for (int k = lane; k < 768; k += 32) acc += w[k]*x[k];
        acc = wred(acc);
        if (lane==0){
            float v = acc + b1[j];
            a1s[j] = 0.5f*v*(1.0f + erff(v*0.70710678118654752f));
        }
    }
    __syncthreads();
    // hm = W2 a1 + b2
    for (int j = wp; j < 256; j += 32){
        const float* w = w2 + j*256;
        float acc = 0.f;
        for (int k = lane; k < 256; k += 32) acc += w[k]*a1s[k];
        acc = wred(acc);
        if (lane==0) hm[j] = acc + b2[j];
    }
    __syncthreads();
    // h += hd(hm)
    for (int j = wp; j < 256; j += 32){
        const float* w = hdw + j*256;
        float acc = 0.f;
        for (int k = lane; k < 256; k += 32) acc += w[k]*hm[k];
        acc = wred(acc);
        if (lane==0) g_h[b*P_+j] = x[512+j] + acc + hdb[j];
    }
    // film: 1024 outputs
    for (int j = wp; j < 2*H_; j += 32){
        const float* w = filmw + j*256;
        float acc = 0.f;
        for (int k = lane; k < 256; k += 32) acc += w[k]*hm[k];
        acc = wred(acc);
        if (lane==0) g_film[b*2*H_+j] = acc + filmb[j];
    }
    if (wp == 0){
        float acc = 0.f;
        for (int k = lane; k < 256; k += 32) acc += haltw[k]*hm[k];
        acc = wred(acc);
        if (lane==0) halt_out[b] = acc + haltb[0];
    }
    if (wp == 1){
        float acc = 0.f;
        for (int k = lane; k < 256; k += 32) acc += gw[k]*hm[k];
        acc = wred(acc);
        if (lane==0) sgate = 1.0f/(1.0f+expf(-(acc + gb[0])));
    }
    // q,k,v: 384 outputs
    for (int j = wp; j < 384; j += 32){
        int which = j >> 7, jj = j & 127;
        const float* w  = (which==0 ? qw : which==1 ? kw : vw) + jj*256;
        float acc = 0.f;
        for (int k = lane; k < 256; k += 32) acc += w[k]*hm[k];
        acc = wred(acc);
        if (lane==0){
            float bb = (which==0 ? qb[jj] : which==1 ? kb[jj] : vb[jj]);
            float v = acc + bb;
            if (which==0) qv[jj]=v; else if (which==1) kv2[jj]=v; else vv[jj]=v;
        }
    }
    __syncthreads();

    const float* memb = g_mem + b*SLOTS_*M_;
    for (int n = wp; n < 64; n += 32){
        const float* m = memb + n*M_;
        float aq=0.f, ak=0.f;
        for (int d = lane; d < 128; d += 32){ float mv=m[d]; aq+=mv*qv[d]; ak+=mv*kv2[d]; }
        aq = wred(aq); ak = wred(ak);
        if (lane==0){ rq[n]=aq*INV_SQRT_M_; rk[n]=ak*INV_SQRT_M_; }
    }
    __syncthreads();
    if (wp < 2){
        float* r = wp ? rk : rq;
        float v0 = r[lane], v1 = r[lane+32];
        float mx = fmaxf(v0,v1);
        #pragma unroll
        for (int o=16;o;o>>=1) mx = fmaxf(mx, __shfl_xor_sync(0xffffffffu, mx, o));
        float e0 = expf(v0-mx), e1 = expf(v1-mx);
        float s = e0+e1;
        #pragma unroll
        for (int o=16;o;o>>=1) s += __shfl_xor_sync(0xffffffffu, s, o);
        float inv = 1.0f/s;
        r[lane] = e0*inv; r[lane+32] = e1*inv;
    }
    __syncthreads();
    if (tid < 128){
        float acc=0.f;
        #pragma unroll 4
        for (int n2=0;n2<64;n2++) acc += rq[n2]*memb[n2*M_+tid];
        ctxm[tid]=acc;
    }
    __syncthreads();
    // ctx = memo(ctx_m): 512 outputs K=128
    for (int j = wp; j < H_; j += 32){
        const float* w = ow + j*M_;
        float acc = 0.f;
        for (int d = lane; d < 128; d += 32) acc += w[d]*ctxm[d];
        acc = wred(acc);
        if (lane==0) g_ctx[b*H_+j] = acc + ob[j];
    }
    // mem update
    float gv = sgate;
    for (int idx=tid; idx<SLOTS_*M_; idx+=1024){
        int n2 = idx>>7, d2 = idx&127;
        float w = rk[n2]*gv;
        g_mem[b*SLOTS_*M_+idx] = memb[idx]*(1.0f-w) + w*vv[d2];
    }
}

// (B,S,H) -> (B,H,S); UPD: fused z-update; NORM: rmsnorm scale from g_zpart
// applied on read. No g_z store (transpose_tz_film fully overwrites g_z).
template<bool UPD, bool NORM>
__global__ void transpose_zt_split(const int* __restrict__ inputs,
                                   const float* __restrict__ embed_w){
    __shared__ float tile[32][33];
    __shared__ float scl[32];
    int b = blockIdx.z;
    int s0 = blockIdx.x*32, h0 = blockIdx.y*32;
    if (NORM){
        if (threadIdx.y == 0){
            const float* pp = g_zpart + (size_t)(b*S_ + s0 + threadIdx.x)*4;
            float ss = pp[0] + pp[1] + pp[2] + pp[3];
            scl[threadIdx.x] = rsqrtf(ss/(float)H_ + 1e-5f);
        }
        __syncthreads();
    }
    int h = h0 + threadIdx.x;
    for (int r=threadIdx.y; r<32; r+=8){
        size_t idx = (size_t)b*S_*H_ + (size_t)(s0+r)*H_ + h;
        float v = g_z[idx];
        if (NORM) v *= scl[r];
        if (UPD){
            int tok = inputs[b*S_ + s0 + r];
            v += SQRT_H_*embed_w[tok*H_ + h] + g_ctx[b*H_ + h];
        }
        tile[r][threadIdx.x] = v;
    }
    __syncthreads();
    int s = s0 + threadIdx.x;
    for (int r=threadIdx.y; r<32; r+=8){
        float v = tile[threadIdx.x][r];
        size_t idx = (size_t)b*H_*S_ + (size_t)(h0+r)*S_ + s;
        g_t[idx] = v;
        g_th[idx] = __float2half(v);
    }
}

// (B,H,S) -> (B,S,H): rmsnorm scale (from g_tpart) + FiLM; writes z + fp16 z
__global__ void transpose_tz_film_split(){
    __shared__ float tile[32][33];
    __shared__ float scl[32];
    int b = blockIdx.z;
    int s0 = blockIdx.x*32, h0 = blockIdx.y*32;
    if (threadIdx.y == 0){
        const float* pp = g_tpart + (size_t)(b*H_ + h0 + threadIdx.x)*16;
        float s = 0.f;
        #pragma unroll
        for (int q = 0; q < 16; q++) s += pp[q];
        scl[threadIdx.x] = rsqrtf(s/(float)S_ + 1e-5f);
    }
    __syncthreads();
    int s = s0 + threadIdx.x;
    for (int r=threadIdx.y; r<32; r+=8)
        tile[r][threadIdx.x] = g_t[(size_t)b*H_*S_ + (size_t)(h0+r)*S_ + s] * scl[r];
    __syncthreads();
    int h = h0 + threadIdx.x;
    float sc = 1.0f + g_film[b*2*H_ + h];
    float sh = g_film[b*2*H_ + H_ + h];
    for (int r=threadIdx.y; r<32; r+=8){
        float v = tile[threadIdx.x][r]*sc + sh;
        size_t idx = (size_t)b*S_*H_ + (size_t)(s0+r)*H_ + h;
        g_z[idx] = v;
        g_zh[idx] = __float2half(v);
    }
}

// single-pass rmsnorm of z rows using precomputed sumsq partials (g_zpart).
// Launched only for each step's final layer.
__global__ void rmsnorm_z_split_kernel(){
    int row = blockIdx.x;
    __shared__ float ssum;
    if (threadIdx.x == 0){
        const float* pp = g_zpart + (size_t)row*4;
        ssum = pp[0] + pp[1] + pp[2] + pp[3];
    }
    __syncthreads();
    float scale = rsqrtf(ssum/(float)H_ + 1e-5f);
    float* p = g_z + (size_t)row*H_;
    for (int i=threadIdx.x; i<H_; i+=256){
        float v = p[i]*scale;
        p[i] = v;
        g_zh[(size_t)row*H_ + i] = __float2half(v);
    }
}

// ---------------------------------------------------------------------------
extern "C" void kernel_launch(void* const* d_in, const int* in_sizes, int n_in,
                              void* d_out, int out_size)
{
    const int*   inputs    = (const int*)  d_in[0];
    const float* z_in      = (const float*)d_in[1];
    const float* h_in      = (const float*)d_in[2];
    const float* mem_in    = (const float*)d_in[3];
    const float* embed_w   = (const float*)d_in[4];
    const float* lm_head_w = (const float*)d_in[5];
    const float* w1        = (const float*)d_in[6];
    const float* b1        = (const float*)d_in[7];
    const float* w2        = (const float*)d_in[8];
    const float* b2        = (const float*)d_in[9];
    const float* hdw       = (const float*)d_in[10];
    const float* hdb       = (const float*)d_in[11];
    const float* filmw     = (const float*)d_in[12];
    const float* filmb     = (const float*)d_in[13];
    const float* haltw     = (const float*)d_in[14];
    const float* haltb     = (const float*)d_in[15];
    const float* qw        = (const float*)d_in[16];
    const float* qb        = (const float*)d_in[17];
    const float* kw        = (const float*)d_in[18];
    const float* kb        = (const float*)d_in[19];
    const float* vw        = (const float*)d_in[20];
    const float* vb        = (const float*)d_in[21];
    const float* gw        = (const float*)d_in[22];
    const float* gb        = (const float*)d_in[23];
    const float* ow        = (const float*)d_in[24];
    const float* ob        = (const float*)d_in[25];
    const float* wt_gu     = (const float*)d_in[26];
    const float* wt_d      = (const float*)d_in[27];
    const float* wm_gu     = (const float*)d_in[28];
    const float* wm_d      = (const float*)d_in[29];
    float* out = (float*)d_out;

    float *zp, *tp, *hp, *memp, *tpart, *zpart;
    cudaGetSymbolAddress((void**)&zp,    g_z);
    cudaGetSymbolAddress((void**)&tp,    g_t);
    cudaGetSymbolAddress((void**)&hp,    g_h);
    cudaGetSymbolAddress((void**)&memp,  g_mem);
    cudaGetSymbolAddress((void**)&tpart, g_tpart);
    cudaGetSymbolAddress((void**)&zpart, g_zpart);

    __half *th, *zh, *ah;
    __half *wtgu, *wtd, *wmgu, *wmd, *lmhh, *lmhl;
    cudaGetSymbolAddress((void**)&th, g_th);
    cudaGetSymbolAddress((void**)&zh, g_zh);
    cudaGetSymbolAddress((void**)&ah, g_acth);
    cudaGetSymbolAddress((void**)&wtgu, g_wtgu);
    cudaGetSymbolAddress((void**)&wtd,  g_wtd);
    cudaGetSymbolAddress((void**)&wmgu, g_wmgu);
    cudaGetSymbolAddress((void**)&wmd,  g_wmd);
    cudaGetSymbolAddress((void**)&lmhh, g_lmh_h);
    cudaGetSymbolAddress((void**)&lmhl, g_lmh_l);

    const int SMEM_GLU = 3*32*1024;  // 96KB per CTA, 2 CTAs/SM
    const int SMEM_G2  = 3*32*1024;  // 96KB per CTA, 2 CTAs/SM
    const int SMEM_G0  = 2*48*1024;  // 96KB per CTA, 2 CTAs/SM
    cudaFuncSetAttribute(mma_gemm_glu, cudaFuncAttributeMaxDynamicSharedMemorySize, SMEM_GLU);
    cudaFuncSetAttribute(mma_gemm2,    cudaFuncAttributeMaxDynamicSharedMemorySize, SMEM_G2);
    cudaFuncSetAttribute(mma_gemm0,    cudaFuncAttributeMaxDynamicSharedMemorySize, SMEM_G0);

    dim3 trBlk(32,8);
    dim3 trGrd(S_/32, H_/32, B_);

    // state init
    {
        int tot4 = (B_*S_*H_ + B_*P_ + B_*SLOTS_*M_)/4;
        copy_init_kernel<<<(tot4+255)/256, 256>>>((const float4*)z_in, (const float4*)h_in, (const float4*)mem_in);
    }
    // weight converts/splits
    split_all_kernel<<<(NSALL/4+255)/256, 256>>>(wt_gu, wt_d, wm_gu, wm_d, lm_head_w);

    for (int st=0; st<HALT_STEPS_; st++){
        planner_kernel<<<B_, 1024>>>(w1,b1,w2,b2,hdw,hdb,filmw,filmb,haltw,haltb,
                                     qw,qb,kw,kb,vw,vb,gw,gb,ow,ob,
                                     out + HALT_OFF + st*B_);

        for (int i=0; i<L_; i++){
            // i=0: fused z-update; i=1: fused rmsnorm of layer-0's z
            if (i==0) transpose_zt_split<true,false><<<trGrd, trBlk>>>(inputs, embed_w);
            else      transpose_zt_split<false,true><<<trGrd, trBlk>>>(inputs, embed_w);
            {
                size_t go = (size_t)i*2*IT_*S_;
                mma_gemm_glu<<<dim3(IT_/64, (B_*H_)/128), 256, SMEM_GLU>>>(
                    th, wtgu+go, wtgu+go+(size_t)IT_*S_, ah, S_, IT_);
            }
            {
                size_t dof = (size_t)i*S_*IT_;
                mma_gemm2<<<dim3(S_/128, (B_*H_)/128), 256, SMEM_G2>>>(
                    ah, wtd+dof, tp, tpart, 16, IT_, S_);
            }
            transpose_tz_film_split<<<trGrd, trBlk>>>();
            {
                size_t go = (size_t)i*2*IM_*H_;
                mma_gemm_glu<<<dim3(IM_/64, (B_*S_)/128), 256, SMEM_GLU>>>(
                    zh, wmgu+go, wmgu+go+(size_t)IM_*H_, ah, H_, IM_);
            }
            {
                size_t dof = (size_t)i*H_*IM_;
                mma_gemm2<<<dim3(H_/128, (B_*S_)/128), 256, SMEM_G2>>>(
                    ah, wmd+dof, zp, zpart, 4, IM_, H_);
            }
            if (i == L_-1)
                rmsnorm_z_split_kernel<<<B_*S_, 256>>>();
        }
        mma_gemm0<<<dim3(V_/128, (B_*S_)/128), 256, SMEM_G0>>>(
            zh, lmhh, lmhl, out + (size_t)st*B_*S_*V_, H_, V_);
    }

    // final state outputs
    copy4_kernel<<<(B_*S_*H_/4+255)/256, 256>>>((float4*)(out + ZL_OFF), (const float4*)zp, B_*S_*H_/4);
    copy4_kernel<<<(B_*P_/4+255)/256,    256>>>((float4*)(out + HOUT_OFF),(const float4*)hp, B_*P_/4);
    copy4_kernel<<<(B_*SLOTS_*M_/4+255)/256,256>>>((float4*)(out + MEM_OFF),(const float4*)memp, B_*SLOTS_*M_/4);
}

// round 16
// speedup vs baseline: 1.0981x; 1.0434x over previous
#include <cuda_runtime.h>
#include <cuda_fp16.h>
#include <math.h>
#include <stdint.h>

// Problem dims
#define B_ 32
#define S_ 2048
#define H_ 512
#define V_ 128
#define P_ 256
#define M_ 128
#define SLOTS_ 64
#define L_ 2
#define IT_ 2816
#define IM_ 768
#define HALT_STEPS_ 4

#define SQRT_H_ 22.62741699796952f
#define INV_SQRT_M_ 0.08838834764831845f

// Output offsets (fp32 elements)
#define HALT_OFF   (HALT_STEPS_*B_*S_*V_)
#define ZL_OFF     (HALT_OFF + HALT_STEPS_*B_)
#define HOUT_OFF   (ZL_OFF + B_*S_*H_)
#define MEM_OFF    (HOUT_OFF + B_*P_)

// ------------------------- static device state -----------------------------
__device__ float g_z[B_*S_*H_];
__device__ float g_t[B_*S_*H_];
__device__ float g_h[B_*P_];
__device__ float g_mem[B_*SLOTS_*M_];
__device__ float g_ctx[B_*H_];
__device__ float g_film[B_*2*H_];
// per-row sum-of-squares partials (written by residual GEMM epilogues)
__device__ float g_tpart[B_*H_*16];    // token-d: 16 col-tiles per row
__device__ float g_zpart[B_*S_*4];     // channel-d: 4 col-tiles per row

// activations: SINGLE fp16 tiles
__device__ __half g_th[B_*S_*H_];
__device__ __half g_zh[B_*S_*H_];
__device__ __half g_acth[B_*S_*IM_];

// recurrent weights: SINGLE fp16; lm_head keeps hi/lo split
__device__ __half g_wtgu[L_*2*IT_*S_];
__device__ __half g_wtd [L_*S_*IT_];
__device__ __half g_wmgu[L_*2*IM_*H_];
__device__ __half g_wmd [L_*H_*IM_];
__device__ __half g_lmh_h[V_*H_], g_lmh_l[V_*H_];

// split sizes (floats)
#define NS0 (L_*2*IT_*S_)
#define NS1 (L_*S_*IT_)
#define NS2 (L_*2*IM_*H_)
#define NS3 (L_*H_*IM_)
#define NS4 (V_*H_)
#define NSALL (NS0+NS1+NS2+NS3+NS4)

// ------------------------- PTX helpers -------------------------------------
__device__ __forceinline__ uint32_t smem_u32(const void* p){
    uint32_t a;
    asm("{ .reg .u64 t; cvta.to.shared.u64 t, %1; cvt.u32.u64 %0, t; }" : "=r"(a) : "l"(p));
    return a;
}
__device__ __forceinline__ void cp16(uint32_t s, const void* g){
    asm volatile("cp.async.cg.shared.global [%0], [%1], 16;" :: "r"(s), "l"(g));
}
__device__ __forceinline__ void cp_commit(){ asm volatile("cp.async.commit_group;" ::: "memory"); }
template<int N> __device__ __forceinline__ void cp_wait(){
    asm volatile("cp.async.wait_group %0;" :: "n"(N) : "memory");
}
__device__ __forceinline__ void ldsm4(uint32_t* r, uint32_t addr){
    asm volatile("ldmatrix.sync.aligned.m8n8.x4.shared.b16 {%0,%1,%2,%3}, [%4];"
        : "=r"(r[0]), "=r"(r[1]), "=r"(r[2]), "=r"(r[3]) : "r"(addr));
}
__device__ __forceinline__ void mma16816(float* c, const uint32_t* a, uint32_t b0, uint32_t b1){
    asm volatile("mma.sync.aligned.m16n8k16.row.col.f32.f16.f16.f32 "
        "{%0,%1,%2,%3}, {%4,%5,%6,%7}, {%8,%9}, {%0,%1,%2,%3};"
        : "+f"(c[0]), "+f"(c[1]), "+f"(c[2]), "+f"(c[3])
        : "r"(a[0]), "r"(a[1]), "r"(a[2]), "r"(a[3]), "r"(b0), "r"(b1));
}
__device__ __forceinline__ void splitw(float x, __half& hi, __half& lo){
    hi = __float2half(x);
    lo = __float2half(x - __half2float(hi));
}
__device__ __forceinline__ float wred(float v){
    #pragma unroll
    for (int o=16;o;o>>=1) v += __shfl_xor_sync(0xffffffffu, v, o);
    return v;
}

// ------------------------- SwiGLU GEMM (3-stage pipe) -----------------------
__global__ void __launch_bounds__(256,2) mma_gemm_glu(
    const __half* __restrict__ A,
    const __half* __restrict__ Bg, const __half* __restrict__ Bu,
    __half* __restrict__ Oh,
    int K, int N)
{
    constexpr int CHUNK = 64;
    constexpr int ROWB  = 128;
    constexpr int TA_B  = 128*ROWB;
    constexpr int TB_B  = 64*ROWB;
    constexpr int STAGE = TA_B + 2*TB_B;
    extern __shared__ char dsm[];
    const uint32_t sb = smem_u32(dsm);
    const int tid  = threadIdx.x;
    const int lane = tid & 31, warp = tid >> 5;
    const int wm = warp >> 2, wn = warp & 3;
    const int rowBase = blockIdx.y*128;
    const int colBase = blockIdx.x*64;

    const __half* pA = A  + (size_t)rowBase*K;
    const __half* pG = Bg + (size_t)colBase*K;
    const __half* pU = Bu + (size_t)colBase*K;

    auto load_stage = [&](uint32_t sbase, int k0){
        {
            const __half* src = pA + k0;
            #pragma unroll
            for (int it = 0; it < 4; it++){
                int i = tid + it*256;
                int row = i >> 3, seg = i & 7;
                uint32_t off = (uint32_t)(row*ROWB + ((seg ^ (row & 7))<<4));
                cp16(sbase + off, (const void*)(src + row*K + seg*8));
            }
        }
        {
            const __half* src = pG + k0;
            #pragma unroll
            for (int it = 0; it < 2; it++){
                int i = tid + it*256;
                int row = i >> 3, seg = i & 7;
                uint32_t off = (uint32_t)(row*ROWB + ((seg ^ (row & 7))<<4));
                cp16(sbase + TA_B + off, (const void*)(src + row*K + seg*8));
            }
        }
        {
            const __half* src = pU + k0;
            #pragma unroll
            for (int it = 0; it < 2; it++){
                int i = tid + it*256;
                int row = i >> 3, seg = i & 7;
                uint32_t off = (uint32_t)(row*ROWB + ((seg ^ (row & 7))<<4));
                cp16(sbase + TA_B + TB_B + off, (const void*)(src + row*K + seg*8));
            }
        }
    };

    float G[4][2][4];
    float U[4][2][4];
    #pragma unroll
    for (int a=0;a<4;a++)
        #pragma unroll
        for (int b=0;b<2;b++)
            #pragma unroll
            for (int c=0;c<4;c++){ G[a][b][c]=0.f; U[a][b][c]=0.f; }

    const int nCh = K / CHUNK;
    load_stage(sb + 0*STAGE, 0);        cp_commit();
    load_stage(sb + 1*STAGE, CHUNK);    cp_commit();
    load_stage(sb + 2*STAGE, 2*CHUNK);  cp_commit();

    const int rA = lane & 15;
    const int segSel = lane >> 4;
    const int xorA = rA & 7;

    int stgIdx = 0;
    for (int c = 0; c < nCh; c++){
        const uint32_t stg = sb + (uint32_t)stgIdx*STAGE;
        cp_wait<2>();
        __syncthreads();

        const uint32_t aBase = stg + (uint32_t)((wm*64 + rA)*ROWB);
        const uint32_t bRow  = (uint32_t)((wn*16 + rA)*ROWB);

        #pragma unroll
        for (int ks = 0; ks < 4; ks++){
            const uint32_t segOff = (uint32_t)(((2*ks + segSel) ^ xorA) << 4);
            uint32_t aF[4][4];
            #pragma unroll
            for (int mt = 0; mt < 4; mt++)
                ldsm4(aF[mt], aBase + mt*16*ROWB + segOff);
            uint32_t bg[4], bu[4];
            ldsm4(bg, stg + TA_B        + bRow + segOff);
            ldsm4(bu, stg + TA_B + TB_B + bRow + segOff);
            #pragma unroll
            for (int mt = 0; mt < 4; mt++){
                mma16816(G[mt][0], aF[mt], bg[0], bg[2]);
                mma16816(G[mt][1], aF[mt], bg[1], bg[3]);
                mma16816(U[mt][0], aF[mt], bu[0], bu[2]);
                mma16816(U[mt][1], aF[mt], bu[1], bu[3]);
            }
        }
        __syncthreads();
        if (c + 3 < nCh) load_stage(stg, (c+3)*CHUNK);
        cp_commit();
        stgIdx = (stgIdx==2) ? 0 : stgIdx+1;
    }

    const int rEp = rowBase + wm*64 + (lane >> 2);
    const int cEp = colBase + wn*16 + (lane & 3)*2;
    #pragma unroll
    for (int mt = 0; mt < 4; mt++){
        #pragma unroll
        for (int nt = 0; nt < 2; nt++){
            int cc = cEp + nt*8;
            #pragma unroll
            for (int half_ = 0; half_ < 2; half_++){
                int rr = rEp + mt*16 + half_*8;
                float g0 = G[mt][nt][half_*2+0], u0 = U[mt][nt][half_*2+0];
                float g1 = G[mt][nt][half_*2+1], u1 = U[mt][nt][half_*2+1];
                float v0 = g0/(1.0f+__expf(-g0))*u0;
                float v1 = g1/(1.0f+__expf(-g1))*u1;
                __half2 hv;
                hv.x = __float2half(v0);
                hv.y = __float2half(v1);
                *(__half2*)(Oh + (size_t)rr*N + cc) = hv;
            }
        }
    }
}

// ------------------------- residual GEMM + row sumsq ------------------------
__global__ void __launch_bounds__(256,2) mma_gemm2(
    const __half* __restrict__ A,
    const __half* __restrict__ Bw,
    float* __restrict__ Cf,
    float* __restrict__ Spart, int npartx,
    int K, int N)
{
    constexpr int CHUNK = 64;
    constexpr int ROWB  = 128;
    constexpr int TILE_B = 128*ROWB;
    constexpr int STAGE  = 2*TILE_B;
    extern __shared__ char dsm[];
    const uint32_t sb = smem_u32(dsm);
    const int tid  = threadIdx.x;
    const int lane = tid & 31, warp = tid >> 5;
    const int wm = warp >> 2, wn = warp & 3;
    const int rowBase = blockIdx.y*128;
    const int colBase = blockIdx.x*128;

    const __half* pA = A  + (size_t)rowBase*K;
    const __half* pB = Bw + (size_t)colBase*K;

    auto load_stage = [&](uint32_t sbase, int k0){
        {
            const __half* src = pA + k0;
            #pragma unroll
            for (int it = 0; it < 4; it++){
                int i = tid + it*256;
                int row = i >> 3, seg = i & 7;
                uint32_t off = (uint32_t)(row*ROWB + ((seg ^ (row & 7))<<4));
                cp16(sbase + off, (const void*)(src + row*K + seg*8));
            }
        }
        {
            const __half* src = pB + k0;
            #pragma unroll
            for (int it = 0; it < 4; it++){
                int i = tid + it*256;
                int row = i >> 3, seg = i & 7;
                uint32_t off = (uint32_t)(row*ROWB + ((seg ^ (row & 7))<<4));
                cp16(sbase + TILE_B + off, (const void*)(src + row*K + seg*8));
            }
        }
    };

    float G[4][4][4];
    #pragma unroll
    for (int a=0;a<4;a++)
        #pragma unroll
        for (int b=0;b<4;b++)
            #pragma unroll
            for (int c=0;c<4;c++) G[a][b][c]=0.f;

    const int nCh = K / CHUNK;
    load_stage(sb + 0*STAGE, 0);        cp_commit();
    load_stage(sb + 1*STAGE, CHUNK);    cp_commit();
    load_stage(sb + 2*STAGE, 2*CHUNK);  cp_commit();

    const int rA = lane & 15;
    const int segSel = lane >> 4;
    const int xorA = rA & 7;

    int stgIdx = 0;
    for (int c = 0; c < nCh; c++){
        const uint32_t stg = sb + (uint32_t)stgIdx*STAGE;
        cp_wait<2>();
        __syncthreads();

        const uint32_t aBase = stg + (uint32_t)((wm*64 + rA)*ROWB);
        const uint32_t bBase = stg + TILE_B + (uint32_t)((wn*32 + rA)*ROWB);

        #pragma unroll
        for (int ks = 0; ks < 4; ks++){
            const uint32_t segOff = (uint32_t)(((2*ks + segSel) ^ xorA) << 4);
            uint32_t aF[4][4];
            #pragma unroll
            for (int mt = 0; mt < 4; mt++)
                ldsm4(aF[mt], aBase + mt*16*ROWB + segOff);
            #pragma unroll
            for (int bt = 0; bt < 2; bt++){
                uint32_t bh[4];
                ldsm4(bh, bBase + bt*16*ROWB + segOff);
                #pragma unroll
                for (int mt = 0; mt < 4; mt++){
                    mma16816(G[mt][bt*2+0], aF[mt], bh[0], bh[2]);
                    mma16816(G[mt][bt*2+1], aF[mt], bh[1], bh[3]);
                }
            }
        }
        __syncthreads();
        if (c + 3 < nCh) load_stage(stg, (c+3)*CHUNK);
        cp_commit();
        stgIdx = (stgIdx==2) ? 0 : stgIdx+1;
    }

    const int rEp = rowBase + wm*64 + (lane >> 2);
    const int cEp = colBase + wn*32 + (lane & 3)*2;
    float rsum[4][2];
    #pragma unroll
    for (int a=0;a<4;a++){ rsum[a][0]=0.f; rsum[a][1]=0.f; }
    #pragma unroll
    for (int mt = 0; mt < 4; mt++){
        #pragma unroll
        for (int nt = 0; nt < 4; nt++){
            int cc = cEp + nt*8;
            #pragma unroll
            for (int half_ = 0; half_ < 2; half_++){
                int rr = rEp + mt*16 + half_*8;
                float2 o;
                o.x = G[mt][nt][half_*2+0];
                o.y = G[mt][nt][half_*2+1];
                float2* cp2 = (float2*)(Cf + (size_t)rr*N + cc);
                float2 old = *cp2;
                o.x += old.x; o.y += old.y;
                *cp2 = o;
                rsum[mt][half_] += o.x*o.x + o.y*o.y;
            }
        }
    }
    __syncthreads();
    float* part = (float*)dsm;
    const int slot = wn*4 + (lane & 3);
    #pragma unroll
    for (int mt = 0; mt < 4; mt++)
        #pragma unroll
        for (int half_ = 0; half_ < 2; half_++){
            int lr = wm*64 + (lane>>2) + mt*16 + half_*8;
            part[lr*16 + slot] = rsum[mt][half_];
        }
    __syncthreads();
    if (tid < 128){
        float s = 0.f;
        #pragma unroll
        for (int q = 0; q < 16; q++) s += part[tid*16 + q];
        Spart[(size_t)(rowBase + tid)*npartx + blockIdx.x] = s;
    }
}

// ------------------------- lm_head GEMM (2-term hi/lo, 2-stage) -------------
__global__ void __launch_bounds__(256,2) mma_gemm0(
    const __half* __restrict__ A,
    const __half* __restrict__ Bh,  const __half* __restrict__ Bl,
    float* __restrict__ Cf,
    int K, int N)
{
    constexpr int CHUNK = 64;
    constexpr int ROWB  = 128;
    constexpr int TILE_B = 128*ROWB;
    constexpr int STAGE  = 3*TILE_B;
    extern __shared__ char dsm[];
    const uint32_t sb = smem_u32(dsm);
    const int tid  = threadIdx.x;
    const int lane = tid & 31, warp = tid >> 5;
    const int wm = warp >> 2, wn = warp & 3;
    const int rowBase = blockIdx.y*128;
    const int colBase = blockIdx.x*128;

    const uint32_t tiles0 = sb;
    const uint32_t tiles1 = sb + STAGE;

    const __half* ps[3];
    ps[0] = A  + (size_t)rowBase*K;
    ps[1] = Bh + (size_t)colBase*K;
    ps[2] = Bl + (size_t)colBase*K;

    auto load_stage = [&](uint32_t sbase, int k0){
        #pragma unroll
        for (int t = 0; t < 3; t++){
            const __half* src = ps[t] + k0;
            const uint32_t tb = sbase + (uint32_t)t*TILE_B;
            #pragma unroll
            for (int it = 0; it < 4; it++){
                int i = tid + it*256;
                int row = i >> 3, seg = i & 7;
                uint32_t off = (uint32_t)(row*ROWB + ((seg ^ (row & 7))<<4));
                cp16(tb + off, (const void*)(src + row*K + seg*8));
            }
        }
    };

    float G[4][4][4];
    #pragma unroll
    for (int a=0;a<4;a++)
        #pragma unroll
        for (int b=0;b<4;b++)
            #pragma unroll
            for (int c=0;c<4;c++) G[a][b][c]=0.f;

    const int nCh = K / CHUNK;
    load_stage(tiles0, 0);      cp_commit();
    load_stage(tiles1, CHUNK);  cp_commit();

    const int rA = lane & 15;
    const int segSel = lane >> 4;
    const int xorA = rA & 7;

    for (int c = 0; c < nCh; c++){
        const uint32_t stg = (c & 1) ? tiles1 : tiles0;
        if (c + 1 < nCh) cp_wait<1>(); else cp_wait<0>();
        __syncthreads();

        const uint32_t aBase = stg + (uint32_t)((wm*64 + rA)*ROWB);
        const uint32_t bBase = stg + TILE_B + (uint32_t)((wn*32 + rA)*ROWB);

        #pragma unroll
        for (int ks = 0; ks < 4; ks++){
            const uint32_t segOff = (uint32_t)(((2*ks + segSel) ^ xorA) << 4);
            uint32_t aF[4][4];
            #pragma unroll
            for (int mt = 0; mt < 4; mt++)
                ldsm4(aF[mt], aBase + mt*16*ROWB + segOff);
            #pragma unroll
            for (int bt = 0; bt < 2; bt++){
                uint32_t bh[4], bl[4];
                ldsm4(bh, bBase + bt*16*ROWB + segOff);
                ldsm4(bl, bBase + TILE_B + bt*16*ROWB + segOff);
                #pragma unroll
                for (int mt = 0; mt < 4; mt++){
                    mma16816(G[mt][bt*2+0], aF[mt], bh[0], bh[2]);
                    mma16816(G[mt][bt*2+1], aF[mt], bh[1], bh[3]);
                    mma16816(G[mt][bt*2+0], aF[mt], bl[0], bl[2]);
                    mma16816(G[mt][bt*2+1], aF[mt], bl[1], bl[3]);
                }
            }
        }
        __syncthreads();
        if (c + 2 < nCh){
            load_stage(stg, (c+2)*CHUNK);
            cp_commit();
        }
    }

    const int rEp = rowBase + wm*64 + (lane >> 2);
    const int cEp = colBase + wn*32 + (lane & 3)*2;
    #pragma unroll
    for (int mt = 0; mt < 4; mt++){
        #pragma unroll
        for (int nt = 0; nt < 4; nt++){
            int cc = cEp + nt*8;
            #pragma unroll
            for (int half_ = 0; half_ < 2; half_++){
                int rr = rEp + mt*16 + half_*8;
                float2 o;
                o.x = G[mt][nt][half_*2+0];
                o.y = G[mt][nt][half_*2+1];
                *(float2*)(Cf + (size_t)rr*N + cc) = o;
            }
        }
    }
}

// ------------------------- aux kernels -------------------------------------
__global__ void copy4_kernel(float4* __restrict__ dst, const float4* __restrict__ src, int n4){
    int i = blockIdx.x*blockDim.x + threadIdx.x;
    if (i < n4) dst[i] = src[i];
}

__global__ void copy_init_kernel(const float4* __restrict__ z_in,
                                 const float4* __restrict__ h_in,
                                 const float4* __restrict__ mem_in){
    int i = blockIdx.x*blockDim.x + threadIdx.x;
    const int NZ = B_*S_*H_/4, NH = B_*P_/4, NM = B_*SLOTS_*M_/4;
    if (i < NZ){ ((float4*)g_z)[i] = z_in[i]; return; }
    i -= NZ;
    if (i < NH){ ((float4*)g_h)[i] = h_in[i]; return; }
    i -= NH;
    if (i < NM){ ((float4*)g_mem)[i] = mem_in[i]; }
}

__global__ void split_all_kernel(const float* __restrict__ wt_gu, const float* __restrict__ wt_d,
                                 const float* __restrict__ wm_gu, const float* __restrict__ wm_d,
                                 const float* __restrict__ lmh){
    long long i = (long long)(blockIdx.x*blockDim.x + threadIdx.x)*4;
    const float* src; __half* hd;
    if (i < NS0)             { src=wt_gu; hd=g_wtgu; }
    else if ((i-=NS0) < NS1) { src=wt_d;  hd=g_wtd;  }
    else if ((i-=NS1) < NS2) { src=wm_gu; hd=g_wmgu; }
    else if ((i-=NS2) < NS3) { src=wm_d;  hd=g_wmd;  }
    else if ((i-=NS3) < NS4) {
        float4 v = *(const float4*)(lmh + i);
        __half h0,l0,h1,l1,h2,l2,h3,l3;
        splitw(v.x,h0,l0); splitw(v.y,h1,l1); splitw(v.z,h2,l2); splitw(v.w,h3,l3);
        __half2 a,b,c,d;
        a.x=h0;a.y=h1; b.x=h2;b.y=h3; c.x=l0;c.y=l1; d.x=l2;d.y=l3;
        ((__half2*)(g_lmh_h+i))[0]=a; ((__half2*)(g_lmh_h+i))[1]=b;
        ((__half2*)(g_lmh_l+i))[0]=c; ((__half2*)(g_lmh_l+i))[1]=d;
        return;
    }
    else return;
    float4 v = *(const float4*)(src + i);
    __half2 a,b;
    a.x=__float2half(v.x); a.y=__float2half(v.y);
    b.x=__float2half(v.z); b.y=__float2half(v.w);
    ((__half2*)(hd+i))[0]=a; ((__half2*)(hd+i))[1]=b;
}

// planner: 1024 threads (32 warps); pooled mean folded into the prologue.
__global__ void __launch_bounds__(1024) planner_kernel(
    const float* __restrict__ w1, const float* __restrict__ b1,
    const float* __restrict__ w2, const float* __restrict__ b2,
    const float* __restrict__ hdw, const float* __restrict__ hdb,
    const float* __restrict__ filmw, const float* __restrict__ filmb,
    const float* __restrict__ haltw, const float* __restrict__ haltb,
    const float* __restrict__ qw, const float* __restrict__ qb,
    const float* __restrict__ kw, const float* __restrict__ kb,
    const float* __restrict__ vw, const float* __restrict__ vb,
    const float* __restrict__ gw, const float* __restrict__ gb,
    const float* __restrict__ ow, const float* __restrict__ ob,
    float* __restrict__ halt_out)
{
    int b = blockIdx.x, tid = threadIdx.x;
    int lane = tid & 31, wp = tid >> 5;
    __shared__ float x[768];
    __shared__ float red2[512];
    __shared__ float a1s[256];
    __shared__ float hm[256];
    __shared__ float qv[128], kv2[128], vv[128];
    __shared__ float rq[64], rk[64];
    __shared__ float ctxm[128];
    __shared__ float sgate;

    {
        int h = tid & 511;
        int chunk = tid >> 9;
        const float* p = g_z + (size_t)b*S_*H_ + (size_t)chunk*(S_/2)*H_ + h;
        float a0=0.f,a1=0.f,a2=0.f,a3=0.f;
        #pragma unroll 4
        for (int s = 0; s < S_/2; s += 4){
            a0 += p[(s+0)*H_]; a1 += p[(s+1)*H_];
            a2 += p[(s+2)*H_]; a3 += p[(s+3)*H_];
        }
        float v = (a0+a1)+(a2+a3);
        if (chunk) red2[h] = v;
        __syncthreads();
        if (!chunk) x[h] = (v + red2[h]) * (1.0f/S_);
        if (tid >= 512 && tid < 768) x[tid] = g_h[b*P_ + tid - 512];
    }
    __syncthreads();

    for (int j = wp; j < 256; j += 32){
        const float* w = w1 + j*768;
        float acc = 0.f;
        for (int k = lane; k < 768; k += 32) acc += w[k]*x[k];
        acc = wred(acc);
        if (lane==0){
            float v = acc + b1[j];
            a1s[j] = 0.5f*v*(1.0f + erff(v*0.70710678118654752f));
        }
    }
    __syncthreads();
    for (int j = wp; j < 256; j += 32){
        const float* w = w2 + j*256;
        float acc = 0.f;
        for (int k = lane; k < 256; k += 32) acc += w[k]*a1s[k];
        acc = wred(acc);
        if (lane==0) hm[j] = acc + b2[j];
    }
    __syncthreads();
    for (int j = wp; j < 256; j += 32){
        const float* w = hdw + j*256;
        float acc = 0.f;
        for (int k = lane; k < 256; k += 32) acc += w[k]*hm[k];
        acc = wred(acc);
        if (lane==0) g_h[b*P_+j] = x[512+j] + acc + hdb[j];
    }
    for (int j = wp; j < 2*H_; j += 32){
        const float* w = filmw + j*256;
        float acc = 0.f;
        for (int k = lane; k < 256; k += 32) acc += w[k]*hm[k];
        acc = wred(acc);
        if (lane==0) g_film[b*2*H_+j] = acc + filmb[j];
    }
    if (wp == 0){
        float acc = 0.f;
        for (int k = lane; k < 256; k += 32) acc += haltw[k]*hm[k];
        acc = wred(acc);
        if (lane==0) halt_out[b] = acc + haltb[0];
    }
    if (wp == 1){
        float acc = 0.f;
        for (int k = lane; k < 256; k += 32) acc += gw[k]*hm[k];
        acc = wred(acc);
        if (lane==0) sgate = 1.0f/(1.0f+expf(-(acc + gb[0])));
    }
    for (int j = wp; j < 384; j += 32){
        int which = j >> 7, jj = j & 127;
        const float* w  = (which==0 ? qw : which==1 ? kw : vw) + jj*256;
        float acc = 0.f;
        for (int k = lane; k < 256; k += 32) acc += w[k]*hm[k];
        acc = wred(acc);
        if (lane==0){
            float bb = (which==0 ? qb[jj] : which==1 ? kb[jj] : vb[jj]);
            float v = acc + bb;
            if (which==0) qv[jj]=v; else if (which==1) kv2[jj]=v; else vv[jj]=v;
        }
    }
    __syncthreads();

    const float* memb = g_mem + b*SLOTS_*M_;
    for (int n = wp; n < 64; n += 32){
        const float* m = memb + n*M_;
        float aq=0.f, ak=0.f;
        for (int d = lane; d < 128; d += 32){ float mv=m[d]; aq+=mv*qv[d]; ak+=mv*kv2[d]; }
        aq = wred(aq); ak = wred(ak);
        if (lane==0){ rq[n]=aq*INV_SQRT_M_; rk[n]=ak*INV_SQRT_M_; }
    }
    __syncthreads();
    if (wp < 2){
        float* r = wp ? rk : rq;
        float v0 = r[lane], v1 = r[lane+32];
        float mx = fmaxf(v0,v1);
        #pragma unroll
        for (int o=16;o;o>>=1) mx = fmaxf(mx, __shfl_xor_sync(0xffffffffu, mx, o));
        float e0 = expf(v0-mx), e1 = expf(v1-mx);
        float s = e0+e1;
        #pragma unroll
        for (int o=16;o;o>>=1) s += __shfl_xor_sync(0xffffffffu, s, o);
        float inv = 1.0f/s;
        r[lane] = e0*inv; r[lane+32] = e1*inv;
    }
    __syncthreads();
    if (tid < 128){
        float acc=0.f;
        #pragma unroll 4
        for (int n2=0;n2<64;n2++) acc += rq[n2]*memb[n2*M_+tid];
        ctxm[tid]=acc;
    }
    __syncthreads();
    for (int j = wp; j < H_; j += 32){
        const float* w = ow + j*M_;
        float acc = 0.f;
        for (int d = lane; d < 128; d += 32) acc += w[d]*ctxm[d];
        acc = wred(acc);
        if (lane==0) g_ctx[b*H_+j] = acc + ob[j];
    }
    float gv = sgate;
    for (int idx=tid; idx<SLOTS_*M_; idx+=1024){
        int n2 = idx>>7, d2 = idx&127;
        float w = rk[n2]*gv;
        g_mem[b*SLOTS_*M_+idx] = memb[idx]*(1.0f-w) + w*vv[d2];
    }
}

// (B,S,H) -> (B,H,S), 64x64 tiles, float2/half2 paths.
// UPD: fused z-update; NORM: rmsnorm scale from g_zpart on read.
template<bool UPD, bool NORM>
__global__ void transpose_zt_split(const int* __restrict__ inputs,
                                   const float* __restrict__ embed_w){
    __shared__ float tile[64][65];
    __shared__ float scl[64];
    int b = blockIdx.z;
    int s0 = blockIdx.x*64, h0 = blockIdx.y*64;
    int tx = threadIdx.x, ty = threadIdx.y;
    int tid = ty*32 + tx;
    if (NORM){
        if (tid < 64){
            const float* pp = g_zpart + (size_t)(b*S_ + s0 + tid)*4;
            float ss = pp[0] + pp[1] + pp[2] + pp[3];
            scl[tid] = rsqrtf(ss/(float)H_ + 1e-5f);
        }
        __syncthreads();
    }
    int h = h0 + 2*tx;
    float cx = 0.f, cy = 0.f;
    if (UPD){ cx = g_ctx[b*H_ + h]; cy = g_ctx[b*H_ + h + 1]; }
    #pragma unroll
    for (int r = ty; r < 64; r += 8){
        size_t idx = (size_t)b*S_*H_ + (size_t)(s0+r)*H_ + h;
        float2 v = *(const float2*)(g_z + idx);
        if (NORM){ float sc = scl[r]; v.x *= sc; v.y *= sc; }
        if (UPD){
            int tok = inputs[b*S_ + s0 + r];
            const float* e = embed_w + (size_t)tok*H_ + h;
            v.x += SQRT_H_*e[0] + cx;
            v.y += SQRT_H_*e[1] + cy;
        }
        tile[r][2*tx]   = v.x;
        tile[r][2*tx+1] = v.y;
    }
    __syncthreads();
    int s = s0 + 2*tx;
    #pragma unroll
    for (int r = ty; r < 64; r += 8){
        float v0 = tile[2*tx][r];
        float v1 = tile[2*tx+1][r];
        size_t idx = (size_t)b*H_*S_ + (size_t)(h0+r)*S_ + s;
        *(float2*)(g_t + idx) = make_float2(v0, v1);
        __half2 hv; hv.x = __float2half(v0); hv.y = __float2half(v1);
        *(__half2*)(g_th + idx) = hv;
    }
}

// (B,H,S) -> (B,S,H), 64x64 tiles: rmsnorm scale (g_tpart) + FiLM.
__global__ void transpose_tz_film_split(){
    __shared__ float tile[64][65];
    __shared__ float scl[64];
    __shared__ float fsc[64], fsh[64];
    int b = blockIdx.z;
    int s0 = blockIdx.x*64, h0 = blockIdx.y*64;
    int tx = threadIdx.x, ty = threadIdx.y;
    int tid = ty*32 + tx;
    if (tid < 64){
        const float* pp = g_tpart + (size_t)(b*H_ + h0 + tid)*16;
        float s = 0.f;
        #pragma unroll
        for (int q = 0; q < 16; q++) s += pp[q];
        scl[tid] = rsqrtf(s/(float)S_ + 1e-5f);
        fsc[tid] = 1.0f + g_film[b*2*H_ + h0 + tid];
        fsh[tid] = g_film[b*2*H_ + H_ + h0 + tid];
    }
    __syncthreads();
    int s = s0 + 2*tx;
    #pragma unroll
    for (int r = ty; r < 64; r += 8){
        float2 v = *(const float2*)(g_t + (size_t)b*H_*S_ + (size_t)(h0+r)*S_ + s);
        float sc = scl[r];
        tile[r][2*tx]   = v.x*sc;
        tile[r][2*tx+1] = v.y*sc;
    }
    __syncthreads();
    int h = h0 + 2*tx;
    float sc0 = fsc[2*tx],   sh0 = fsh[2*tx];
    float sc1 = fsc[2*tx+1], sh1 = fsh[2*tx+1];
    #pragma unroll
    for (int r = ty; r < 64; r += 8){
        float v0 = tile[2*tx][r]  *sc0 + sh0;
        float v1 = tile[2*tx+1][r]*sc1 + sh1;
        size_t idx = (size_t)b*S_*H_ + (size_t)(s0+r)*H_ + h;
        *(float2*)(g_z + idx) = make_float2(v0, v1);
        __half2 hv; hv.x = __float2half(v0); hv.y = __float2half(v1);
        *(__half2*)(g_zh + idx) = hv;
    }
}

// single-pass rmsnorm of z rows (float2), using g_zpart partials.
__global__ void rmsnorm_z_split_kernel(){
    int row = blockIdx.x;
    __shared__ float ssum;
    if (threadIdx.x == 0){
        const float* pp = g_zpart + (size_t)row*4;
        ssum = pp[0] + pp[1] + pp[2] + pp[3];
    }
    __syncthreads();
    float scale = rsqrtf(ssum/(float)H_ + 1e-5f);
    float* p = g_z + (size_t)row*H_;
    int i = threadIdx.x*2;
    if (i < H_){
        float2 v = *(float2*)(p + i);
        v.x *= scale; v.y *= scale;
        *(float2*)(p + i) = v;
        __half2 hv; hv.x = __float2half(v.x); hv.y = __float2half(v.y);
        *(__half2*)(g_zh + (size_t)row*H_ + i) = hv;
    }
}

// ---------------------------------------------------------------------------
extern "C" void kernel_launch(void* const* d_in, const int* in_sizes, int n_in,
                              void* d_out, int out_size)
{
    const int*   inputs    = (const int*)  d_in[0];
    const float* z_in      = (const float*)d_in[1];
    const float* h_in      = (const float*)d_in[2];
    const float* mem_in    = (const float*)d_in[3];
    const float* embed_w   = (const float*)d_in[4];
    const float* lm_head_w = (const float*)d_in[5];
    const float* w1        = (const float*)d_in[6];
    const float* b1        = (const float*)d_in[7];
    const float* w2        = (const float*)d_in[8];
    const float* b2        = (const float*)d_in[9];
    const float* hdw       = (const float*)d_in[10];
    const float* hdb       = (const float*)d_in[11];
    const float* filmw     = (const float*)d_in[12];
    const float* filmb     = (const float*)d_in[13];
    const float* haltw     = (const float*)d_in[14];
    const float* haltb     = (const float*)d_in[15];
    const float* qw        = (const float*)d_in[16];
    const float* qb        = (const float*)d_in[17];
    const float* kw        = (const float*)d_in[18];
    const float* kb        = (const float*)d_in[19];
    const float* vw        = (const float*)d_in[20];
    const float* vb        = (const float*)d_in[21];
    const float* gw        = (const float*)d_in[22];
    const float* gb        = (const float*)d_in[23];
    const float* ow        = (const float*)d_in[24];
    const float* ob        = (const float*)d_in[25];
    const float* wt_gu     = (const float*)d_in[26];
    const float* wt_d      = (const float*)d_in[27];
    const float* wm_gu     = (const float*)d_in[28];
    const float* wm_d      = (const float*)d_in[29];
    float* out = (float*)d_out;

    float *zp, *tp, *hp, *memp, *tpart, *zpart;
    cudaGetSymbolAddress((void**)&zp,    g_z);
    cudaGetSymbolAddress((void**)&tp,    g_t);
    cudaGetSymbolAddress((void**)&hp,    g_h);
    cudaGetSymbolAddress((void**)&memp,  g_mem);
    cudaGetSymbolAddress((void**)&tpart, g_tpart);
    cudaGetSymbolAddress((void**)&zpart, g_zpart);

    __half *th, *zh, *ah;
    __half *wtgu, *wtd, *wmgu, *wmd, *lmhh, *lmhl;
    cudaGetSymbolAddress((void**)&th, g_th);
    cudaGetSymbolAddress((void**)&zh, g_zh);
    cudaGetSymbolAddress((void**)&ah, g_acth);
    cudaGetSymbolAddress((void**)&wtgu, g_wtgu);
    cudaGetSymbolAddress((void**)&wtd,  g_wtd);
    cudaGetSymbolAddress((void**)&wmgu, g_wmgu);
    cudaGetSymbolAddress((void**)&wmd,  g_wmd);
    cudaGetSymbolAddress((void**)&lmhh, g_lmh_h);
    cudaGetSymbolAddress((void**)&lmhl, g_lmh_l);

    const int SMEM_GLU = 3*32*1024;
    const int SMEM_G2  = 3*32*1024;
    const int SMEM_G0  = 2*48*1024;
    cudaFuncSetAttribute(mma_gemm_glu, cudaFuncAttributeMaxDynamicSharedMemorySize, SMEM_GLU);
    cudaFuncSetAttribute(mma_gemm2,    cudaFuncAttributeMaxDynamicSharedMemorySize, SMEM_G2);
    cudaFuncSetAttribute(mma_gemm0,    cudaFuncAttributeMaxDynamicSharedMemorySize, SMEM_G0);

    dim3 trBlk(32,8);
    dim3 trGrd(S_/64, H_/64, B_);

    // state init
    {
        int tot4 = (B_*S_*H_ + B_*P_ + B_*SLOTS_*M_)/4;
        copy_init_kernel<<<(tot4+255)/256, 256>>>((const float4*)z_in, (const float4*)h_in, (const float4*)mem_in);
    }
    // weight converts/splits
    split_all_kernel<<<(NSALL/4+255)/256, 256>>>(wt_gu, wt_d, wm_gu, wm_d, lm_head_w);

    for (int st=0; st<HALT_STEPS_; st++){
        planner_kernel<<<B_, 1024>>>(w1,b1,w2,b2,hdw,hdb,filmw,filmb,haltw,haltb,
                                     qw,qb,kw,kb,vw,vb,gw,gb,ow,ob,
                                     out + HALT_OFF + st*B_);

        for (int i=0; i<L_; i++){
            if (i==0) transpose_zt_split<true,false><<<trGrd, trBlk>>>(inputs, embed_w);
            else      transpose_zt_split<false,true><<<trGrd, trBlk>>>(inputs, embed_w);
            {
                size_t go = (size_t)i*2*IT_*S_;
                mma_gemm_glu<<<dim3(IT_/64, (B_*H_)/128), 256, SMEM_GLU>>>(
                    th, wtgu+go, wtgu+go+(size_t)IT_*S_, ah, S_, IT_);
            }
            {
                size_t dof = (size_t)i*S_*IT_;
                mma_gemm2<<<dim3(S_/128, (B_*H_)/128), 256, SMEM_G2>>>(
                    ah, wtd+dof, tp, tpart, 16, IT_, S_);
            }
            transpose_tz_film_split<<<trGrd, trBlk>>>();
            {
                size_t go = (size_t)i*2*IM_*H_;
                mma_gemm_glu<<<dim3(IM_/64, (B_*S_)/128), 256, SMEM_GLU>>>(
                    zh, wmgu+go, wmgu+go+(size_t)IM_*H_, ah, H_, IM_);
            }
            {
                size_t dof = (size_t)i*H_*IM_;
                mma_gemm2<<<dim3(H_/128, (B_*S_)/128), 256, SMEM_G2>>>(
                    ah, wmd+dof, zp, zpart, 4, IM_, H_);
            }
            if (i == L_-1)
                rmsnorm_z_split_kernel<<<B_*S_, 256>>>();
        }
        mma_gemm0<<<dim3(V_/128, (B_*S_)/128), 256, SMEM_G0>>>(
            zh, lmhh, lmhl, out + (size_t)st*B_*S_*V_, H_, V_);
    }

    // final state outputs
    copy4_kernel<<<(B_*S_*H_/4+255)/256, 256>>>((float4*)(out + ZL_OFF), (const float4*)zp, B_*S_*H_/4);
    copy4_kernel<<<(B_*P_/4+255)/256,    256>>>((float4*)(out + HOUT_OFF),(const float4*)hp, B_*P_/4);
    copy4_kernel<<<(B_*SLOTS_*M_/4+255)/256,256>>>((float4*)(out + MEM_OFF),(const float4*)memp, B_*SLOTS_*M_/4);
}

// round 17
// speedup vs baseline: 1.1132x; 1.0138x over previous
#include <cuda_runtime.h>
#include <cuda_fp16.h>
#include <math.h>
#include <stdint.h>

// Problem dims
#define B_ 32
#define S_ 2048
#define H_ 512
#define V_ 128
#define P_ 256
#define M_ 128
#define SLOTS_ 64
#define L_ 2
#define IT_ 2816
#define IM_ 768
#define HALT_STEPS_ 4

#define SQRT_H_ 22.62741699796952f
#define INV_SQRT_M_ 0.08838834764831845f

// Output offsets (fp32 elements)
#define HALT_OFF   (HALT_STEPS_*B_*S_*V_)
#define ZL_OFF     (HALT_OFF + HALT_STEPS_*B_)
#define HOUT_OFF   (ZL_OFF + B_*S_*H_)
#define MEM_OFF    (HOUT_OFF + B_*P_)

// ------------------------- static device state -----------------------------
__device__ float g_z[B_*S_*H_];
__device__ float g_t[B_*S_*H_];
__device__ float g_h[B_*P_];
__device__ float g_mem[B_*SLOTS_*M_];
__device__ float g_ctx[B_*H_];
__device__ float g_film[B_*2*H_];
// per-row sum-of-squares partials (written by residual GEMM epilogues)
__device__ float g_tpart[B_*H_*16];    // token-d: 16 col-tiles per row
__device__ float g_zpart[B_*S_*4];     // channel-d: 4 col-tiles per row

// activations: SINGLE fp16 tiles
__device__ __half g_th[B_*S_*H_];
__device__ __half g_zh[B_*S_*H_];
__device__ __half g_acth[B_*S_*IM_];

// recurrent weights: SINGLE fp16; lm_head keeps hi/lo split
__device__ __half g_wtgu[L_*2*IT_*S_];
__device__ __half g_wtd [L_*S_*IT_];
__device__ __half g_wmgu[L_*2*IM_*H_];
__device__ __half g_wmd [L_*H_*IM_];
__device__ __half g_lmh_h[V_*H_], g_lmh_l[V_*H_];

// split sizes (floats)
#define NS0 (L_*2*IT_*S_)
#define NS1 (L_*S_*IT_)
#define NS2 (L_*2*IM_*H_)
#define NS3 (L_*H_*IM_)
#define NS4 (V_*H_)
#define NSALL (NS0+NS1+NS2+NS3+NS4)

// ------------------------- PTX helpers -------------------------------------
__device__ __forceinline__ uint32_t smem_u32(const void* p){
    uint32_t a;
    asm("{ .reg .u64 t; cvta.to.shared.u64 t, %1; cvt.u32.u64 %0, t; }" : "=r"(a) : "l"(p));
    return a;
}
__device__ __forceinline__ void cp16(uint32_t s, const void* g){
    asm volatile("cp.async.cg.shared.global [%0], [%1], 16;" :: "r"(s), "l"(g));
}
__device__ __forceinline__ void cp_commit(){ asm volatile("cp.async.commit_group;" ::: "memory"); }
template<int N> __device__ __forceinline__ void cp_wait(){
    asm volatile("cp.async.wait_group %0;" :: "n"(N) : "memory");
}
__device__ __forceinline__ void ldsm4(uint32_t* r, uint32_t addr){
    asm volatile("ldmatrix.sync.aligned.m8n8.x4.shared.b16 {%0,%1,%2,%3}, [%4];"
        : "=r"(r[0]), "=r"(r[1]), "=r"(r[2]), "=r"(r[3]) : "r"(addr));
}
__device__ __forceinline__ void mma16816(float* c, const uint32_t* a, uint32_t b0, uint32_t b1){
    asm volatile("mma.sync.aligned.m16n8k16.row.col.f32.f16.f16.f32 "
        "{%0,%1,%2,%3}, {%4,%5,%6,%7}, {%8,%9}, {%0,%1,%2,%3};"
        : "+f"(c[0]), "+f"(c[1]), "+f"(c[2]), "+f"(c[3])
        : "r"(a[0]), "r"(a[1]), "r"(a[2]), "r"(a[3]), "r"(b0), "r"(b1));
}
__device__ __forceinline__ void splitw(float x, __half& hi, __half& lo){
    hi = __float2half(x);
    lo = __float2half(x - __half2float(hi));
}
__device__ __forceinline__ float wred(float v){
    #pragma unroll
    for (int o=16;o;o>>=1) v += __shfl_xor_sync(0xffffffffu, v, o);
    return v;
}

// ------------------------- SwiGLU GEMM (3-stage pipe) -----------------------
__global__ void __launch_bounds__(256,2) mma_gemm_glu(
    const __half* __restrict__ A,
    const __half* __restrict__ Bg, const __half* __restrict__ Bu,
    __half* __restrict__ Oh,
    int K, int N)
{
    constexpr int CHUNK = 64;
    constexpr int ROWB  = 128;
    constexpr int TA_B  = 128*ROWB;
    constexpr int TB_B  = 64*ROWB;
    constexpr int STAGE = TA_B + 2*TB_B;
    extern __shared__ char dsm[];
    const uint32_t sb = smem_u32(dsm);
    const int tid  = threadIdx.x;
    const int lane = tid & 31, warp = tid >> 5;
    const int wm = warp >> 2, wn = warp & 3;
    const int rowBase = blockIdx.y*128;
    const int colBase = blockIdx.x*64;

    const __half* pA = A  + (size_t)rowBase*K;
    const __half* pG = Bg + (size_t)colBase*K;
    const __half* pU = Bu + (size_t)colBase*K;

    auto load_stage = [&](uint32_t sbase, int k0){
        {
            const __half* src = pA + k0;
            #pragma unroll
            for (int it = 0; it < 4; it++){
                int i = tid + it*256;
                int row = i >> 3, seg = i & 7;
                uint32_t off = (uint32_t)(row*ROWB + ((seg ^ (row & 7))<<4));
                cp16(sbase + off, (const void*)(src + row*K + seg*8));
            }
        }
        {
            const __half* src = pG + k0;
            #pragma unroll
            for (int it = 0; it < 2; it++){
                int i = tid + it*256;
                int row = i >> 3, seg = i & 7;
                uint32_t off = (uint32_t)(row*ROWB + ((seg ^ (row & 7))<<4));
                cp16(sbase + TA_B + off, (const void*)(src + row*K + seg*8));
            }
        }
        {
            const __half* src = pU + k0;
            #pragma unroll
            for (int it = 0; it < 2; it++){
                int i = tid + it*256;
                int row = i >> 3, seg = i & 7;
                uint32_t off = (uint32_t)(row*ROWB + ((seg ^ (row & 7))<<4));
                cp16(sbase + TA_B + TB_B + off, (const void*)(src + row*K + seg*8));
            }
        }
    };

    float G[4][2][4];
    float U[4][2][4];
    #pragma unroll
    for (int a=0;a<4;a++)
        #pragma unroll
        for (int b=0;b<2;b++)
            #pragma unroll
            for (int c=0;c<4;c++){ G[a][b][c]=0.f; U[a][b][c]=0.f; }

    const int nCh = K / CHUNK;
    load_stage(sb + 0*STAGE, 0);        cp_commit();
    load_stage(sb + 1*STAGE, CHUNK);    cp_commit();
    load_stage(sb + 2*STAGE, 2*CHUNK);  cp_commit();

    const int rA = lane & 15;
    const int segSel = lane >> 4;
    const int xorA = rA & 7;

    int stgIdx = 0;
    for (int c = 0; c < nCh; c++){
        const uint32_t stg = sb + (uint32_t)stgIdx*STAGE;
        cp_wait<2>();
        __syncthreads();

        const uint32_t aBase = stg + (uint32_t)((wm*64 + rA)*ROWB);
        const uint32_t bRow  = (uint32_t)((wn*16 + rA)*ROWB);

        #pragma unroll
        for (int ks = 0; ks < 4; ks++){
            const uint32_t segOff = (uint32_t)(((2*ks + segSel) ^ xorA) << 4);
            uint32_t aF[4][4];
            #pragma unroll
            for (int mt = 0; mt < 4; mt++)
                ldsm4(aF[mt], aBase + mt*16*ROWB + segOff);
            uint32_t bg[4], bu[4];
            ldsm4(bg, stg + TA_B        + bRow + segOff);
            ldsm4(bu, stg + TA_B + TB_B + bRow + segOff);
            #pragma unroll
            for (int mt = 0; mt < 4; mt++){
                mma16816(G[mt][0], aF[mt], bg[0], bg[2]);
                mma16816(G[mt][1], aF[mt], bg[1], bg[3]);
                mma16816(U[mt][0], aF[mt], bu[0], bu[2]);
                mma16816(U[mt][1], aF[mt], bu[1], bu[3]);
            }
        }
        __syncthreads();
        if (c + 3 < nCh) load_stage(stg, (c+3)*CHUNK);
        cp_commit();
        stgIdx = (stgIdx==2) ? 0 : stgIdx+1;
    }

    const int rEp = rowBase + wm*64 + (lane >> 2);
    const int cEp = colBase + wn*16 + (lane & 3)*2;
    #pragma unroll
    for (int mt = 0; mt < 4; mt++){
        #pragma unroll
        for (int nt = 0; nt < 2; nt++){
            int cc = cEp + nt*8;
            #pragma unroll
            for (int half_ = 0; half_ < 2; half_++){
                int rr = rEp + mt*16 + half_*8;
                float g0 = G[mt][nt][half_*2+0], u0 = U[mt][nt][half_*2+0];
                float g1 = G[mt][nt][half_*2+1], u1 = U[mt][nt][half_*2+1];
                float v0 = g0/(1.0f+__expf(-g0))*u0;
                float v1 = g1/(1.0f+__expf(-g1))*u1;
                __half2 hv;
                hv.x = __float2half(v0);
                hv.y = __float2half(v1);
                *(__half2*)(Oh + (size_t)rr*N + cc) = hv;
            }
        }
    }
}

// ------------------------- residual GEMM + row sumsq ------------------------
__global__ void __launch_bounds__(256,2) mma_gemm2(
    const __half* __restrict__ A,
    const __half* __restrict__ Bw,
    float* __restrict__ Cf,
    float* __restrict__ Spart, int npartx,
    int K, int N)
{
    constexpr int CHUNK = 64;
    constexpr int ROWB  = 128;
    constexpr int TILE_B = 128*ROWB;
    constexpr int STAGE  = 2*TILE_B;
    extern __shared__ char dsm[];
    const uint32_t sb = smem_u32(dsm);
    const int tid  = threadIdx.x;
    const int lane = tid & 31, warp = tid >> 5;
    const int wm = warp >> 2, wn = warp & 3;
    const int rowBase = blockIdx.y*128;
    const int colBase = blockIdx.x*128;

    const __half* pA = A  + (size_t)rowBase*K;
    const __half* pB = Bw + (size_t)colBase*K;

    auto load_stage = [&](uint32_t sbase, int k0){
        {
            const __half* src = pA + k0;
            #pragma unroll
            for (int it = 0; it < 4; it++){
                int i = tid + it*256;
                int row = i >> 3, seg = i & 7;
                uint32_t off = (uint32_t)(row*ROWB + ((seg ^ (row & 7))<<4));
                cp16(sbase + off, (const void*)(src + row*K + seg*8));
            }
        }
        {
            const __half* src = pB + k0;
            #pragma unroll
            for (int it = 0; it < 4; it++){
                int i = tid + it*256;
                int row = i >> 3, seg = i & 7;
                uint32_t off = (uint32_t)(row*ROWB + ((seg ^ (row & 7))<<4));
                cp16(sbase + TILE_B + off, (const void*)(src + row*K + seg*8));
            }
        }
    };

    float G[4][4][4];
    #pragma unroll
    for (int a=0;a<4;a++)
        #pragma unroll
        for (int b=0;b<4;b++)
            #pragma unroll
            for (int c=0;c<4;c++) G[a][b][c]=0.f;

    const int nCh = K / CHUNK;
    load_stage(sb + 0*STAGE, 0);        cp_commit();
    load_stage(sb + 1*STAGE, CHUNK);    cp_commit();
    load_stage(sb + 2*STAGE, 2*CHUNK);  cp_commit();

    const int rA = lane & 15;
    const int segSel = lane >> 4;
    const int xorA = rA & 7;

    int stgIdx = 0;
    for (int c = 0; c < nCh; c++){
        const uint32_t stg = sb + (uint32_t)stgIdx*STAGE;
        cp_wait<2>();
        __syncthreads();

        const uint32_t aBase = stg + (uint32_t)((wm*64 + rA)*ROWB);
        const uint32_t bBase = stg + TILE_B + (uint32_t)((wn*32 + rA)*ROWB);

        #pragma unroll
        for (int ks = 0; ks < 4; ks++){
            const uint32_t segOff = (uint32_t)(((2*ks + segSel) ^ xorA) << 4);
            uint32_t aF[4][4];
            #pragma unroll
            for (int mt = 0; mt < 4; mt++)
                ldsm4(aF[mt], aBase + mt*16*ROWB + segOff);
            #pragma unroll
            for (int bt = 0; bt < 2; bt++){
                uint32_t bh[4];
                ldsm4(bh, bBase + bt*16*ROWB + segOff);
                #pragma unroll
                for (int mt = 0; mt < 4; mt++){
                    mma16816(G[mt][bt*2+0], aF[mt], bh[0], bh[2]);
                    mma16816(G[mt][bt*2+1], aF[mt], bh[1], bh[3]);
                }
            }
        }
        __syncthreads();
        if (c + 3 < nCh) load_stage(stg, (c+3)*CHUNK);
        cp_commit();
        stgIdx = (stgIdx==2) ? 0 : stgIdx+1;
    }

    const int rEp = rowBase + wm*64 + (lane >> 2);
    const int cEp = colBase + wn*32 + (lane & 3)*2;
    float rsum[4][2];
    #pragma unroll
    for (int a=0;a<4;a++){ rsum[a][0]=0.f; rsum[a][1]=0.f; }
    #pragma unroll
    for (int mt = 0; mt < 4; mt++){
        #pragma unroll
        for (int nt = 0; nt < 4; nt++){
            int cc = cEp + nt*8;
            #pragma unroll
            for (int half_ = 0; half_ < 2; half_++){
                int rr = rEp + mt*16 + half_*8;
                float2 o;
                o.x = G[mt][nt][half_*2+0];
                o.y = G[mt][nt][half_*2+1];
                float2* cp2 = (float2*)(Cf + (size_t)rr*N + cc);
                float2 old = *cp2;
                o.x += old.x; o.y += old.y;
                *cp2 = o;
                rsum[mt][half_] += o.x*o.x + o.y*o.y;
            }
        }
    }
    __syncthreads();
    float* part = (float*)dsm;
    const int slot = wn*4 + (lane & 3);
    #pragma unroll
    for (int mt = 0; mt < 4; mt++)
        #pragma unroll
        for (int half_ = 0; half_ < 2; half_++){
            int lr = wm*64 + (lane>>2) + mt*16 + half_*8;
            part[lr*16 + slot] = rsum[mt][half_];
        }
    __syncthreads();
    if (tid < 128){
        float s = 0.f;
        #pragma unroll
        for (int q = 0; q < 16; q++) s += part[tid*16 + q];
        Spart[(size_t)(rowBase + tid)*npartx + blockIdx.x] = s;
    }
}

// ------------------------- lm_head GEMM (2-term hi/lo, 2-stage) -------------
__global__ void __launch_bounds__(256,2) mma_gemm0(
    const __half* __restrict__ A,
    const __half* __restrict__ Bh,  const __half* __restrict__ Bl,
    float* __restrict__ Cf,
    int K, int N)
{
    constexpr int CHUNK = 64;
    constexpr int ROWB  = 128;
    constexpr int TILE_B = 128*ROWB;
    constexpr int STAGE  = 3*TILE_B;
    extern __shared__ char dsm[];
    const uint32_t sb = smem_u32(dsm);
    const int tid  = threadIdx.x;
    const int lane = tid & 31, warp = tid >> 5;
    const int wm = warp >> 2, wn = warp & 3;
    const int rowBase = blockIdx.y*128;
    const int colBase = blockIdx.x*128;

    const uint32_t tiles0 = sb;
    const uint32_t tiles1 = sb + STAGE;

    const __half* ps[3];
    ps[0] = A  + (size_t)rowBase*K;
    ps[1] = Bh + (size_t)colBase*K;
    ps[2] = Bl + (size_t)colBase*K;

    auto load_stage = [&](uint32_t sbase, int k0){
        #pragma unroll
        for (int t = 0; t < 3; t++){
            const __half* src = ps[t] + k0;
            const uint32_t tb = sbase + (uint32_t)t*TILE_B;
            #pragma unroll
            for (int it = 0; it < 4; it++){
                int i = tid + it*256;
                int row = i >> 3, seg = i & 7;
                uint32_t off = (uint32_t)(row*ROWB + ((seg ^ (row & 7))<<4));
                cp16(tb + off, (const void*)(src + row*K + seg*8));
            }
        }
    };

    float G[4][4][4];
    #pragma unroll
    for (int a=0;a<4;a++)
        #pragma unroll
        for (int b=0;b<4;b++)
            #pragma unroll
            for (int c=0;c<4;c++) G[a][b][c]=0.f;

    const int nCh = K / CHUNK;
    load_stage(tiles0, 0);      cp_commit();
    load_stage(tiles1, CHUNK);  cp_commit();

    const int rA = lane & 15;
    const int segSel = lane >> 4;
    const int xorA = rA & 7;

    for (int c = 0; c < nCh; c++){
        const uint32_t stg = (c & 1) ? tiles1 : tiles0;
        if (c + 1 < nCh) cp_wait<1>(); else cp_wait<0>();
        __syncthreads();

        const uint32_t aBase = stg + (uint32_t)((wm*64 + rA)*ROWB);
        const uint32_t bBase = stg + TILE_B + (uint32_t)((wn*32 + rA)*ROWB);

        #pragma unroll
        for (int ks = 0; ks < 4; ks++){
            const uint32_t segOff = (uint32_t)(((2*ks + segSel) ^ xorA) << 4);
            uint32_t aF[4][4];
            #pragma unroll
            for (int mt = 0; mt < 4; mt++)
                ldsm4(aF[mt], aBase + mt*16*ROWB + segOff);
            #pragma unroll
            for (int bt = 0; bt < 2; bt++){
                uint32_t bh[4], bl[4];
                ldsm4(bh, bBase + bt*16*ROWB + segOff);
                ldsm4(bl, bBase + TILE_B + bt*16*ROWB + segOff);
                #pragma unroll
                for (int mt = 0; mt < 4; mt++){
                    mma16816(G[mt][bt*2+0], aF[mt], bh[0], bh[2]);
                    mma16816(G[mt][bt*2+1], aF[mt], bh[1], bh[3]);
                    mma16816(G[mt][bt*2+0], aF[mt], bl[0], bl[2]);
                    mma16816(G[mt][bt*2+1], aF[mt], bl[1], bl[3]);
                }
            }
        }
        __syncthreads();
        if (c + 2 < nCh){
            load_stage(stg, (c+2)*CHUNK);
            cp_commit();
        }
    }

    const int rEp = rowBase + wm*64 + (lane >> 2);
    const int cEp = colBase + wn*32 + (lane & 3)*2;
    #pragma unroll
    for (int mt = 0; mt < 4; mt++){
        #pragma unroll
        for (int nt = 0; nt < 4; nt++){
            int cc = cEp + nt*8;
            #pragma unroll
            for (int half_ = 0; half_ < 2; half_++){
                int rr = rEp + mt*16 + half_*8;
                float2 o;
                o.x = G[mt][nt][half_*2+0];
                o.y = G[mt][nt][half_*2+1];
                *(float2*)(Cf + (size_t)rr*N + cc) = o;
            }
        }
    }
}

// ------------------------- aux kernels -------------------------------------
__global__ void copy4_kernel(float4* __restrict__ dst, const float4* __restrict__ src, int n4){
    int i = blockIdx.x*blockDim.x + threadIdx.x;
    if (i < n4) dst[i] = src[i];
}

__global__ void copy_init_kernel(const float4* __restrict__ z_in,
                                 const float4* __restrict__ h_in,
                                 const float4* __restrict__ mem_in){
    int i = blockIdx.x*blockDim.x + threadIdx.x;
    const int NZ = B_*S_*H_/4, NH = B_*P_/4, NM = B_*SLOTS_*M_/4;
    if (i < NZ){ ((float4*)g_z)[i] = z_in[i]; return; }
    i -= NZ;
    if (i < NH){ ((float4*)g_h)[i] = h_in[i]; return; }
    i -= NH;
    if (i < NM){ ((float4*)g_mem)[i] = mem_in[i]; }
}

__global__ void split_all_kernel(const float* __restrict__ wt_gu, const float* __restrict__ wt_d,
                                 const float* __restrict__ wm_gu, const float* __restrict__ wm_d,
                                 const float* __restrict__ lmh){
    long long i = (long long)(blockIdx.x*blockDim.x + threadIdx.x)*4;
    const float* src; __half* hd;
    if (i < NS0)             { src=wt_gu; hd=g_wtgu; }
    else if ((i-=NS0) < NS1) { src=wt_d;  hd=g_wtd;  }
    else if ((i-=NS1) < NS2) { src=wm_gu; hd=g_wmgu; }
    else if ((i-=NS2) < NS3) { src=wm_d;  hd=g_wmd;  }
    else if ((i-=NS3) < NS4) {
        float4 v = *(const float4*)(lmh + i);
        __half h0,l0,h1,l1,h2,l2,h3,l3;
        splitw(v.x,h0,l0); splitw(v.y,h1,l1); splitw(v.z,h2,l2); splitw(v.w,h3,l3);
        __half2 a,b,c,d;
        a.x=h0;a.y=h1; b.x=h2;b.y=h3; c.x=l0;c.y=l1; d.x=l2;d.y=l3;
        ((__half2*)(g_lmh_h+i))[0]=a; ((__half2*)(g_lmh_h+i))[1]=b;
        ((__half2*)(g_lmh_l+i))[0]=c; ((__half2*)(g_lmh_l+i))[1]=d;
        return;
    }
    else return;
    float4 v = *(const float4*)(src + i);
    __half2 a,b;
    a.x=__float2half(v.x); a.y=__float2half(v.y);
    b.x=__float2half(v.z); b.y=__float2half(v.w);
    ((__half2*)(hd+i))[0]=a; ((__half2*)(hd+i))[1]=b;
}

// planner: 1024 threads (32 warps); pooled mean folded into the prologue.
__global__ void __launch_bounds__(1024) planner_kernel(
    const float* __restrict__ w1, const float* __restrict__ b1,
    const float* __restrict__ w2, const float* __restrict__ b2,
    const float* __restrict__ hdw, const float* __restrict__ hdb,
    const float* __restrict__ filmw, const float* __restrict__ filmb,
    const float* __restrict__ haltw, const float* __restrict__ haltb,
    const float* __restrict__ qw, const float* __restrict__ qb,
    const float* __restrict__ kw, const float* __restrict__ kb,
    const float* __restrict__ vw, const float* __restrict__ vb,
    const float* __restrict__ gw, const float* __restrict__ gb,
    const float* __restrict__ ow, const float* __restrict__ ob,
    float* __restrict__ halt_out)
{
    int b = blockIdx.x, tid = threadIdx.x;
    int lane = tid & 31, wp = tid >> 5;
    __shared__ float x[768];
    __shared__ float red2[512];
    __shared__ float a1s[256];
    __shared__ float hm[256];
    __shared__ float qv[128], kv2[128], vv[128];
    __shared__ float rq[64], rk[64];
    __shared__ float ctxm[128];
    __shared__ float sgate;

    {
        int h = tid & 511;
        int chunk = tid >> 9;
        const float* p = g_z + (size_t)b*S_*H_ + (size_t)chunk*(S_/2)*H_ + h;
        float a0=0.f,a1=0.f,a2=0.f,a3=0.f;
        #pragma unroll 4
        for (int s = 0; s < S_/2; s += 4){
            a0 += p[(s+0)*H_]; a1 += p[(s+1)*H_];
            a2 += p[(s+2)*H_]; a3 += p[(s+3)*H_];
        }
        float v = (a0+a1)+(a2+a3);
        if (chunk) red2[h] = v;
        __syncthreads();
        if (!chunk) x[h] = (v + red2[h]) * (1.0f/S_);
        if (tid >= 512 && tid < 768) x[tid] = g_h[b*P_ + tid - 512];
    }
    __syncthreads();

    for (int j = wp; j < 256; j += 32){
        const float* w = w1 + j*768;
        float acc = 0.f;
        for (int k = lane; k < 768; k += 32) acc += w[k]*x[k];
        acc = wred(acc);
        if (lane==0){
            float v = acc + b1[j];
            a1s[j] = 0.5f*v*(1.0f + erff(v*0.70710678118654752f));
        }
    }
    __syncthreads();
    for (int j = wp; j < 256; j += 32){
        const float* w = w2 + j*256;
        float acc = 0.f;
        for (int k = lane; k < 256; k += 32) acc += w[k]*a1s[k];
        acc = wred(acc);
        if (lane==0) hm[j] = acc + b2[j];
    }
    __syncthreads();
    for (int j = wp; j < 256; j += 32){
        const float* w = hdw + j*256;
        float acc = 0.f;
        for (int k = lane; k < 256; k += 32) acc += w[k]*hm[k];
        acc = wred(acc);
        if (lane==0) g_h[b*P_+j] = x[512+j] + acc + hdb[j];
    }
    for (int j = wp; j < 2*H_; j += 32){
        const float* w = filmw + j*256;
        float acc = 0.f;
        for (int k = lane; k < 256; k += 32) acc += w[k]*hm[k];
        acc = wred(acc);
        if (lane==0) g_film[b*2*H_+j] = acc + filmb[j];
    }
    if (wp == 0){
        float acc = 0.f;
        for (int k = lane; k < 256; k += 32) acc += haltw[k]*hm[k];
        acc = wred(acc);
        if (lane==0) halt_out[b] = acc + haltb[0];
    }
    if (wp == 1){
        float acc = 0.f;
        for (int k = lane; k < 256; k += 32) acc += gw[k]*hm[k];
        acc = wred(acc);
        if (lane==0) sgate = 1.0f/(1.0f+expf(-(acc + gb[0])));
    }
    for (int j = wp; j < 384; j += 32){
        int which = j >> 7, jj = j & 127;
        const float* w  = (which==0 ? qw : which==1 ? kw : vw) + jj*256;
        float acc = 0.f;
        for (int k = lane; k < 256; k += 32) acc += w[k]*hm[k];
        acc = wred(acc);
        if (lane==0){
            float bb = (which==0 ? qb[jj] : which==1 ? kb[jj] : vb[jj]);
            float v = acc + bb;
            if (which==0) qv[jj]=v; else if (which==1) kv2[jj]=v; else vv[jj]=v;
        }
    }
    __syncthreads();

    const float* memb = g_mem + b*SLOTS_*M_;
    for (int n = wp; n < 64; n += 32){
        const float* m = memb + n*M_;
        float aq=0.f, ak=0.f;
        for (int d = lane; d < 128; d += 32){ float mv=m[d]; aq+=mv*qv[d]; ak+=mv*kv2[d]; }
        aq = wred(aq); ak = wred(ak);
        if (lane==0){ rq[n]=aq*INV_SQRT_M_; rk[n]=ak*INV_SQRT_M_; }
    }
    __syncthreads();
    if (wp < 2){
        float* r = wp ? rk : rq;
        float v0 = r[lane], v1 = r[lane+32];
        float mx = fmaxf(v0,v1);
        #pragma unroll
        for (int o=16;o;o>>=1) mx = fmaxf(mx, __shfl_xor_sync(0xffffffffu, mx, o));
        float e0 = expf(v0-mx), e1 = expf(v1-mx);
        float s = e0+e1;
        #pragma unroll
        for (int o=16;o;o>>=1) s += __shfl_xor_sync(0xffffffffu, s, o);
        float inv = 1.0f/s;
        r[lane] = e0*inv; r[lane+32] = e1*inv;
    }
    __syncthreads();
    if (tid < 128){
        float acc=0.f;
        #pragma unroll 4
        for (int n2=0;n2<64;n2++) acc += rq[n2]*memb[n2*M_+tid];
        ctxm[tid]=acc;
    }
    __syncthreads();
    for (int j = wp; j < H_; j += 32){
        const float* w = ow + j*M_;
        float acc = 0.f;
        for (int d = lane; d < 128; d += 32) acc += w[d]*ctxm[d];
        acc = wred(acc);
        if (lane==0) g_ctx[b*H_+j] = acc + ob[j];
    }
    float gv = sgate;
    for (int idx=tid; idx<SLOTS_*M_; idx+=1024){
        int n2 = idx>>7, d2 = idx&127;
        float w = rk[n2]*gv;
        g_mem[b*SLOTS_*M_+idx] = memb[idx]*(1.0f-w) + w*vv[d2];
    }
}

// (B,S,H) -> (B,H,S), 64x64 tiles, float4 paths. blockDim (16,16).
// UPD: fused z-update; NORM: rmsnorm scale from g_zpart on read.
template<bool UPD, bool NORM>
__global__ void transpose_zt_split(const int* __restrict__ inputs,
                                   const float* __restrict__ embed_w){
    __shared__ float tile[64][65];
    __shared__ float scl[64];
    int b = blockIdx.z;
    int s0 = blockIdx.x*64, h0 = blockIdx.y*64;
    int tx = threadIdx.x, ty = threadIdx.y;   // 16 x 16
    int tid = ty*16 + tx;
    if (NORM){
        if (tid < 64){
            const float* pp = g_zpart + (size_t)(b*S_ + s0 + tid)*4;
            float ss = pp[0] + pp[1] + pp[2] + pp[3];
            scl[tid] = rsqrtf(ss/(float)H_ + 1e-5f);
        }
        __syncthreads();
    }
    int h = h0 + 4*tx;
    float4 cv = make_float4(0.f,0.f,0.f,0.f);
    if (UPD) cv = *(const float4*)(g_ctx + b*H_ + h);
    #pragma unroll
    for (int r = ty; r < 64; r += 16){
        size_t idx = (size_t)b*S_*H_ + (size_t)(s0+r)*H_ + h;
        float4 v = *(const float4*)(g_z + idx);
        if (NORM){ float sc = scl[r]; v.x*=sc; v.y*=sc; v.z*=sc; v.w*=sc; }
        if (UPD){
            int tok = inputs[b*S_ + s0 + r];
            float4 e = *(const float4*)(embed_w + (size_t)tok*H_ + h);
            v.x += SQRT_H_*e.x + cv.x;
            v.y += SQRT_H_*e.y + cv.y;
            v.z += SQRT_H_*e.z + cv.z;
            v.w += SQRT_H_*e.w + cv.w;
        }
        tile[r][4*tx]   = v.x;
        tile[r][4*tx+1] = v.y;
        tile[r][4*tx+2] = v.z;
        tile[r][4*tx+3] = v.w;
    }
    __syncthreads();
    int s = s0 + 4*tx;
    #pragma unroll
    for (int r = ty; r < 64; r += 16){
        float v0 = tile[4*tx  ][r];
        float v1 = tile[4*tx+1][r];
        float v2 = tile[4*tx+2][r];
        float v3 = tile[4*tx+3][r];
        size_t idx = (size_t)b*H_*S_ + (size_t)(h0+r)*S_ + s;
        *(float4*)(g_t + idx) = make_float4(v0,v1,v2,v3);
        __half2 ha, hb;
        ha.x=__float2half(v0); ha.y=__float2half(v1);
        hb.x=__float2half(v2); hb.y=__float2half(v3);
        uint2 hp;
        hp.x = *(uint32_t*)&ha; hp.y = *(uint32_t*)&hb;
        *(uint2*)(g_th + idx) = hp;
    }
}

// (B,H,S) -> (B,S,H), 64x64 tiles, float4: rmsnorm scale (g_tpart) + FiLM.
__global__ void transpose_tz_film_split(){
    __shared__ float tile[64][65];
    __shared__ float scl[64];
    __shared__ float fsc[64], fsh[64];
    int b = blockIdx.z;
    int s0 = blockIdx.x*64, h0 = blockIdx.y*64;
    int tx = threadIdx.x, ty = threadIdx.y;   // 16 x 16
    int tid = ty*16 + tx;
    if (tid < 64){
        const float* pp = g_tpart + (size_t)(b*H_ + h0 + tid)*16;
        float s = 0.f;
        #pragma unroll
        for (int q = 0; q < 16; q++) s += pp[q];
        scl[tid] = rsqrtf(s/(float)S_ + 1e-5f);
        fsc[tid] = 1.0f + g_film[b*2*H_ + h0 + tid];
        fsh[tid] = g_film[b*2*H_ + H_ + h0 + tid];
    }
    __syncthreads();
    int s = s0 + 4*tx;
    #pragma unroll
    for (int r = ty; r < 64; r += 16){
        float4 v = *(const float4*)(g_t + (size_t)b*H_*S_ + (size_t)(h0+r)*S_ + s);
        float sc = scl[r];
        tile[r][4*tx]   = v.x*sc;
        tile[r][4*tx+1] = v.y*sc;
        tile[r][4*tx+2] = v.z*sc;
        tile[r][4*tx+3] = v.w*sc;
    }
    __syncthreads();
    int h = h0 + 4*tx;
    float sc0=fsc[4*tx],  sh0=fsh[4*tx];
    float sc1=fsc[4*tx+1],sh1=fsh[4*tx+1];
    float sc2=fsc[4*tx+2],sh2=fsh[4*tx+2];
    float sc3=fsc[4*tx+3],sh3=fsh[4*tx+3];
    #pragma unroll
    for (int r = ty; r < 64; r += 16){
        float v0 = tile[4*tx  ][r]*sc0 + sh0;
        float v1 = tile[4*tx+1][r]*sc1 + sh1;
        float v2 = tile[4*tx+2][r]*sc2 + sh2;
        float v3 = tile[4*tx+3][r]*sc3 + sh3;
        size_t idx = (size_t)b*S_*H_ + (size_t)(s0+r)*H_ + h;
        *(float4*)(g_z + idx) = make_float4(v0,v1,v2,v3);
        __half2 ha, hb;
        ha.x=__float2half(v0); ha.y=__float2half(v1);
        hb.x=__float2half(v2); hb.y=__float2half(v3);
        uint2 hp;
        hp.x = *(uint32_t*)&ha; hp.y = *(uint32_t*)&hb;
        *(uint2*)(g_zh + idx) = hp;
    }
}

// single-pass rmsnorm of z rows (float4), using g_zpart partials.
// If outz != null also writes final z to the output buffer (last step).
__global__ void rmsnorm_z_split_kernel(float* __restrict__ outz){
    int row = blockIdx.x;
    __shared__ float ssum;
    if (threadIdx.x == 0){
        const float* pp = g_zpart + (size_t)row*4;
        ssum = pp[0] + pp[1] + pp[2] + pp[3];
    }
    __syncthreads();
    float scale = rsqrtf(ssum/(float)H_ + 1e-5f);
    float* p = g_z + (size_t)row*H_;
    int i = threadIdx.x*4;   // 128 threads x 4 = 512
    float4 v = *(float4*)(p + i);
    v.x *= scale; v.y *= scale; v.z *= scale; v.w *= scale;
    *(float4*)(p + i) = v;
    if (outz) *(float4*)(outz + (size_t)row*H_ + i) = v;
    __half2 ha, hb;
    ha.x=__float2half(v.x); ha.y=__float2half(v.y);
    hb.x=__float2half(v.z); hb.y=__float2half(v.w);
    uint2 hp;
    hp.x = *(uint32_t*)&ha; hp.y = *(uint32_t*)&hb;
    *(uint2*)(g_zh + (size_t)row*H_ + i) = hp;
}

// ---------------------------------------------------------------------------
extern "C" void kernel_launch(void* const* d_in, const int* in_sizes, int n_in,
                              void* d_out, int out_size)
{
    const int*   inputs    = (const int*)  d_in[0];
    const float* z_in      = (const float*)d_in[1];
    const float* h_in      = (const float*)d_in[2];
    const float* mem_in    = (const float*)d_in[3];
    const float* embed_w   = (const float*)d_in[4];
    const float* lm_head_w = (const float*)d_in[5];
    const float* w1        = (const float*)d_in[6];
    const float* b1        = (const float*)d_in[7];
    const float* w2        = (const float*)d_in[8];
    const float* b2        = (const float*)d_in[9];
    const float* hdw       = (const float*)d_in[10];
    const float* hdb       = (const float*)d_in[11];
    const float* filmw     = (const float*)d_in[12];
    const float* filmb     = (const float*)d_in[13];
    const float* haltw     = (const float*)d_in[14];
    const float* haltb     = (const float*)d_in[15];
    const float* qw        = (const float*)d_in[16];
    const float* qb        = (const float*)d_in[17];
    const float* kw        = (const float*)d_in[18];
    const float* kb        = (const float*)d_in[19];
    const float* vw        = (const float*)d_in[20];
    const float* vb        = (const float*)d_in[21];
    const float* gw        = (const float*)d_in[22];
    const float* gb        = (const float*)d_in[23];
    const float* ow        = (const float*)d_in[24];
    const float* ob        = (const float*)d_in[25];
    const float* wt_gu     = (const float*)d_in[26];
    const float* wt_d      = (const float*)d_in[27];
    const float* wm_gu     = (const float*)d_in[28];
    const float* wm_d      = (const float*)d_in[29];
    float* out = (float*)d_out;

    float *zp, *tp, *hp, *memp, *tpart, *zpart;
    cudaGetSymbolAddress((void**)&zp,    g_z);
    cudaGetSymbolAddress((void**)&tp,    g_t);
    cudaGetSymbolAddress((void**)&hp,    g_h);
    cudaGetSymbolAddress((void**)&memp,  g_mem);
    cudaGetSymbolAddress((void**)&tpart, g_tpart);
    cudaGetSymbolAddress((void**)&zpart, g_zpart);

    __half *th, *zh, *ah;
    __half *wtgu, *wtd, *wmgu, *wmd, *lmhh, *lmhl;
    cudaGetSymbolAddress((void**)&th, g_th);
    cudaGetSymbolAddress((void**)&zh, g_zh);
    cudaGetSymbolAddress((void**)&ah, g_acth);
    cudaGetSymbolAddress((void**)&wtgu, g_wtgu);
    cudaGetSymbolAddress((void**)&wtd,  g_wtd);
    cudaGetSymbolAddress((void**)&wmgu, g_wmgu);
    cudaGetSymbolAddress((void**)&wmd,  g_wmd);
    cudaGetSymbolAddress((void**)&lmhh, g_lmh_h);
    cudaGetSymbolAddress((void**)&lmhl, g_lmh_l);

    const int SMEM_GLU = 3*32*1024;
    const int SMEM_G2  = 3*32*1024;
    const int SMEM_G0  = 2*48*1024;
    cudaFuncSetAttribute(mma_gemm_glu, cudaFuncAttributeMaxDynamicSharedMemorySize, SMEM_GLU);
    cudaFuncSetAttribute(mma_gemm2,    cudaFuncAttributeMaxDynamicSharedMemorySize, SMEM_G2);
    cudaFuncSetAttribute(mma_gemm0,    cudaFuncAttributeMaxDynamicSharedMemorySize, SMEM_G0);

    dim3 trBlk(16,16);
    dim3 trGrd(S_/64, H_/64, B_);

    // state init
    {
        int tot4 = (B_*S_*H_ + B_*P_ + B_*SLOTS_*M_)/4;
        copy_init_kernel<<<(tot4+255)/256, 256>>>((const float4*)z_in, (const float4*)h_in, (const float4*)mem_in);
    }
    // weight converts/splits
    split_all_kernel<<<(NSALL/4+255)/256, 256>>>(wt_gu, wt_d, wm_gu, wm_d, lm_head_w);

    for (int st=0; st<HALT_STEPS_; st++){
        planner_kernel<<<B_, 1024>>>(w1,b1,w2,b2,hdw,hdb,filmw,filmb,haltw,haltb,
                                     qw,qb,kw,kb,vw,vb,gw,gb,ow,ob,
                                     out + HALT_OFF + st*B_);

        for (int i=0; i<L_; i++){
            if (i==0) transpose_zt_split<true,false><<<trGrd, trBlk>>>(inputs, embed_w);
            else      transpose_zt_split<false,true><<<trGrd, trBlk>>>(inputs, embed_w);
            {
                size_t go = (size_t)i*2*IT_*S_;
                mma_gemm_glu<<<dim3(IT_/64, (B_*H_)/128), 256, SMEM_GLU>>>(
                    th, wtgu+go, wtgu+go+(size_t)IT_*S_, ah, S_, IT_);
            }
            {
                size_t dof = (size_t)i*S_*IT_;
                mma_gemm2<<<dim3(S_/128, (B_*H_)/128), 256, SMEM_G2>>>(
                    ah, wtd+dof, tp, tpart, 16, IT_, S_);
            }
            transpose_tz_film_split<<<trGrd, trBlk>>>();
            {
                size_t go = (size_t)i*2*IM_*H_;
                mma_gemm_glu<<<dim3(IM_/64, (B_*S_)/128), 256, SMEM_GLU>>>(
                    zh, wmgu+go, wmgu+go+(size_t)IM_*H_, ah, H_, IM_);
            }
            {
                size_t dof = (size_t)i*H_*IM_;
                mma_gemm2<<<dim3(H_/128, (B_*S_)/128), 256, SMEM_G2>>>(
                    ah, wmd+dof, zp, zpart, 4, IM_, H_);
            }
            if (i == L_-1)
                rmsnorm_z_split_kernel<<<B_*S_, 128>>>(
                    (st == HALT_STEPS_-1) ? (out + ZL_OFF) : nullptr);
        }
        mma_gemm0<<<dim3(V_/128, (B_*S_)/128), 256, SMEM_G0>>>(
            zh, lmhh, lmhl, out + (size_t)st*B_*S_*V_, H_, V_);
    }

    // final state outputs (z is written by the last rmsnorm directly)
    copy4_kernel<<<(B_*P_/4+255)/256,    256>>>((float4*)(out + HOUT_OFF),(const float4*)hp, B_*P_/4);
    copy4_kernel<<<(B_*SLOTS_*M_/4+255)/256,256>>>((float4*)(out + MEM_OFF),(const float4*)memp, B_*SLOTS_*M_/4);
}